// round 3
// baseline (speedup 1.0000x reference)
#include <cuda_runtime.h>
#include <cuda_bf16.h>

// Problem constants
#define BATCH 8
#define CH    256
#define CQK   32
#define NQ    4096   // H*W = 64*64

typedef unsigned long long ull;

// ---------------- packed f32x2 helpers (Blackwell FFMA2) ----------------
__device__ __forceinline__ void ffma2(ull& d, ull a, ull b) {
    asm("fma.rn.f32x2 %0, %1, %2, %0;" : "+l"(d) : "l"(a), "l"(b));
}
__device__ __forceinline__ ull mul2(ull a, ull b) {
    ull r; asm("mul.rn.f32x2 %0, %1, %2;" : "=l"(r) : "l"(a), "l"(b)); return r;
}
__device__ __forceinline__ ull pack2(float x, float y) {
    ull r; asm("mov.b64 %0, {%1, %2};" : "=l"(r) : "f"(x), "f"(y)); return r;
}
__device__ __forceinline__ float2 unpack2(ull v) {
    float2 f; asm("mov.b64 {%0, %1}, %2;" : "=f"(f.x), "=f"(f.y) : "l"(v)); return f;
}

// Fast exp on the FMA pipe (avoids MUFU bottleneck). |err| ~3e-6 rel.
__device__ __forceinline__ float fexp(float x) {
    x = fmaxf(x, -87.0f);
    float t = x * 1.4426950408889634f;          // log2(e)
    float z = t + 12582912.0f;                  // round-to-nearest via magic
    int   i = __float_as_int(z) - 0x4B400000;   // integer part
    float r = z - 12582912.0f;
    float f = t - r;                            // frac in [-0.5, 0.5]
    float p = 0.00133336f;
    p = fmaf(p, f, 0.00961813f);
    p = fmaf(p, f, 0.05550411f);
    p = fmaf(p, f, 0.24022651f);
    p = fmaf(p, f, 0.69314718f);
    p = fmaf(p, f, 1.0f);
    float s = __int_as_float((i + 127) << 23);  // 2^i
    return p * s;
}

// ---------------- scratch (no allocation allowed) ----------------
__device__ float g_Q[BATCH * NQ * CQK];   // [b][n][32]
__device__ float g_K[BATCH * NQ * CQK];   // [b][m][32]
__device__ float g_V[BATCH * NQ * CH];    // [b][m][256]

// ---------------- 1x1 conv == per-pixel GEMM ----------------
// out[b][n][o0 + o] = sum_c F[b][c][n] * W[o0+o][c] + bias[o0+o]
// Tile: 64 n x OT o per block, threads = 16 * (OT/4)
template<int OT>
__global__ void conv1x1_kernel(const float* __restrict__ F,
                               const float* __restrict__ W,
                               const float* __restrict__ bias,
                               float* __restrict__ out, int ostride) {
    constexpr int T = 16 * (OT / 4);
    __shared__ float Fs[64][64];       // [c][n]
    __shared__ float Ws[64][OT + 4];   // [c][o] transposed, padded
    const int tid = threadIdx.x;
    const int tx = tid & 15;           // n group (4 each)
    const int ty = tid >> 4;           // o group (4 each)
    const int n0 = blockIdx.x * 64;
    const int o0 = blockIdx.y * OT;
    const int b  = blockIdx.z;
    const float* Fb = F + (size_t)b * CH * NQ;

    float acc[4][4];
#pragma unroll
    for (int i = 0; i < 4; i++)
#pragma unroll
        for (int j = 0; j < 4; j++) acc[i][j] = 0.f;

    for (int c0 = 0; c0 < CH; c0 += 64) {
        // load F tile [64 c][64 n], coalesced
        for (int idx = tid; idx < 1024; idx += T) {
            int r = idx >> 4, c4 = idx & 15;
            *(float4*)&Fs[r][c4 * 4] =
                *(const float4*)&Fb[(size_t)(c0 + r) * NQ + n0 + c4 * 4];
        }
        // load W tile [OT o][64 c], store transposed [c][o]
        for (int idx = tid; idx < OT * 16; idx += T) {
            int o_r = idx >> 4, c4 = idx & 15;
            float4 w4 = *(const float4*)&W[(size_t)(o0 + o_r) * CH + c0 + c4 * 4];
            Ws[c4 * 4 + 0][o_r] = w4.x;
            Ws[c4 * 4 + 1][o_r] = w4.y;
            Ws[c4 * 4 + 2][o_r] = w4.z;
            Ws[c4 * 4 + 3][o_r] = w4.w;
        }
        __syncthreads();
#pragma unroll 8
        for (int cc = 0; cc < 64; cc++) {
            float4 f4 = *(const float4*)&Fs[cc][tx * 4];
            float4 w4 = *(const float4*)&Ws[cc][ty * 4];
            float fa[4] = {f4.x, f4.y, f4.z, f4.w};
            float wa[4] = {w4.x, w4.y, w4.z, w4.w};
#pragma unroll
            for (int i = 0; i < 4; i++)
#pragma unroll
                for (int j = 0; j < 4; j++) acc[i][j] += fa[i] * wa[j];
        }
        __syncthreads();
    }
    float bs[4];
#pragma unroll
    for (int j = 0; j < 4; j++) bs[j] = bias[o0 + ty * 4 + j];
#pragma unroll
    for (int i = 0; i < 4; i++) {
        int n = n0 + tx * 4 + i;
        float4 r = make_float4(acc[i][0] + bs[0], acc[i][1] + bs[1],
                               acc[i][2] + bs[2], acc[i][3] + bs[3]);
        *(float4*)&out[((size_t)b * NQ + n) * ostride + o0 + ty * 4] = r;
    }
}

// ---------------- fused flash attention ----------------
// Block: 64 queries x 256 channels, loop 64-key tiles.
// Thread (ty,tx): q rows = ty*4+i, keys m = tx+16j (S phase), channels = tx*16..+15 (PV phase)
#define SM_QS 0
#define SM_KS 2048            // stride 36
#define SM_VS (2048 + 64*36)  // 4352, stride 256
#define SM_PS (SM_VS + 64*256) // 20736, layout [m][q] stride 68
#define SMEM_FLOATS (SM_PS + 64*68)
#define SMEM_BYTES (SMEM_FLOATS * 4)

__global__ void __launch_bounds__(256, 2)
attn_kernel(const float* __restrict__ Qg, const float* __restrict__ Kg,
            const float* __restrict__ Vg, float* __restrict__ Og) {
    extern __shared__ float sm[];
    float* Qs = sm + SM_QS;
    float* Ks = sm + SM_KS;
    float* Vs = sm + SM_VS;
    float* Ps = sm + SM_PS;

    const int tid = threadIdx.x;
    const int tx = tid & 15;
    const int ty = tid >> 4;
    const int q0 = blockIdx.x * 64;
    const int b  = blockIdx.y;

    // load Q tile once (flat [64][32])
    {
        const float4* qg4 = (const float4*)(Qg + ((size_t)b * NQ + q0) * CQK);
        float4* qs4 = (float4*)Qs;
        for (int idx = tid; idx < 512; idx += 256) qs4[idx] = qg4[idx];
    }

    float m_run[4], l_run[4];
    ull accO[4][8];
#pragma unroll
    for (int i = 0; i < 4; i++) {
        m_run[i] = -1e30f; l_run[i] = 0.f;
#pragma unroll
        for (int k = 0; k < 8; k++) accO[i][k] = 0ULL;
    }

    const float* Kb = Kg + (size_t)b * NQ * CQK;
    const float* Vb = Vg + (size_t)b * NQ * CH;

    for (int kt = 0; kt < NQ / 64; kt++) {
        const int m0 = kt * 64;
        // ---- load K tile (padded stride 36) and V tile (flat) ----
        {
            const float4* kg4 = (const float4*)(Kb + (size_t)m0 * CQK);
            for (int idx = tid; idx < 512; idx += 256) {
                float4 v = kg4[idx];
                int r = idx >> 3, c4 = idx & 7;
                *(float4*)&Ks[r * 36 + c4 * 4] = v;
            }
            const float4* vg4 = (const float4*)(Vb + (size_t)m0 * CH);
            float4* vs4 = (float4*)Vs;
            for (int idx = tid; idx < 4096; idx += 256) vs4[idx] = vg4[idx];
        }
        __syncthreads();

        // ---- S = Q K^T (f32x2 packed over c) ----
        float sreg[4][4];
#pragma unroll
        for (int jp = 0; jp < 2; jp++) {
            ull a2[4][2];
#pragma unroll
            for (int i = 0; i < 4; i++) { a2[i][0] = 0ULL; a2[i][1] = 0ULL; }
#pragma unroll
            for (int c4 = 0; c4 < 8; c4++) {
                ulonglong2 k0 = *(const ulonglong2*)&Ks[(tx + 32 * jp) * 36 + c4 * 4];
                ulonglong2 k1 = *(const ulonglong2*)&Ks[(tx + 32 * jp + 16) * 36 + c4 * 4];
#pragma unroll
                for (int i = 0; i < 4; i++) {
                    ulonglong2 q2 = *(const ulonglong2*)&Qs[(ty * 4 + i) * 32 + c4 * 4];
                    ffma2(a2[i][0], q2.x, k0.x);
                    ffma2(a2[i][0], q2.y, k0.y);
                    ffma2(a2[i][1], q2.x, k1.x);
                    ffma2(a2[i][1], q2.y, k1.y);
                }
            }
#pragma unroll
            for (int i = 0; i < 4; i++) {
                float2 u0 = unpack2(a2[i][0]);
                float2 u1 = unpack2(a2[i][1]);
                sreg[i][2 * jp]     = u0.x + u0.y;
                sreg[i][2 * jp + 1] = u1.x + u1.y;
            }
        }

        // ---- online softmax (per q-row, reduced over 16-lane group) ----
#pragma unroll
        for (int i = 0; i < 4; i++) {
            float tm = fmaxf(fmaxf(sreg[i][0], sreg[i][1]),
                             fmaxf(sreg[i][2], sreg[i][3]));
#pragma unroll
            for (int d = 1; d < 16; d <<= 1)
                tm = fmaxf(tm, __shfl_xor_sync(0xffffffffu, tm, d));
            float mnew = fmaxf(m_run[i], tm);
            float corr = fexp(m_run[i] - mnew);
            m_run[i] = mnew;
            float ps = 0.f;
#pragma unroll
            for (int j = 0; j < 4; j++) {
                float p = fexp(sreg[i][j] - mnew);
                ps += p;
                Ps[(tx + 16 * j) * 68 + ty * 4 + i] = p;   // transposed [m][q]
            }
#pragma unroll
            for (int d = 1; d < 16; d <<= 1)
                ps += __shfl_xor_sync(0xffffffffu, ps, d);
            l_run[i] = l_run[i] * corr + ps;
            ull c2 = pack2(corr, corr);
#pragma unroll
            for (int k = 0; k < 8; k++) accO[i][k] = mul2(accO[i][k], c2);
        }
        __syncthreads();

        // ---- PV: acc[q][c] += p[q][m] * V[m][c] (f32x2 packed over c) ----
#pragma unroll 2
        for (int m = 0; m < 64; m++) {
            float4 p4 = *(const float4*)&Ps[m * 68 + ty * 4];
            ull p2[4];
            p2[0] = pack2(p4.x, p4.x);
            p2[1] = pack2(p4.y, p4.y);
            p2[2] = pack2(p4.z, p4.z);
            p2[3] = pack2(p4.w, p4.w);
            const ulonglong2* vr = (const ulonglong2*)&Vs[m * 256 + tx * 16];
            ulonglong2 va = vr[0], vb2 = vr[1];
#pragma unroll
            for (int i = 0; i < 4; i++) {
                ffma2(accO[i][0], p2[i], va.x);
                ffma2(accO[i][1], p2[i], va.y);
                ffma2(accO[i][2], p2[i], vb2.x);
                ffma2(accO[i][3], p2[i], vb2.y);
            }
            ulonglong2 vc = vr[2], vd = vr[3];
#pragma unroll
            for (int i = 0; i < 4; i++) {
                ffma2(accO[i][4], p2[i], vc.x);
                ffma2(accO[i][5], p2[i], vc.y);
                ffma2(accO[i][6], p2[i], vd.x);
                ffma2(accO[i][7], p2[i], vd.y);
            }
        }
        __syncthreads();
    }

    // ---- epilogue: normalize + store out[b][c][n] ----
    float inv[4];
#pragma unroll
    for (int i = 0; i < 4; i++) inv[i] = 1.0f / l_run[i];
    float* ob = Og + (size_t)b * CH * NQ + q0 + ty * 4;
#pragma unroll
    for (int k = 0; k < 8; k++) {
        float lo[4], hi[4];
#pragma unroll
        for (int i = 0; i < 4; i++) {
            float2 u = unpack2(accO[i][k]);
            lo[i] = u.x * inv[i];
            hi[i] = u.y * inv[i];
        }
        int c = tx * 16 + 2 * k;
        *(float4*)&ob[(size_t)c * NQ]       = make_float4(lo[0], lo[1], lo[2], lo[3]);
        *(float4*)&ob[(size_t)(c + 1) * NQ] = make_float4(hi[0], hi[1], hi[2], hi[3]);
    }
}

// ---------------- launch ----------------
extern "C" void kernel_launch(void* const* d_in, const int* in_sizes, int n_in,
                              void* d_out, int out_size) {
    const float* f1 = (const float*)d_in[0];
    const float* f2 = (const float*)d_in[1];
    const float* f3 = (const float*)d_in[2];
    const float* wq = (const float*)d_in[3];
    const float* bq = (const float*)d_in[4];
    const float* wk = (const float*)d_in[5];
    const float* bk = (const float*)d_in[6];
    const float* wv = (const float*)d_in[7];
    const float* bv = (const float*)d_in[8];
    float* out = (float*)d_out;

    float *qp, *kp, *vp;
    cudaGetSymbolAddress((void**)&qp, g_Q);
    cudaGetSymbolAddress((void**)&kp, g_K);
    cudaGetSymbolAddress((void**)&vp, g_V);

    dim3 gqk(NQ / 64, 1, BATCH);
    conv1x1_kernel<32><<<gqk, 128>>>(f1, wq, bq, qp, CQK);
    conv1x1_kernel<32><<<gqk, 128>>>(f2, wk, bk, kp, CQK);
    dim3 gv(NQ / 64, CH / 64, BATCH);
    conv1x1_kernel<64><<<gv, 256>>>(f3, wv, bv, vp, CH);

    cudaFuncSetAttribute(attn_kernel, cudaFuncAttributeMaxDynamicSharedMemorySize,
                         SMEM_BYTES);
    dim3 ga(NQ / 64, BATCH);
    attn_kernel<<<ga, 256, SMEM_BYTES>>>(qp, kp, vp, out);
}

// round 4
// speedup vs baseline: 1.6402x; 1.6402x over previous
#include <cuda_runtime.h>
#include <cuda_bf16.h>

// Problem constants
#define BATCH 8
#define CH    256
#define CQK   32
#define NQ    4096   // H*W = 64*64

typedef unsigned long long ull;

// ---------------- packed f32x2 helpers (Blackwell FFMA2) ----------------
__device__ __forceinline__ void ffma2(ull& d, ull a, ull b) {
    asm("fma.rn.f32x2 %0, %1, %2, %0;" : "+l"(d) : "l"(a), "l"(b));
}
__device__ __forceinline__ ull mul2(ull a, ull b) {
    ull r; asm("mul.rn.f32x2 %0, %1, %2;" : "=l"(r) : "l"(a), "l"(b)); return r;
}
__device__ __forceinline__ ull pack2(float x, float y) {
    ull r; asm("mov.b64 %0, {%1, %2};" : "=l"(r) : "f"(x), "f"(y)); return r;
}
__device__ __forceinline__ float2 unpack2(ull v) {
    float2 f; asm("mov.b64 {%0, %1}, %2;" : "=f"(f.x), "=f"(f.y) : "l"(v)); return f;
}

// Fast exp on the FMA pipe (avoids MUFU bottleneck). |err| ~3e-6 rel.
__device__ __forceinline__ float fexp(float x) {
    x = fmaxf(x, -87.0f);
    float t = x * 1.4426950408889634f;          // log2(e)
    float z = t + 12582912.0f;                  // round-to-nearest via magic
    int   i = __float_as_int(z) - 0x4B400000;   // integer part
    float r = z - 12582912.0f;
    float f = t - r;                            // frac in [-0.5, 0.5]
    float p = 0.00133336f;
    p = fmaf(p, f, 0.00961813f);
    p = fmaf(p, f, 0.05550411f);
    p = fmaf(p, f, 0.24022651f);
    p = fmaf(p, f, 0.69314718f);
    p = fmaf(p, f, 1.0f);
    float s = __int_as_float((i + 127) << 23);  // 2^i
    return p * s;
}

// ---------------- scratch (no allocation allowed) ----------------
__device__ float g_Q[BATCH * NQ * CQK];   // [b][n][32]
__device__ float g_K[BATCH * NQ * CQK];   // [b][m][32]
__device__ float g_V[BATCH * NQ * CH];    // [b][m][256]

// ---------------- 1x1 conv == per-pixel GEMM ----------------
// out[b][n][o0 + o] = sum_c F[b][c][n] * W[o0+o][c] + bias[o0+o]
// Tile: 64 n x OT o per block, threads = 16 * (OT/4)
template<int OT>
__global__ void conv1x1_kernel(const float* __restrict__ F,
                               const float* __restrict__ W,
                               const float* __restrict__ bias,
                               float* __restrict__ out, int ostride) {
    constexpr int T = 16 * (OT / 4);
    __shared__ float Fs[64][64];       // [c][n]
    __shared__ float Ws[64][OT + 4];   // [c][o] transposed, padded
    const int tid = threadIdx.x;
    const int tx = tid & 15;           // n group (4 each)
    const int ty = tid >> 4;           // o group (4 each)
    const int n0 = blockIdx.x * 64;
    const int o0 = blockIdx.y * OT;
    const int b  = blockIdx.z;
    const float* Fb = F + (size_t)b * CH * NQ;

    float acc[4][4];
#pragma unroll
    for (int i = 0; i < 4; i++)
#pragma unroll
        for (int j = 0; j < 4; j++) acc[i][j] = 0.f;

    for (int c0 = 0; c0 < CH; c0 += 64) {
        // load F tile [64 c][64 n], coalesced
        for (int idx = tid; idx < 1024; idx += T) {
            int r = idx >> 4, c4 = idx & 15;
            *(float4*)&Fs[r][c4 * 4] =
                *(const float4*)&Fb[(size_t)(c0 + r) * NQ + n0 + c4 * 4];
        }
        // load W tile [OT o][64 c], store transposed [c][o]
        for (int idx = tid; idx < OT * 16; idx += T) {
            int o_r = idx >> 4, c4 = idx & 15;
            float4 w4 = *(const float4*)&W[(size_t)(o0 + o_r) * CH + c0 + c4 * 4];
            Ws[c4 * 4 + 0][o_r] = w4.x;
            Ws[c4 * 4 + 1][o_r] = w4.y;
            Ws[c4 * 4 + 2][o_r] = w4.z;
            Ws[c4 * 4 + 3][o_r] = w4.w;
        }
        __syncthreads();
#pragma unroll 8
        for (int cc = 0; cc < 64; cc++) {
            float4 f4 = *(const float4*)&Fs[cc][tx * 4];
            float4 w4 = *(const float4*)&Ws[cc][ty * 4];
            float fa[4] = {f4.x, f4.y, f4.z, f4.w};
            float wa[4] = {w4.x, w4.y, w4.z, w4.w};
#pragma unroll
            for (int i = 0; i < 4; i++)
#pragma unroll
                for (int j = 0; j < 4; j++) acc[i][j] += fa[i] * wa[j];
        }
        __syncthreads();
    }
    float bs[4];
#pragma unroll
    for (int j = 0; j < 4; j++) bs[j] = bias[o0 + ty * 4 + j];
#pragma unroll
    for (int i = 0; i < 4; i++) {
        int n = n0 + tx * 4 + i;
        float4 r = make_float4(acc[i][0] + bs[0], acc[i][1] + bs[1],
                               acc[i][2] + bs[2], acc[i][3] + bs[3]);
        *(float4*)&out[((size_t)b * NQ + n) * ostride + o0 + ty * 4] = r;
    }
}

// ---------------- fused flash attention ----------------
// Block: 64 queries x 256 channels, loop 64-key tiles.
// Thread (ty,tx): q rows = ty*4+i, keys m = tx+16j (S phase), channels = tx*16..+15 (PV phase)
#define SM_QS 0
#define SM_KS 2048            // stride 36
#define SM_VS (2048 + 64*36)  // 4352, stride 256
#define SM_PS (SM_VS + 64*256) // 20736, layout [m][q] stride 68
#define SMEM_FLOATS (SM_PS + 64*68)
#define SMEM_BYTES (SMEM_FLOATS * 4)

__global__ void __launch_bounds__(256, 2)
attn_kernel(const float* __restrict__ Qg, const float* __restrict__ Kg,
            const float* __restrict__ Vg, float* __restrict__ Og) {
    extern __shared__ float sm[];
    float* Qs = sm + SM_QS;
    float* Ks = sm + SM_KS;
    float* Vs = sm + SM_VS;
    float* Ps = sm + SM_PS;

    const int tid = threadIdx.x;
    const int tx = tid & 15;
    const int ty = tid >> 4;
    const int q0 = blockIdx.x * 64;
    const int b  = blockIdx.y;

    // load Q tile once (flat [64][32])
    {
        const float4* qg4 = (const float4*)(Qg + ((size_t)b * NQ + q0) * CQK);
        float4* qs4 = (float4*)Qs;
        for (int idx = tid; idx < 512; idx += 256) qs4[idx] = qg4[idx];
    }

    float m_run[4], l_run[4];
    ull accO[4][8];
#pragma unroll
    for (int i = 0; i < 4; i++) {
        m_run[i] = -1e30f; l_run[i] = 0.f;
#pragma unroll
        for (int k = 0; k < 8; k++) accO[i][k] = 0ULL;
    }

    const float* Kb = Kg + (size_t)b * NQ * CQK;
    const float* Vb = Vg + (size_t)b * NQ * CH;

    for (int kt = 0; kt < NQ / 64; kt++) {
        const int m0 = kt * 64;
        // ---- load K tile (padded stride 36) and V tile (flat) ----
        {
            const float4* kg4 = (const float4*)(Kb + (size_t)m0 * CQK);
            for (int idx = tid; idx < 512; idx += 256) {
                float4 v = kg4[idx];
                int r = idx >> 3, c4 = idx & 7;
                *(float4*)&Ks[r * 36 + c4 * 4] = v;
            }
            const float4* vg4 = (const float4*)(Vb + (size_t)m0 * CH);
            float4* vs4 = (float4*)Vs;
            for (int idx = tid; idx < 4096; idx += 256) vs4[idx] = vg4[idx];
        }
        __syncthreads();

        // ---- S = Q K^T (f32x2 packed over c) ----
        float sreg[4][4];
#pragma unroll
        for (int jp = 0; jp < 2; jp++) {
            ull a2[4][2];
#pragma unroll
            for (int i = 0; i < 4; i++) { a2[i][0] = 0ULL; a2[i][1] = 0ULL; }
#pragma unroll
            for (int c4 = 0; c4 < 8; c4++) {
                ulonglong2 k0 = *(const ulonglong2*)&Ks[(tx + 32 * jp) * 36 + c4 * 4];
                ulonglong2 k1 = *(const ulonglong2*)&Ks[(tx + 32 * jp + 16) * 36 + c4 * 4];
#pragma unroll
                for (int i = 0; i < 4; i++) {
                    ulonglong2 q2 = *(const ulonglong2*)&Qs[(ty * 4 + i) * 32 + c4 * 4];
                    ffma2(a2[i][0], q2.x, k0.x);
                    ffma2(a2[i][0], q2.y, k0.y);
                    ffma2(a2[i][1], q2.x, k1.x);
                    ffma2(a2[i][1], q2.y, k1.y);
                }
            }
#pragma unroll
            for (int i = 0; i < 4; i++) {
                float2 u0 = unpack2(a2[i][0]);
                float2 u1 = unpack2(a2[i][1]);
                sreg[i][2 * jp]     = u0.x + u0.y;
                sreg[i][2 * jp + 1] = u1.x + u1.y;
            }
        }

        // ---- online softmax (per q-row, reduced over 16-lane group) ----
#pragma unroll
        for (int i = 0; i < 4; i++) {
            float tm = fmaxf(fmaxf(sreg[i][0], sreg[i][1]),
                             fmaxf(sreg[i][2], sreg[i][3]));
#pragma unroll
            for (int d = 1; d < 16; d <<= 1)
                tm = fmaxf(tm, __shfl_xor_sync(0xffffffffu, tm, d));
            float mnew = fmaxf(m_run[i], tm);
            float corr = fexp(m_run[i] - mnew);
            m_run[i] = mnew;
            float ps = 0.f;
#pragma unroll
            for (int j = 0; j < 4; j++) {
                float p = fexp(sreg[i][j] - mnew);
                ps += p;
                Ps[(tx + 16 * j) * 68 + ty * 4 + i] = p;   // transposed [m][q]
            }
#pragma unroll
            for (int d = 1; d < 16; d <<= 1)
                ps += __shfl_xor_sync(0xffffffffu, ps, d);
            l_run[i] = l_run[i] * corr + ps;
            ull c2 = pack2(corr, corr);
#pragma unroll
            for (int k = 0; k < 8; k++) accO[i][k] = mul2(accO[i][k], c2);
        }
        __syncthreads();

        // ---- PV: acc[q][c] += p[q][m] * V[m][c] (f32x2 packed over c) ----
#pragma unroll 2
        for (int m = 0; m < 64; m++) {
            float4 p4 = *(const float4*)&Ps[m * 68 + ty * 4];
            ull p2[4];
            p2[0] = pack2(p4.x, p4.x);
            p2[1] = pack2(p4.y, p4.y);
            p2[2] = pack2(p4.z, p4.z);
            p2[3] = pack2(p4.w, p4.w);
            const ulonglong2* vr = (const ulonglong2*)&Vs[m * 256 + tx * 16];
            ulonglong2 va = vr[0], vb2 = vr[1];
#pragma unroll
            for (int i = 0; i < 4; i++) {
                ffma2(accO[i][0], p2[i], va.x);
                ffma2(accO[i][1], p2[i], va.y);
                ffma2(accO[i][2], p2[i], vb2.x);
                ffma2(accO[i][3], p2[i], vb2.y);
            }
            ulonglong2 vc = vr[2], vd = vr[3];
#pragma unroll
            for (int i = 0; i < 4; i++) {
                ffma2(accO[i][4], p2[i], vc.x);
                ffma2(accO[i][5], p2[i], vc.y);
                ffma2(accO[i][6], p2[i], vd.x);
                ffma2(accO[i][7], p2[i], vd.y);
            }
        }
        __syncthreads();
    }

    // ---- epilogue: normalize + store out[b][c][n] ----
    float inv[4];
#pragma unroll
    for (int i = 0; i < 4; i++) inv[i] = 1.0f / l_run[i];
    float* ob = Og + (size_t)b * CH * NQ + q0 + ty * 4;
#pragma unroll
    for (int k = 0; k < 8; k++) {
        float lo[4], hi[4];
#pragma unroll
        for (int i = 0; i < 4; i++) {
            float2 u = unpack2(accO[i][k]);
            lo[i] = u.x * inv[i];
            hi[i] = u.y * inv[i];
        }
        int c = tx * 16 + 2 * k;
        *(float4*)&ob[(size_t)c * NQ]       = make_float4(lo[0], lo[1], lo[2], lo[3]);
        *(float4*)&ob[(size_t)(c + 1) * NQ] = make_float4(hi[0], hi[1], hi[2], hi[3]);
    }
}

// ---------------- launch ----------------
extern "C" void kernel_launch(void* const* d_in, const int* in_sizes, int n_in,
                              void* d_out, int out_size) {
    const float* f1 = (const float*)d_in[0];
    const float* f2 = (const float*)d_in[1];
    const float* f3 = (const float*)d_in[2];
    const float* wq = (const float*)d_in[3];
    const float* bq = (const float*)d_in[4];
    const float* wk = (const float*)d_in[5];
    const float* bk = (const float*)d_in[6];
    const float* wv = (const float*)d_in[7];
    const float* bv = (const float*)d_in[8];
    float* out = (float*)d_out;

    float *qp, *kp, *vp;
    cudaGetSymbolAddress((void**)&qp, g_Q);
    cudaGetSymbolAddress((void**)&kp, g_K);
    cudaGetSymbolAddress((void**)&vp, g_V);

    dim3 gqk(NQ / 64, 1, BATCH);
    conv1x1_kernel<32><<<gqk, 128>>>(f1, wq, bq, qp, CQK);
    conv1x1_kernel<32><<<gqk, 128>>>(f2, wk, bk, kp, CQK);
    dim3 gv(NQ / 64, CH / 64, BATCH);
    conv1x1_kernel<64><<<gv, 256>>>(f3, wv, bv, vp, CH);

    cudaFuncSetAttribute(attn_kernel, cudaFuncAttributeMaxDynamicSharedMemorySize,
                         SMEM_BYTES);
    dim3 ga(NQ / 64, BATCH);
    attn_kernel<<<ga, 256, SMEM_BYTES>>>(qp, kp, vp, out);
}

// round 9
// speedup vs baseline: 10.1415x; 6.1831x over previous
#include <cuda_runtime.h>
#include <cuda_bf16.h>

#define BATCH 8
#define CH    256
#define CQK   32
#define NQ    4096
#define LOG2E 1.4426950408889634f

typedef unsigned long long ull;
typedef unsigned int u32;

// ---------------- scratch ----------------
__device__ __nv_bfloat16 g_Qhl[BATCH * NQ * 64];   // [b][n][32 hi | 32 lo]
__device__ __nv_bfloat16 g_Khl[BATCH * NQ * 64];   // [b][m][32 hi | 32 lo]
__device__ __nv_bfloat16 g_VTh[BATCH * CH * NQ];   // [b][c][m] hi
__device__ __nv_bfloat16 g_VTl[BATCH * CH * NQ];   // [b][c][m] lo

// ---------------- helpers ----------------
__device__ __forceinline__ void ffma2(ull& d, ull a, ull b) {
    asm("fma.rn.f32x2 %0, %1, %2, %0;" : "+l"(d) : "l"(a), "l"(b));
}
__device__ __forceinline__ ull pack2(float x, float y) {
    ull r; asm("mov.b64 %0, {%1, %2};" : "=l"(r) : "f"(x), "f"(y)); return r;
}
__device__ __forceinline__ float2 unpack2(ull v) {
    float2 f; asm("mov.b64 {%0, %1}, %2;" : "=f"(f.x), "=f"(f.y) : "l"(v)); return f;
}
__device__ __forceinline__ float ex2f(float x) {
    float r; asm("ex2.approx.f32 %0, %1;" : "=f"(r) : "f"(x)); return r;
}
__device__ __forceinline__ u32 smem_u32(const void* p) {
    u32 a; asm("{ .reg .u64 t; cvta.to.shared.u64 t, %1; cvt.u32.u64 %0, t; }" : "=r"(a) : "l"(p));
    return a;
}
__device__ __forceinline__ void cpa(u32 dst, const void* src) {
    asm volatile("cp.async.cg.shared.global [%0], [%1], 16;" :: "r"(dst), "l"(src));
}
#define CP_COMMIT() asm volatile("cp.async.commit_group;" ::: "memory")
template<int N> __device__ __forceinline__ void cp_wait() {
    asm volatile("cp.async.wait_group %0;" :: "n"(N) : "memory");
}
__device__ __forceinline__ void ldm4(u32* r, u32 addr) {
    asm volatile("ldmatrix.sync.aligned.m8n8.x4.shared.b16 {%0,%1,%2,%3}, [%4];"
                 : "=r"(r[0]), "=r"(r[1]), "=r"(r[2]), "=r"(r[3]) : "r"(addr));
}
__device__ __forceinline__ void mma16816(float* d, const u32* a, const u32* b) {
    asm volatile(
        "mma.sync.aligned.m16n8k16.row.col.f32.bf16.bf16.f32 "
        "{%0,%1,%2,%3}, {%4,%5,%6,%7}, {%8,%9}, {%0,%1,%2,%3};"
        : "+f"(d[0]), "+f"(d[1]), "+f"(d[2]), "+f"(d[3])
        : "r"(a[0]), "r"(a[1]), "r"(a[2]), "r"(a[3]), "r"(b[0]), "r"(b[1]));
}

// ---------------- conv -> Q/K bf16 hi|lo ([n][32hi|32lo]) ----------------
__global__ void conv_qk(const float* __restrict__ F, const float* __restrict__ W,
                        const float* __restrict__ bias, __nv_bfloat16* __restrict__ out) {
    __shared__ float Fs[64][64];
    __shared__ float Ws[64][36];
    const int tid = threadIdx.x;
    const int tx = tid & 15, ty = tid >> 4;
    const int n0 = blockIdx.x * 64, b = blockIdx.z;
    const float* Fb = F + (size_t)b * CH * NQ;

    ull acc2[4][2];
#pragma unroll
    for (int i = 0; i < 4; i++) { acc2[i][0] = 0ULL; acc2[i][1] = 0ULL; }

    for (int c0 = 0; c0 < CH; c0 += 64) {
        for (int idx = tid; idx < 1024; idx += 128) {
            int r = idx >> 4, c4 = idx & 15;
            *(float4*)&Fs[r][c4 * 4] = *(const float4*)&Fb[(size_t)(c0 + r) * NQ + n0 + c4 * 4];
        }
        for (int idx = tid; idx < 512; idx += 128) {
            int o_r = idx >> 4, c4 = idx & 15;
            float4 w4 = *(const float4*)&W[(size_t)o_r * CH + c0 + c4 * 4];
            Ws[c4 * 4 + 0][o_r] = w4.x; Ws[c4 * 4 + 1][o_r] = w4.y;
            Ws[c4 * 4 + 2][o_r] = w4.z; Ws[c4 * 4 + 3][o_r] = w4.w;
        }
        __syncthreads();
#pragma unroll 8
        for (int cc = 0; cc < 64; cc++) {
            float4 f4 = *(const float4*)&Fs[cc][tx * 4];
            ulonglong2 w2 = *(const ulonglong2*)&Ws[cc][ty * 4];
            float fa[4] = {f4.x, f4.y, f4.z, f4.w};
#pragma unroll
            for (int i = 0; i < 4; i++) {
                ull fp = pack2(fa[i], fa[i]);
                ffma2(acc2[i][0], fp, w2.x);
                ffma2(acc2[i][1], fp, w2.y);
            }
        }
        __syncthreads();
    }
    float bs[4];
#pragma unroll
    for (int j = 0; j < 4; j++) bs[j] = bias[ty * 4 + j];
#pragma unroll
    for (int i = 0; i < 4; i++) {
        int n = n0 + tx * 4 + i;
        union { __nv_bfloat16 h[4]; uint2 u; } H, L;
#pragma unroll
        for (int jp = 0; jp < 2; jp++) {
            float2 u = unpack2(acc2[i][jp]);
            float p0 = u.x + bs[2 * jp], p1 = u.y + bs[2 * jp + 1];
            __nv_bfloat16 h0 = __float2bfloat16(p0), h1 = __float2bfloat16(p1);
            H.h[2 * jp] = h0; H.h[2 * jp + 1] = h1;
            L.h[2 * jp] = __float2bfloat16(p0 - __bfloat162float(h0));
            L.h[2 * jp + 1] = __float2bfloat16(p1 - __bfloat162float(h1));
        }
        size_t base = ((size_t)b * NQ + n) * 64 + ty * 4;
        *(uint2*)&out[base] = H.u;
        *(uint2*)&out[base + 32] = L.u;
    }
}

// V conv -> transposed bf16 hi/lo [b][c][m]
__global__ void conv_v(const float* __restrict__ F, const float* __restrict__ W,
                       const float* __restrict__ bias,
                       __nv_bfloat16* __restrict__ oh, __nv_bfloat16* __restrict__ ol) {
    __shared__ float Fs[64][64];
    __shared__ float Ws[64][68];
    const int tid = threadIdx.x;
    const int tx = tid & 15, ty = tid >> 4;
    const int n0 = blockIdx.x * 64, o0 = blockIdx.y * 64, b = blockIdx.z;
    const float* Fb = F + (size_t)b * CH * NQ;

    ull acc2[4][2];
#pragma unroll
    for (int i = 0; i < 4; i++) { acc2[i][0] = 0ULL; acc2[i][1] = 0ULL; }

    for (int c0 = 0; c0 < CH; c0 += 64) {
        for (int idx = tid; idx < 1024; idx += 256) {
            int r = idx >> 4, c4 = idx & 15;
            *(float4*)&Fs[r][c4 * 4] = *(const float4*)&Fb[(size_t)(c0 + r) * NQ + n0 + c4 * 4];
        }
        for (int idx = tid; idx < 1024; idx += 256) {
            int o_r = idx >> 4, c4 = idx & 15;
            float4 w4 = *(const float4*)&W[(size_t)(o0 + o_r) * CH + c0 + c4 * 4];
            Ws[c4 * 4 + 0][o_r] = w4.x; Ws[c4 * 4 + 1][o_r] = w4.y;
            Ws[c4 * 4 + 2][o_r] = w4.z; Ws[c4 * 4 + 3][o_r] = w4.w;
        }
        __syncthreads();
#pragma unroll 8
        for (int cc = 0; cc < 64; cc++) {
            float4 f4 = *(const float4*)&Fs[cc][tx * 4];
            ulonglong2 w2 = *(const ulonglong2*)&Ws[cc][ty * 4];
            float fa[4] = {f4.x, f4.y, f4.z, f4.w};
#pragma unroll
            for (int i = 0; i < 4; i++) {
                ull fp = pack2(fa[i], fa[i]);
                ffma2(acc2[i][0], fp, w2.x);
                ffma2(acc2[i][1], fp, w2.y);
            }
        }
        __syncthreads();
    }
    float accv[4][4];
#pragma unroll
    for (int i = 0; i < 4; i++) {
        float2 u0 = unpack2(acc2[i][0]), u1 = unpack2(acc2[i][1]);
        accv[i][0] = u0.x; accv[i][1] = u0.y; accv[i][2] = u1.x; accv[i][3] = u1.y;
    }
#pragma unroll
    for (int j = 0; j < 4; j++) {
        int o = o0 + ty * 4 + j;
        float bj = bias[o];
        union { __nv_bfloat16 h[4]; uint2 u; } H, L;
#pragma unroll
        for (int i = 0; i < 4; i++) {
            float p = accv[i][j] + bj;
            __nv_bfloat16 h = __float2bfloat16(p);
            H.h[i] = h;
            L.h[i] = __float2bfloat16(p - __bfloat162float(h));
        }
        size_t base = ((size_t)b * CH + o) * NQ + n0 + tx * 4;
        *(uint2*)&oh[base] = H.u;
        *(uint2*)&ol[base] = L.u;
    }
}

// ---------------- mma.sync flash attention ----------------
// CTA: 128 q (8 warps x 16q) x 64 tiles of 64 keys. No max-subtraction softmax.
// smem: Q[128x128B] | K 2x[64x128B] | V 2x[hi 256x128B | lo 256x128B]
#define QS_OFF 0
#define KS_OFF 16384
#define VS_OFF 32768
#define NKT    (NQ / 64)      // 64 key tiles
#define ATTN_SMEM 163840

__device__ __forceinline__ void load_kv(u32 su, const __nv_bfloat16* Kb,
                                        const __nv_bfloat16* Vhb, const __nv_bfloat16* Vlb,
                                        int kt, int tid) {
    int bf = kt & 1;
    for (int i = tid; i < 512; i += 256) {
        int m = i >> 3, j = i & 7;
        cpa(su + KS_OFF + bf * 8192 + m * 128 + ((j ^ (m & 7)) << 4),
            Kb + ((size_t)(kt * 64 + m)) * 64 + j * 8);
    }
    for (int i = tid; i < 4096; i += 256) {
        int arr = i >> 11, rem = i & 2047, c = rem >> 3, j = rem & 7;
        const __nv_bfloat16* src = (arr ? Vlb : Vhb) + (size_t)c * NQ + kt * 64 + j * 8;
        cpa(su + VS_OFF + bf * 65536 + arr * 32768 + c * 128 + ((j ^ (c & 7)) << 4), src);
    }
}

__global__ void __launch_bounds__(256, 1)
attn_kernel(const __nv_bfloat16* __restrict__ Qg, const __nv_bfloat16* __restrict__ Kg,
            const __nv_bfloat16* __restrict__ Vhg, const __nv_bfloat16* __restrict__ Vlg,
            float* __restrict__ Og) {
    extern __shared__ char smx[];
    const u32 su = smem_u32(smx);
    const int tid = threadIdx.x, warp = tid >> 5, lane = tid & 31;
    const int b = blockIdx.y, q0 = blockIdx.x * 128;

    const __nv_bfloat16* Qb  = Qg  + ((size_t)b * NQ + q0) * 64;
    const __nv_bfloat16* Kb  = Kg  + (size_t)b * NQ * 64;
    const __nv_bfloat16* Vhb = Vhg + (size_t)b * CH * NQ;
    const __nv_bfloat16* Vlb = Vlg + (size_t)b * CH * NQ;

    // prologue: Q + K0/V0 (group0), K1/V1 (group1)
    for (int i = tid; i < 1024; i += 256) {
        int q = i >> 3, j = i & 7;
        cpa(su + QS_OFF + q * 128 + ((j ^ (q & 7)) << 4), Qb + (size_t)q * 64 + j * 8);
    }
    load_kv(su, Kb, Vhb, Vlb, 0, tid);
    CP_COMMIT();
    load_kv(su, Kb, Vhb, Vlb, 1, tid);
    CP_COMMIT();

    float oacc[32][4];
#pragma unroll
    for (int i = 0; i < 32; i++)
#pragma unroll
        for (int j = 0; j < 4; j++) oacc[i][j] = 0.f;
    float lsum0 = 0.f, lsum1 = 0.f;
    u32 qa[4][4];

    // ldmatrix per-thread addressing
    const int arow = (lane & 7) | (((lane >> 3) & 1) << 3);  // A-type
    const int achk = lane >> 4;
    const int brow = (lane & 7) | ((lane >> 4) << 3);        // B-type
    const int bchk = (lane >> 3) & 1;

    for (int kt = 0; kt < NKT; kt++) {
        cp_wait<1>();
        __syncthreads();
        if (kt == 0) {
            int qr = warp * 16 + arow;
            u32 qb_ = su + QS_OFF + qr * 128;
#pragma unroll
            for (int t = 0; t < 4; t++)
                ldm4(qa[t], qb_ + (((2 * t + achk) ^ (qr & 7)) << 4));
        }
        u32 kbuf = su + KS_OFF + (kt & 1) * 8192;
        u32 vbuf = su + VS_OFF + (kt & 1) * 65536;

        // ---- S = QK^T (3-term) + exp + pack to P A-frags, all in regs ----
        u32 pah[4][4], pal[4][4];
#pragma unroll
        for (int mt = 0; mt < 4; mt++) {
            int kr = mt * 16 + brow;
            u32 kb_ = kbuf + kr * 128;
            int sw = kr & 7;
            u32 kh0[4], kh1[4], kl0[4], kl1[4];
            ldm4(kh0, kb_ + (((0 + bchk) ^ sw) << 4));
            ldm4(kh1, kb_ + (((2 + bchk) ^ sw) << 4));
            ldm4(kl0, kb_ + (((4 + bchk) ^ sw) << 4));
            ldm4(kl1, kb_ + (((6 + bchk) ^ sw) << 4));
#pragma unroll
            for (int g = 0; g < 2; g++) {
                float d[4] = {0.f, 0.f, 0.f, 0.f};
                mma16816(d, qa[0], &kh0[2 * g]);
                mma16816(d, qa[1], &kh1[2 * g]);
                mma16816(d, qa[0], &kl0[2 * g]);   // Qh * Klo
                mma16816(d, qa[1], &kl1[2 * g]);
                mma16816(d, qa[2], &kh0[2 * g]);   // Qlo * Kh
                mma16816(d, qa[3], &kh1[2 * g]);
                float p0 = ex2f(d[0] * LOG2E), p1 = ex2f(d[1] * LOG2E);
                float p2 = ex2f(d[2] * LOG2E), p3 = ex2f(d[3] * LOG2E);
                lsum0 += p0 + p1;
                lsum1 += p2 + p3;
                u32 h01, h23;
                asm("cvt.rn.bf16x2.f32 %0, %1, %2;" : "=r"(h01) : "f"(p1), "f"(p0));
                asm("cvt.rn.bf16x2.f32 %0, %1, %2;" : "=r"(h23) : "f"(p3), "f"(p2));
                float f0 = __uint_as_float(h01 << 16), f1 = __uint_as_float(h01 & 0xffff0000u);
                float f2 = __uint_as_float(h23 << 16), f3 = __uint_as_float(h23 & 0xffff0000u);
                u32 l01, l23;
                asm("cvt.rn.bf16x2.f32 %0, %1, %2;" : "=r"(l01) : "f"(p1 - f1), "f"(p0 - f0));
                asm("cvt.rn.bf16x2.f32 %0, %1, %2;" : "=r"(l23) : "f"(p3 - f3), "f"(p2 - f2));
                pah[mt][2 * g] = h01; pah[mt][2 * g + 1] = h23;
                pal[mt][2 * g] = l01; pal[mt][2 * g + 1] = l23;
            }
        }

        // ---- O += P V (3-term) ----
#pragma unroll
        for (int cb = 0; cb < 16; cb++) {
            int vr = cb * 16 + brow;
            u32 vh_ = vbuf + vr * 128;
            u32 vl_ = vh_ + 32768;
            int sw = vr & 7;
#pragma unroll
            for (int t = 0; t < 4; t++) {
                u32 vh[4], vl[4];
                ldm4(vh, vh_ + (((2 * t + bchk) ^ sw) << 4));
                ldm4(vl, vl_ + (((2 * t + bchk) ^ sw) << 4));
                mma16816(oacc[2 * cb],     pah[t], &vh[0]);
                mma16816(oacc[2 * cb + 1], pah[t], &vh[2]);
                mma16816(oacc[2 * cb],     pah[t], &vl[0]);  // Ph * Vlo
                mma16816(oacc[2 * cb + 1], pah[t], &vl[2]);
                mma16816(oacc[2 * cb],     pal[t], &vh[0]);  // Plo * Vh
                mma16816(oacc[2 * cb + 1], pal[t], &vh[2]);
            }
        }
        __syncthreads();
        if (kt + 2 < NKT) load_kv(su, Kb, Vhb, Vlb, kt + 2, tid);
        CP_COMMIT();
    }

    // ---- epilogue: row-sum reduce + normalize + store out[b][c][q] ----
    lsum0 += __shfl_xor_sync(0xffffffffu, lsum0, 1);
    lsum0 += __shfl_xor_sync(0xffffffffu, lsum0, 2);
    lsum1 += __shfl_xor_sync(0xffffffffu, lsum1, 1);
    lsum1 += __shfl_xor_sync(0xffffffffu, lsum1, 2);
    float inv0 = 1.0f / lsum0, inv1 = 1.0f / lsum1;
    float* og = Og + (size_t)b * CH * NQ;
    int q = q0 + warp * 16 + (lane >> 2);
#pragma unroll
    for (int ng = 0; ng < 32; ng++) {
        int c = ng * 8 + (lane & 3) * 2;
        og[(size_t)c * NQ + q]           = oacc[ng][0] * inv0;
        og[(size_t)(c + 1) * NQ + q]     = oacc[ng][1] * inv0;
        og[(size_t)c * NQ + q + 8]       = oacc[ng][2] * inv1;
        og[(size_t)(c + 1) * NQ + q + 8] = oacc[ng][3] * inv1;
    }
}

// ---------------- launch ----------------
extern "C" void kernel_launch(void* const* d_in, const int* in_sizes, int n_in,
                              void* d_out, int out_size) {
    const float* f1 = (const float*)d_in[0];
    const float* f2 = (const float*)d_in[1];
    const float* f3 = (const float*)d_in[2];
    const float* wq = (const float*)d_in[3];
    const float* bq = (const float*)d_in[4];
    const float* wk = (const float*)d_in[5];
    const float* bk = (const float*)d_in[6];
    const float* wv = (const float*)d_in[7];
    const float* bv = (const float*)d_in[8];
    float* out = (float*)d_out;

    __nv_bfloat16 *qp, *kp, *vhp, *vlp;
    cudaGetSymbolAddress((void**)&qp, g_Qhl);
    cudaGetSymbolAddress((void**)&kp, g_Khl);
    cudaGetSymbolAddress((void**)&vhp, g_VTh);
    cudaGetSymbolAddress((void**)&vlp, g_VTl);

    dim3 gqk(NQ / 64, 1, BATCH);
    conv_qk<<<gqk, 128>>>(f1, wq, bq, qp);
    conv_qk<<<gqk, 128>>>(f2, wk, bk, kp);
    dim3 gv(NQ / 64, CH / 64, BATCH);
    conv_v<<<gv, 256>>>(f3, wv, bv, vhp, vlp);

    cudaFuncSetAttribute(attn_kernel, cudaFuncAttributeMaxDynamicSharedMemorySize,
                         ATTN_SMEM);
    dim3 ga(NQ / 128, BATCH);
    attn_kernel<<<ga, 256, ATTN_SMEM>>>(qp, kp, vhp, vlp, out);
}

// round 10
// speedup vs baseline: 13.4757x; 1.3288x over previous
#include <cuda_runtime.h>
#include <cuda_bf16.h>
#include <cuda_fp16.h>

#define BATCH 8
#define CH    256
#define CQK   32
#define NQ    4096
#define LOG2E 1.4426950408889634f

typedef unsigned long long ull;
typedef unsigned int u32;

// ---------------- scratch ----------------
__device__ __half g_Qhl[BATCH * NQ * 64];   // [b][n][32 hi | 32 lo] fp16
__device__ __half g_Khl[BATCH * NQ * 64];   // [b][m][32 hi | 32 lo] fp16
__device__ __half g_VTh[BATCH * CH * NQ];   // [b][c][m] fp16 (single precision level)

// ---------------- helpers ----------------
__device__ __forceinline__ void ffma2(ull& d, ull a, ull b) {
    asm("fma.rn.f32x2 %0, %1, %2, %0;" : "+l"(d) : "l"(a), "l"(b));
}
__device__ __forceinline__ ull pack2(float x, float y) {
    ull r; asm("mov.b64 %0, {%1, %2};" : "=l"(r) : "f"(x), "f"(y)); return r;
}
__device__ __forceinline__ float2 unpack2(ull v) {
    float2 f; asm("mov.b64 {%0, %1}, %2;" : "=f"(f.x), "=f"(f.y) : "l"(v)); return f;
}
__device__ __forceinline__ float ex2f(float x) {
    float r; asm("ex2.approx.f32 %0, %1;" : "=f"(r) : "f"(x)); return r;
}
__device__ __forceinline__ u32 smem_u32(const void* p) {
    u32 a; asm("{ .reg .u64 t; cvta.to.shared.u64 t, %1; cvt.u32.u64 %0, t; }" : "=r"(a) : "l"(p));
    return a;
}
__device__ __forceinline__ void cpa(u32 dst, const void* src) {
    asm volatile("cp.async.cg.shared.global [%0], [%1], 16;" :: "r"(dst), "l"(src));
}
#define CP_COMMIT() asm volatile("cp.async.commit_group;" ::: "memory")
template<int N> __device__ __forceinline__ void cp_wait() {
    asm volatile("cp.async.wait_group %0;" :: "n"(N) : "memory");
}
__device__ __forceinline__ void ldm4(u32* r, u32 addr) {
    asm volatile("ldmatrix.sync.aligned.m8n8.x4.shared.b16 {%0,%1,%2,%3}, [%4];"
                 : "=r"(r[0]), "=r"(r[1]), "=r"(r[2]), "=r"(r[3]) : "r"(addr));
}
__device__ __forceinline__ void mma16816(float* d, const u32* a, const u32* b) {
    asm volatile(
        "mma.sync.aligned.m16n8k16.row.col.f32.f16.f16.f32 "
        "{%0,%1,%2,%3}, {%4,%5,%6,%7}, {%8,%9}, {%0,%1,%2,%3};"
        : "+f"(d[0]), "+f"(d[1]), "+f"(d[2]), "+f"(d[3])
        : "r"(a[0]), "r"(a[1]), "r"(a[2]), "r"(a[3]), "r"(b[0]), "r"(b[1]));
}

// ---------------- conv -> Q/K fp16 hi|lo ([n][32hi|32lo]) ----------------
__global__ void conv_qk(const float* __restrict__ F, const float* __restrict__ W,
                        const float* __restrict__ bias, __half* __restrict__ out) {
    __shared__ float Fs[64][64];
    __shared__ float Ws[64][36];
    const int tid = threadIdx.x;
    const int tx = tid & 15, ty = tid >> 4;
    const int n0 = blockIdx.x * 64, b = blockIdx.z;
    const float* Fb = F + (size_t)b * CH * NQ;

    ull acc2[4][2];
#pragma unroll
    for (int i = 0; i < 4; i++) { acc2[i][0] = 0ULL; acc2[i][1] = 0ULL; }

    for (int c0 = 0; c0 < CH; c0 += 64) {
        for (int idx = tid; idx < 1024; idx += 128) {
            int r = idx >> 4, c4 = idx & 15;
            *(float4*)&Fs[r][c4 * 4] = *(const float4*)&Fb[(size_t)(c0 + r) * NQ + n0 + c4 * 4];
        }
        for (int idx = tid; idx < 512; idx += 128) {
            int o_r = idx >> 4, c4 = idx & 15;
            float4 w4 = *(const float4*)&W[(size_t)o_r * CH + c0 + c4 * 4];
            Ws[c4 * 4 + 0][o_r] = w4.x; Ws[c4 * 4 + 1][o_r] = w4.y;
            Ws[c4 * 4 + 2][o_r] = w4.z; Ws[c4 * 4 + 3][o_r] = w4.w;
        }
        __syncthreads();
#pragma unroll 8
        for (int cc = 0; cc < 64; cc++) {
            float4 f4 = *(const float4*)&Fs[cc][tx * 4];
            ulonglong2 w2 = *(const ulonglong2*)&Ws[cc][ty * 4];
            float fa[4] = {f4.x, f4.y, f4.z, f4.w};
#pragma unroll
            for (int i = 0; i < 4; i++) {
                ull fp = pack2(fa[i], fa[i]);
                ffma2(acc2[i][0], fp, w2.x);
                ffma2(acc2[i][1], fp, w2.y);
            }
        }
        __syncthreads();
    }
    float bs[4];
#pragma unroll
    for (int j = 0; j < 4; j++) bs[j] = bias[ty * 4 + j];
#pragma unroll
    for (int i = 0; i < 4; i++) {
        int n = n0 + tx * 4 + i;
        uint2 Hu, Lu;
        {
            float2 u = unpack2(acc2[i][0]);
            float p0 = u.x + bs[0], p1 = u.y + bs[1];
            __half2 hh = __floats2half2_rn(p0, p1);
            float2 hf = __half22float2(hh);
            __half2 ll = __floats2half2_rn(p0 - hf.x, p1 - hf.y);
            Hu.x = *(u32*)&hh; Lu.x = *(u32*)&ll;
        }
        {
            float2 u = unpack2(acc2[i][1]);
            float p0 = u.x + bs[2], p1 = u.y + bs[3];
            __half2 hh = __floats2half2_rn(p0, p1);
            float2 hf = __half22float2(hh);
            __half2 ll = __floats2half2_rn(p0 - hf.x, p1 - hf.y);
            Hu.y = *(u32*)&hh; Lu.y = *(u32*)&ll;
        }
        size_t base = ((size_t)b * NQ + n) * 64;
        *(uint2*)&out[base + ty * 4]      = Hu;
        *(uint2*)&out[base + 32 + ty * 4] = Lu;
    }
}

// V conv -> transposed fp16 [b][c][m]
__global__ void conv_v(const float* __restrict__ F, const float* __restrict__ W,
                       const float* __restrict__ bias, __half* __restrict__ oh) {
    __shared__ float Fs[64][64];
    __shared__ float Ws[64][68];
    const int tid = threadIdx.x;
    const int tx = tid & 15, ty = tid >> 4;
    const int n0 = blockIdx.x * 64, o0 = blockIdx.y * 64, b = blockIdx.z;
    const float* Fb = F + (size_t)b * CH * NQ;

    ull acc2[4][2];
#pragma unroll
    for (int i = 0; i < 4; i++) { acc2[i][0] = 0ULL; acc2[i][1] = 0ULL; }

    for (int c0 = 0; c0 < CH; c0 += 64) {
        for (int idx = tid; idx < 1024; idx += 256) {
            int r = idx >> 4, c4 = idx & 15;
            *(float4*)&Fs[r][c4 * 4] = *(const float4*)&Fb[(size_t)(c0 + r) * NQ + n0 + c4 * 4];
        }
        for (int idx = tid; idx < 1024; idx += 256) {
            int o_r = idx >> 4, c4 = idx & 15;
            float4 w4 = *(const float4*)&W[(size_t)(o0 + o_r) * CH + c0 + c4 * 4];
            Ws[c4 * 4 + 0][o_r] = w4.x; Ws[c4 * 4 + 1][o_r] = w4.y;
            Ws[c4 * 4 + 2][o_r] = w4.z; Ws[c4 * 4 + 3][o_r] = w4.w;
        }
        __syncthreads();
#pragma unroll 8
        for (int cc = 0; cc < 64; cc++) {
            float4 f4 = *(const float4*)&Fs[cc][tx * 4];
            ulonglong2 w2 = *(const ulonglong2*)&Ws[cc][ty * 4];
            float fa[4] = {f4.x, f4.y, f4.z, f4.w};
#pragma unroll
            for (int i = 0; i < 4; i++) {
                ull fp = pack2(fa[i], fa[i]);
                ffma2(acc2[i][0], fp, w2.x);
                ffma2(acc2[i][1], fp, w2.y);
            }
        }
        __syncthreads();
    }
    float accv[4][4];
#pragma unroll
    for (int i = 0; i < 4; i++) {
        float2 u0 = unpack2(acc2[i][0]), u1 = unpack2(acc2[i][1]);
        accv[i][0] = u0.x; accv[i][1] = u0.y; accv[i][2] = u1.x; accv[i][3] = u1.y;
    }
#pragma unroll
    for (int j = 0; j < 4; j++) {
        int o = o0 + ty * 4 + j;
        float bj = bias[o];
        __half2 h0 = __floats2half2_rn(accv[0][j] + bj, accv[1][j] + bj);
        __half2 h1 = __floats2half2_rn(accv[2][j] + bj, accv[3][j] + bj);
        uint2 Hu = make_uint2(*(u32*)&h0, *(u32*)&h1);
        size_t base = ((size_t)b * CH + o) * NQ + n0 + tx * 4;
        *(uint2*)&oh[base] = Hu;
    }
}

// ---------------- mma.sync flash attention (fp16) ----------------
// CTA: 128 q (8 warps x 16q) x 64 tiles of 64 keys. No max-subtraction softmax
// (P pre-scaled by 2^-8 in the exponent; softmax is scale-invariant).
// smem: Q[128x128B] | K 2x[64x128B] | V 2x[256x128B]
#define QS_OFF 0
#define KS_OFF 16384
#define VS_OFF 32768
#define NKT    (NQ / 64)      // 64 key tiles
#define ATTN_SMEM 98304

__device__ __forceinline__ void load_kv(u32 su, const __half* Kb,
                                        const __half* Vhb, int kt, int tid) {
    int bf = kt & 1;
    for (int i = tid; i < 512; i += 256) {
        int m = i >> 3, j = i & 7;
        cpa(su + KS_OFF + bf * 8192 + m * 128 + ((j ^ (m & 7)) << 4),
            Kb + ((size_t)(kt * 64 + m)) * 64 + j * 8);
    }
    for (int i = tid; i < 2048; i += 256) {
        int c = i >> 3, j = i & 7;
        cpa(su + VS_OFF + bf * 32768 + c * 128 + ((j ^ (c & 7)) << 4),
            Vhb + (size_t)c * NQ + kt * 64 + j * 8);
    }
}

__global__ void __launch_bounds__(256, 1)
attn_kernel(const __half* __restrict__ Qg, const __half* __restrict__ Kg,
            const __half* __restrict__ Vhg, float* __restrict__ Og) {
    extern __shared__ char smx[];
    const u32 su = smem_u32(smx);
    const int tid = threadIdx.x, warp = tid >> 5, lane = tid & 31;
    const int b = blockIdx.y, q0 = blockIdx.x * 128;

    const __half* Qb  = Qg  + ((size_t)b * NQ + q0) * 64;
    const __half* Kb  = Kg  + (size_t)b * NQ * 64;
    const __half* Vhb = Vhg + (size_t)b * CH * NQ;

    // prologue: Q + K0/V0 (group0), K1/V1 (group1)
    for (int i = tid; i < 1024; i += 256) {
        int q = i >> 3, j = i & 7;
        cpa(su + QS_OFF + q * 128 + ((j ^ (q & 7)) << 4), Qb + (size_t)q * 64 + j * 8);
    }
    load_kv(su, Kb, Vhb, 0, tid);
    CP_COMMIT();
    load_kv(su, Kb, Vhb, 1, tid);
    CP_COMMIT();

    float oacc[32][4];
#pragma unroll
    for (int i = 0; i < 32; i++)
#pragma unroll
        for (int j = 0; j < 4; j++) oacc[i][j] = 0.f;
    float lsum0 = 0.f, lsum1 = 0.f;
    u32 qa[4][4];

    // ldmatrix per-thread addressing
    const int arow = (lane & 7) | (((lane >> 3) & 1) << 3);  // A-type
    const int achk = lane >> 4;
    const int brow = (lane & 7) | ((lane >> 4) << 3);        // B-type
    const int bchk = (lane >> 3) & 1;

    for (int kt = 0; kt < NKT; kt++) {
        cp_wait<1>();
        __syncthreads();
        if (kt == 0) {
            int qr = warp * 16 + arow;
            u32 qb_ = su + QS_OFF + qr * 128;
#pragma unroll
            for (int t = 0; t < 4; t++)
                ldm4(qa[t], qb_ + (((2 * t + achk) ^ (qr & 7)) << 4));
        }
        u32 kbuf = su + KS_OFF + (kt & 1) * 8192;
        u32 vbuf = su + VS_OFF + (kt & 1) * 32768;

        // ---- S = QK^T (3-term fp16) + exp(S - 8ln2) + pack P hi/lo frags ----
        u32 pah[4][4], pal[4][4];
#pragma unroll
        for (int mt = 0; mt < 4; mt++) {
            int kr = mt * 16 + brow;
            u32 kb_ = kbuf + kr * 128;
            int sw = kr & 7;
            u32 kh0[4], kh1[4], kl0[4], kl1[4];
            ldm4(kh0, kb_ + (((0 + bchk) ^ sw) << 4));
            ldm4(kh1, kb_ + (((2 + bchk) ^ sw) << 4));
            ldm4(kl0, kb_ + (((4 + bchk) ^ sw) << 4));
            ldm4(kl1, kb_ + (((6 + bchk) ^ sw) << 4));
#pragma unroll
            for (int g = 0; g < 2; g++) {
                float d[4] = {0.f, 0.f, 0.f, 0.f};
                mma16816(d, qa[0], &kh0[2 * g]);
                mma16816(d, qa[1], &kh1[2 * g]);
                mma16816(d, qa[0], &kl0[2 * g]);   // Qh * Klo
                mma16816(d, qa[1], &kl1[2 * g]);
                mma16816(d, qa[2], &kh0[2 * g]);   // Qlo * Kh
                mma16816(d, qa[3], &kh1[2 * g]);
                float p0 = ex2f(fmaf(d[0], LOG2E, -8.0f));
                float p1 = ex2f(fmaf(d[1], LOG2E, -8.0f));
                float p2 = ex2f(fmaf(d[2], LOG2E, -8.0f));
                float p3 = ex2f(fmaf(d[3], LOG2E, -8.0f));
                lsum0 += p0 + p1;
                lsum1 += p2 + p3;
                __half2 hh01 = __floats2half2_rn(p0, p1);
                __half2 hh23 = __floats2half2_rn(p2, p3);
                float2 hf01 = __half22float2(hh01);
                float2 hf23 = __half22float2(hh23);
                __half2 ll01 = __floats2half2_rn(p0 - hf01.x, p1 - hf01.y);
                __half2 ll23 = __floats2half2_rn(p2 - hf23.x, p3 - hf23.y);
                pah[mt][2 * g] = *(u32*)&hh01; pah[mt][2 * g + 1] = *(u32*)&hh23;
                pal[mt][2 * g] = *(u32*)&ll01; pal[mt][2 * g + 1] = *(u32*)&ll23;
            }
        }

        // ---- O += P V (2-term: (Ph + Pl) * Vh) ----
#pragma unroll
        for (int cb = 0; cb < 16; cb++) {
            int vr = cb * 16 + brow;
            u32 vh_ = vbuf + vr * 128;
            int sw = vr & 7;
#pragma unroll
            for (int t = 0; t < 4; t++) {
                u32 vh[4];
                ldm4(vh, vh_ + (((2 * t + bchk) ^ sw) << 4));
                mma16816(oacc[2 * cb],     pah[t], &vh[0]);
                mma16816(oacc[2 * cb + 1], pah[t], &vh[2]);
                mma16816(oacc[2 * cb],     pal[t], &vh[0]);  // Plo * Vh
                mma16816(oacc[2 * cb + 1], pal[t], &vh[2]);
            }
        }
        __syncthreads();
        if (kt + 2 < NKT) load_kv(su, Kb, Vhb, kt + 2, tid);
        CP_COMMIT();
    }

    // ---- epilogue: row-sum reduce + normalize + store out[b][c][q] ----
    lsum0 += __shfl_xor_sync(0xffffffffu, lsum0, 1);
    lsum0 += __shfl_xor_sync(0xffffffffu, lsum0, 2);
    lsum1 += __shfl_xor_sync(0xffffffffu, lsum1, 1);
    lsum1 += __shfl_xor_sync(0xffffffffu, lsum1, 2);
    float inv0 = 1.0f / lsum0, inv1 = 1.0f / lsum1;
    float* og = Og + (size_t)b * CH * NQ;
    int q = q0 + warp * 16 + (lane >> 2);
#pragma unroll
    for (int ng = 0; ng < 32; ng++) {
        int c = ng * 8 + (lane & 3) * 2;
        og[(size_t)c * NQ + q]           = oacc[ng][0] * inv0;
        og[(size_t)(c + 1) * NQ + q]     = oacc[ng][1] * inv0;
        og[(size_t)c * NQ + q + 8]       = oacc[ng][2] * inv1;
        og[(size_t)(c + 1) * NQ + q + 8] = oacc[ng][3] * inv1;
    }
}

// ---------------- launch ----------------
extern "C" void kernel_launch(void* const* d_in, const int* in_sizes, int n_in,
                              void* d_out, int out_size) {
    const float* f1 = (const float*)d_in[0];
    const float* f2 = (const float*)d_in[1];
    const float* f3 = (const float*)d_in[2];
    const float* wq = (const float*)d_in[3];
    const float* bq = (const float*)d_in[4];
    const float* wk = (const float*)d_in[5];
    const float* bk = (const float*)d_in[6];
    const float* wv = (const float*)d_in[7];
    const float* bv = (const float*)d_in[8];
    float* out = (float*)d_out;

    __half *qp, *kp, *vhp;
    cudaGetSymbolAddress((void**)&qp, g_Qhl);
    cudaGetSymbolAddress((void**)&kp, g_Khl);
    cudaGetSymbolAddress((void**)&vhp, g_VTh);

    dim3 gqk(NQ / 64, 1, BATCH);
    conv_qk<<<gqk, 128>>>(f1, wq, bq, qp);
    conv_qk<<<gqk, 128>>>(f2, wk, bk, kp);
    dim3 gv(NQ / 64, CH / 64, BATCH);
    conv_v<<<gv, 256>>>(f3, wv, bv, vhp);

    cudaFuncSetAttribute(attn_kernel, cudaFuncAttributeMaxDynamicSharedMemorySize,
                         ATTN_SMEM);
    dim3 ga(NQ / 128, BATCH);
    attn_kernel<<<ga, 256, ATTN_SMEM>>>(qp, kp, vhp, out);
}

// round 11
// speedup vs baseline: 15.9254x; 1.1818x over previous
#include <cuda_runtime.h>
#include <cuda_bf16.h>
#include <cuda_fp16.h>

#define BATCH 8
#define CH    256
#define CQK   32
#define NQ    4096
#define LOG2E 1.4426950408889634f

typedef unsigned long long ull;
typedef unsigned int u32;

// ---------------- scratch ----------------
__device__ __half g_Qhl[BATCH * NQ * 64];   // [b][n][32 hi | 32 lo] fp16
__device__ __half g_Khl[BATCH * NQ * 64];   // [b][m][32 hi | 32 lo] fp16
__device__ __half g_VTh[BATCH * CH * NQ];   // [b][c][m] fp16
__device__ __half g_Whl[163840];            // wq h/l | wk h/l | wv h/l

// ---------------- helpers ----------------
__device__ __forceinline__ float ex2f(float x) {
    float r; asm("ex2.approx.f32 %0, %1;" : "=f"(r) : "f"(x)); return r;
}
__device__ __forceinline__ u32 smem_u32(const void* p) {
    u32 a; asm("{ .reg .u64 t; cvta.to.shared.u64 t, %1; cvt.u32.u64 %0, t; }" : "=r"(a) : "l"(p));
    return a;
}
__device__ __forceinline__ void cpa(u32 dst, const void* src) {
    asm volatile("cp.async.cg.shared.global [%0], [%1], 16;" :: "r"(dst), "l"(src));
}
#define CP_COMMIT() asm volatile("cp.async.commit_group;" ::: "memory")
template<int N> __device__ __forceinline__ void cp_wait() {
    asm volatile("cp.async.wait_group %0;" :: "n"(N) : "memory");
}
__device__ __forceinline__ void ldm4(u32* r, u32 addr) {
    asm volatile("ldmatrix.sync.aligned.m8n8.x4.shared.b16 {%0,%1,%2,%3}, [%4];"
                 : "=r"(r[0]), "=r"(r[1]), "=r"(r[2]), "=r"(r[3]) : "r"(addr));
}
__device__ __forceinline__ void ldm4t(u32* r, u32 addr) {
    asm volatile("ldmatrix.sync.aligned.m8n8.x4.trans.shared.b16 {%0,%1,%2,%3}, [%4];"
                 : "=r"(r[0]), "=r"(r[1]), "=r"(r[2]), "=r"(r[3]) : "r"(addr));
}
__device__ __forceinline__ void mma16816(float* d, const u32* a, const u32* b) {
    asm volatile(
        "mma.sync.aligned.m16n8k16.row.col.f32.f16.f16.f32 "
        "{%0,%1,%2,%3}, {%4,%5,%6,%7}, {%8,%9}, {%0,%1,%2,%3};"
        : "+f"(d[0]), "+f"(d[1]), "+f"(d[2]), "+f"(d[3])
        : "r"(a[0]), "r"(a[1]), "r"(a[2]), "r"(a[3]), "r"(b[0]), "r"(b[1]));
}

// ---------------- prep: W fp32 -> fp16 hi/lo ----------------
__global__ void prep_w(const float* __restrict__ wq, const float* __restrict__ wk,
                       const float* __restrict__ wv, __half* __restrict__ o) {
    int idx = blockIdx.x * 256 + threadIdx.x;
    float v; int hoff, loff, pos;
    if (idx < 8192)       { v = wq[idx];         hoff = 0;     loff = 8192;  pos = idx; }
    else if (idx < 16384) { v = wk[idx - 8192];  hoff = 16384; loff = 24576; pos = idx - 8192; }
    else if (idx < 81920) { v = wv[idx - 16384]; hoff = 32768; loff = 98304; pos = idx - 16384; }
    else return;
    __half h = __float2half_rn(v);
    o[hoff + pos] = h;
    o[loff + pos] = __float2half_rn(v - __half2float(h));
}

// F chunk convert: pre[8] float4 (32 c x 256 n) -> smem hi/lo [c][n] swizzled
__device__ __forceinline__ void f_store(char* smx, u32 fh_off, u32 fl_off,
                                        const float4* pre, int tid) {
#pragma unroll
    for (int i = 0; i < 8; i++) {
        int idx = i * 256 + tid, row = idx >> 6, n = (idx & 63) * 4;
        float4 f = pre[i];
        __half2 h0 = __floats2half2_rn(f.x, f.y);
        __half2 h1 = __floats2half2_rn(f.z, f.w);
        float2 g0 = __half22float2(h0), g1 = __half22float2(h1);
        __half2 l0 = __floats2half2_rn(f.x - g0.x, f.y - g0.y);
        __half2 l1 = __floats2half2_rn(f.z - g1.x, f.w - g1.y);
        u32 off = row * 512 + (((n >> 3) ^ (row & 7)) << 4) + (n & 7) * 2;
        *(uint2*)(smx + fh_off + off) = make_uint2(*(u32*)&h0, *(u32*)&h1);
        *(uint2*)(smx + fl_off + off) = make_uint2(*(u32*)&l0, *(u32*)&l1);
    }
}

// ---------------- conv Q/K via HMMA: out [n][32hi|32lo] ----------------
// smem: Wh[0,16K) Wl[16K,32K) Fh[32K,48K) Fl[48K,64K); staging reuse [32K, 68K)
#define QK_SMEM 69632
__global__ void __launch_bounds__(256, 1)
conv_qk_mma(const float* __restrict__ F, const __half* __restrict__ Wh,
            const __half* __restrict__ Wl, const float* __restrict__ bias,
            __half* __restrict__ out) {
    extern __shared__ char smx[];
    const u32 su = smem_u32(smx);
    const int tid = threadIdx.x, warp = tid >> 5, lane = tid & 31;
    const int n0 = blockIdx.x * 256, b = blockIdx.z;
    const float* Fb = F + (size_t)b * CH * NQ;

    for (int i = tid; i < 2048; i += 256) {
        int arr = i >> 10, rem = i & 1023, row = rem >> 5, cch = rem & 31;
        const __half* src = (arr ? Wl : Wh) + row * 256 + cch * 8;
        *(uint4*)(smx + arr * 16384 + row * 512 + ((cch ^ (row & 7)) << 4)) =
            *(const uint4*)src;
    }

    float4 pre[8];
#pragma unroll
    for (int i = 0; i < 8; i++) {
        int idx = i * 256 + tid, row = idx >> 6, n = (idx & 63) * 4;
        pre[i] = *(const float4*)&Fb[(size_t)row * NQ + n0 + n];
    }

    float oacc[8][4];
#pragma unroll
    for (int i = 0; i < 8; i++)
#pragma unroll
        for (int j = 0; j < 4; j++) oacc[i][j] = 0.f;

    const int arow = (lane & 7) | (((lane >> 3) & 1) << 3);
    const int achk = lane >> 4;
    const int krow = (lane & 7) + ((lane >> 3) & 1) * 8;
    const int nsel = lane >> 4;
    const int ow = warp >> 2, nw = warp & 3;

    for (int ck = 0; ck < 8; ck++) {
        __syncthreads();
        f_store(smx, 32768, 49152, pre, tid);
        if (ck < 7) {
#pragma unroll
            for (int i = 0; i < 8; i++) {
                int idx = i * 256 + tid, row = idx >> 6, n = (idx & 63) * 4;
                pre[i] = *(const float4*)&Fb[(size_t)((ck + 1) * 32 + row) * NQ + n0 + n];
            }
        }
        __syncthreads();
#pragma unroll
        for (int kk = 0; kk < 2; kk++) {
            int orow = ow * 16 + arow;
            int cchunk = ck * 4 + kk * 2 + achk;
            u32 aaddr = su + orow * 512 + ((cchunk ^ (orow & 7)) << 4);
            u32 ah[4], al[4];
            ldm4(ah, aaddr);
            ldm4(al, aaddr + 16384);
            int crow = kk * 16 + krow;
#pragma unroll
            for (int ns = 0; ns < 4; ns++) {
                int nch = (nw * 64 + ns * 16 + nsel * 8) >> 3;
                u32 baddr = su + 32768 + crow * 512 + ((nch ^ (crow & 7)) << 4);
                u32 bh[4], bl[4];
                ldm4t(bh, baddr);
                ldm4t(bl, baddr + 16384);
#pragma unroll
                for (int g = 0; g < 2; g++) {
                    float* d = oacc[ns * 2 + g];
                    mma16816(d, ah, &bh[2 * g]);
                    mma16816(d, ah, &bl[2 * g]);
                    mma16816(d, al, &bh[2 * g]);
                }
            }
        }
    }

    // epilogue: bias + hi/lo split -> staging [n 256][72 halves] at byte 32768
    __syncthreads();
    const int or0 = ow * 16 + (lane >> 2);
    const float b0 = bias[or0], b1 = bias[or0 + 8];
    __half* stg = (__half*)(smx + 32768);
#pragma unroll
    for (int j = 0; j < 8; j++) {
        int n = nw * 64 + j * 8 + (lane & 3) * 2;
#pragma unroll
        for (int e = 0; e < 2; e++) {
            float v0 = oacc[j][e] + b0;          // row or0,   col n+e
            float v1 = oacc[j][2 + e] + b1;      // row or0+8, col n+e
            __half h0 = __float2half_rn(v0);
            __half h1 = __float2half_rn(v1);
            stg[(n + e) * 72 + or0] = h0;
            stg[(n + e) * 72 + 32 + or0] = __float2half_rn(v0 - __half2float(h0));
            stg[(n + e) * 72 + or0 + 8] = h1;
            stg[(n + e) * 72 + 32 + or0 + 8] = __float2half_rn(v1 - __half2float(h1));
        }
    }
    __syncthreads();
    for (int i = tid; i < 2048; i += 256) {
        int n = i >> 3, u4 = i & 7;
        *(uint4*)&out[((size_t)b * NQ + n0 + n) * 64 + u4 * 8] =
            *(uint4*)(stg + n * 72 + u4 * 8);
    }
}

// ---------------- conv V via HMMA: out [c][m] fp16 ----------------
// smem: Wh[0,32K) Wl[32K,64K) Fh[64K,80K) Fl[80K,96K); staging reuse [0, 34816)
#define CV_SMEM 98304
__global__ void __launch_bounds__(256, 1)
conv_v_mma(const float* __restrict__ F, const __half* __restrict__ Wh,
           const __half* __restrict__ Wl, const float* __restrict__ bias,
           __half* __restrict__ out) {
    extern __shared__ char smx[];
    const u32 su = smem_u32(smx);
    const int tid = threadIdx.x, warp = tid >> 5, lane = tid & 31;
    const int n0 = blockIdx.x * 256, o0 = blockIdx.y * 64, b = blockIdx.z;
    const float* Fb = F + (size_t)b * CH * NQ;

    for (int i = tid; i < 4096; i += 256) {
        int arr = i >> 11, rem = i & 2047, row = rem >> 5, cch = rem & 31;
        const __half* src = (arr ? Wl : Wh) + (size_t)(o0 + row) * 256 + cch * 8;
        *(uint4*)(smx + arr * 32768 + row * 512 + ((cch ^ (row & 7)) << 4)) =
            *(const uint4*)src;
    }

    float4 pre[8];
#pragma unroll
    for (int i = 0; i < 8; i++) {
        int idx = i * 256 + tid, row = idx >> 6, n = (idx & 63) * 4;
        pre[i] = *(const float4*)&Fb[(size_t)row * NQ + n0 + n];
    }

    float oacc[16][4];
#pragma unroll
    for (int i = 0; i < 16; i++)
#pragma unroll
        for (int j = 0; j < 4; j++) oacc[i][j] = 0.f;

    const int arow = (lane & 7) | (((lane >> 3) & 1) << 3);
    const int achk = lane >> 4;
    const int krow = (lane & 7) + ((lane >> 3) & 1) * 8;
    const int nsel = lane >> 4;
    const int ob = warp >> 1, nw = warp & 1;

    for (int ck = 0; ck < 8; ck++) {
        __syncthreads();
        f_store(smx, 65536, 81920, pre, tid);
        if (ck < 7) {
#pragma unroll
            for (int i = 0; i < 8; i++) {
                int idx = i * 256 + tid, row = idx >> 6, n = (idx & 63) * 4;
                pre[i] = *(const float4*)&Fb[(size_t)((ck + 1) * 32 + row) * NQ + n0 + n];
            }
        }
        __syncthreads();
#pragma unroll
        for (int kk = 0; kk < 2; kk++) {
            int orow = ob * 16 + arow;
            int cchunk = ck * 4 + kk * 2 + achk;
            u32 aaddr = su + orow * 512 + ((cchunk ^ (orow & 7)) << 4);
            u32 ah[4], al[4];
            ldm4(ah, aaddr);
            ldm4(al, aaddr + 32768);
            int crow = kk * 16 + krow;
#pragma unroll
            for (int ns = 0; ns < 8; ns++) {
                int nch = (nw * 128 + ns * 16 + nsel * 8) >> 3;
                u32 baddr = su + 65536 + crow * 512 + ((nch ^ (crow & 7)) << 4);
                u32 bh[4], bl[4];
                ldm4t(bh, baddr);
                ldm4t(bl, baddr + 16384);
#pragma unroll
                for (int g = 0; g < 2; g++) {
                    float* d = oacc[ns * 2 + g];
                    mma16816(d, ah, &bh[2 * g]);
                    mma16816(d, ah, &bl[2 * g]);
                    mma16816(d, al, &bh[2 * g]);
                }
            }
        }
    }

    // epilogue -> staging [o 64][272 halves] at byte 0 (reuse W region)
    __syncthreads();
    const int or0 = ob * 16 + (lane >> 2);
    const float b0 = bias[o0 + or0], b1 = bias[o0 + or0 + 8];
    __half* stg = (__half*)smx;
#pragma unroll
    for (int j = 0; j < 16; j++) {
        int n = nw * 128 + j * 8 + (lane & 3) * 2;
        __half2 h0 = __floats2half2_rn(oacc[j][0] + b0, oacc[j][1] + b0);
        __half2 h1 = __floats2half2_rn(oacc[j][2] + b1, oacc[j][3] + b1);
        *(__half2*)&stg[or0 * 272 + n] = h0;
        *(__half2*)&stg[(or0 + 8) * 272 + n] = h1;
    }
    __syncthreads();
    for (int i = tid; i < 2048; i += 256) {
        int row = i >> 5, c4 = i & 31;
        *(uint4*)&out[((size_t)b * CH + o0 + row) * NQ + n0 + c4 * 8] =
            *(uint4*)(stg + row * 272 + c4 * 8);
    }
}

// ---------------- mma.sync flash attention (fp16) — unchanged from R10 ----------------
#define QS_OFF 0
#define KS_OFF 16384
#define VS_OFF 32768
#define NKT    (NQ / 64)
#define ATTN_SMEM 98304

__device__ __forceinline__ void load_kv(u32 su, const __half* Kb,
                                        const __half* Vhb, int kt, int tid) {
    int bf = kt & 1;
    for (int i = tid; i < 512; i += 256) {
        int m = i >> 3, j = i & 7;
        cpa(su + KS_OFF + bf * 8192 + m * 128 + ((j ^ (m & 7)) << 4),
            Kb + ((size_t)(kt * 64 + m)) * 64 + j * 8);
    }
    for (int i = tid; i < 2048; i += 256) {
        int c = i >> 3, j = i & 7;
        cpa(su + VS_OFF + bf * 32768 + c * 128 + ((j ^ (c & 7)) << 4),
            Vhb + (size_t)c * NQ + kt * 64 + j * 8);
    }
}

__global__ void __launch_bounds__(256, 1)
attn_kernel(const __half* __restrict__ Qg, const __half* __restrict__ Kg,
            const __half* __restrict__ Vhg, float* __restrict__ Og) {
    extern __shared__ char smx[];
    const u32 su = smem_u32(smx);
    const int tid = threadIdx.x, warp = tid >> 5, lane = tid & 31;
    const int b = blockIdx.y, q0 = blockIdx.x * 128;

    const __half* Qb  = Qg  + ((size_t)b * NQ + q0) * 64;
    const __half* Kb  = Kg  + (size_t)b * NQ * 64;
    const __half* Vhb = Vhg + (size_t)b * CH * NQ;

    for (int i = tid; i < 1024; i += 256) {
        int q = i >> 3, j = i & 7;
        cpa(su + QS_OFF + q * 128 + ((j ^ (q & 7)) << 4), Qb + (size_t)q * 64 + j * 8);
    }
    load_kv(su, Kb, Vhb, 0, tid);
    CP_COMMIT();
    load_kv(su, Kb, Vhb, 1, tid);
    CP_COMMIT();

    float oacc[32][4];
#pragma unroll
    for (int i = 0; i < 32; i++)
#pragma unroll
        for (int j = 0; j < 4; j++) oacc[i][j] = 0.f;
    float lsum0 = 0.f, lsum1 = 0.f;
    u32 qa[4][4];

    const int arow = (lane & 7) | (((lane >> 3) & 1) << 3);
    const int achk = lane >> 4;
    const int brow = (lane & 7) | ((lane >> 4) << 3);
    const int bchk = (lane >> 3) & 1;

    for (int kt = 0; kt < NKT; kt++) {
        cp_wait<1>();
        __syncthreads();
        if (kt == 0) {
            int qr = warp * 16 + arow;
            u32 qb_ = su + QS_OFF + qr * 128;
#pragma unroll
            for (int t = 0; t < 4; t++)
                ldm4(qa[t], qb_ + (((2 * t + achk) ^ (qr & 7)) << 4));
        }
        u32 kbuf = su + KS_OFF + (kt & 1) * 8192;
        u32 vbuf = su + VS_OFF + (kt & 1) * 32768;

        u32 pah[4][4], pal[4][4];
#pragma unroll
        for (int mt = 0; mt < 4; mt++) {
            int kr = mt * 16 + brow;
            u32 kb_ = kbuf + kr * 128;
            int sw = kr & 7;
            u32 kh0[4], kh1[4], kl0[4], kl1[4];
            ldm4(kh0, kb_ + (((0 + bchk) ^ sw) << 4));
            ldm4(kh1, kb_ + (((2 + bchk) ^ sw) << 4));
            ldm4(kl0, kb_ + (((4 + bchk) ^ sw) << 4));
            ldm4(kl1, kb_ + (((6 + bchk) ^ sw) << 4));
#pragma unroll
            for (int g = 0; g < 2; g++) {
                float d[4] = {0.f, 0.f, 0.f, 0.f};
                mma16816(d, qa[0], &kh0[2 * g]);
                mma16816(d, qa[1], &kh1[2 * g]);
                mma16816(d, qa[0], &kl0[2 * g]);
                mma16816(d, qa[1], &kl1[2 * g]);
                mma16816(d, qa[2], &kh0[2 * g]);
                mma16816(d, qa[3], &kh1[2 * g]);
                float p0 = ex2f(fmaf(d[0], LOG2E, -8.0f));
                float p1 = ex2f(fmaf(d[1], LOG2E, -8.0f));
                float p2 = ex2f(fmaf(d[2], LOG2E, -8.0f));
                float p3 = ex2f(fmaf(d[3], LOG2E, -8.0f));
                lsum0 += p0 + p1;
                lsum1 += p2 + p3;
                __half2 hh01 = __floats2half2_rn(p0, p1);
                __half2 hh23 = __floats2half2_rn(p2, p3);
                float2 hf01 = __half22float2(hh01);
                float2 hf23 = __half22float2(hh23);
                __half2 ll01 = __floats2half2_rn(p0 - hf01.x, p1 - hf01.y);
                __half2 ll23 = __floats2half2_rn(p2 - hf23.x, p3 - hf23.y);
                pah[mt][2 * g] = *(u32*)&hh01; pah[mt][2 * g + 1] = *(u32*)&hh23;
                pal[mt][2 * g] = *(u32*)&ll01; pal[mt][2 * g + 1] = *(u32*)&ll23;
            }
        }

#pragma unroll
        for (int cb = 0; cb < 16; cb++) {
            int vr = cb * 16 + brow;
            u32 vh_ = vbuf + vr * 128;
            int sw = vr & 7;
#pragma unroll
            for (int t = 0; t < 4; t++) {
                u32 vh[4];
                ldm4(vh, vh_ + (((2 * t + bchk) ^ sw) << 4));
                mma16816(oacc[2 * cb],     pah[t], &vh[0]);
                mma16816(oacc[2 * cb + 1], pah[t], &vh[2]);
                mma16816(oacc[2 * cb],     pal[t], &vh[0]);
                mma16816(oacc[2 * cb + 1], pal[t], &vh[2]);
            }
        }
        __syncthreads();
        if (kt + 2 < NKT) load_kv(su, Kb, Vhb, kt + 2, tid);
        CP_COMMIT();
    }

    lsum0 += __shfl_xor_sync(0xffffffffu, lsum0, 1);
    lsum0 += __shfl_xor_sync(0xffffffffu, lsum0, 2);
    lsum1 += __shfl_xor_sync(0xffffffffu, lsum1, 1);
    lsum1 += __shfl_xor_sync(0xffffffffu, lsum1, 2);
    float inv0 = 1.0f / lsum0, inv1 = 1.0f / lsum1;
    float* og = Og + (size_t)b * CH * NQ;
    int q = q0 + warp * 16 + (lane >> 2);
#pragma unroll
    for (int ng = 0; ng < 32; ng++) {
        int c = ng * 8 + (lane & 3) * 2;
        og[(size_t)c * NQ + q]           = oacc[ng][0] * inv0;
        og[(size_t)(c + 1) * NQ + q]     = oacc[ng][1] * inv0;
        og[(size_t)c * NQ + q + 8]       = oacc[ng][2] * inv1;
        og[(size_t)(c + 1) * NQ + q + 8] = oacc[ng][3] * inv1;
    }
}

// ---------------- launch ----------------
extern "C" void kernel_launch(void* const* d_in, const int* in_sizes, int n_in,
                              void* d_out, int out_size) {
    const float* f1 = (const float*)d_in[0];
    const float* f2 = (const float*)d_in[1];
    const float* f3 = (const float*)d_in[2];
    const float* wq = (const float*)d_in[3];
    const float* bq = (const float*)d_in[4];
    const float* wk = (const float*)d_in[5];
    const float* bk = (const float*)d_in[6];
    const float* wv = (const float*)d_in[7];
    const float* bv = (const float*)d_in[8];
    float* out = (float*)d_out;

    __half *qp, *kp, *vhp, *whl;
    cudaGetSymbolAddress((void**)&qp, g_Qhl);
    cudaGetSymbolAddress((void**)&kp, g_Khl);
    cudaGetSymbolAddress((void**)&vhp, g_VTh);
    cudaGetSymbolAddress((void**)&whl, g_Whl);

    prep_w<<<320, 256>>>(wq, wk, wv, whl);

    cudaFuncSetAttribute(conv_qk_mma, cudaFuncAttributeMaxDynamicSharedMemorySize, QK_SMEM);
    cudaFuncSetAttribute(conv_v_mma, cudaFuncAttributeMaxDynamicSharedMemorySize, CV_SMEM);

    dim3 gqk(NQ / 256, 1, BATCH);
    conv_qk_mma<<<gqk, 256, QK_SMEM>>>(f1, whl, whl + 8192, bq, qp);
    conv_qk_mma<<<gqk, 256, QK_SMEM>>>(f2, whl + 16384, whl + 24576, bk, kp);
    dim3 gv(NQ / 256, CH / 64, BATCH);
    conv_v_mma<<<gv, 256, CV_SMEM>>>(f3, whl + 32768, whl + 98304, bv, vhp);

    cudaFuncSetAttribute(attn_kernel, cudaFuncAttributeMaxDynamicSharedMemorySize,
                         ATTN_SMEM);
    dim3 ga(NQ / 128, BATCH);
    attn_kernel<<<ga, 256, ATTN_SMEM>>>(qp, kp, vhp, out);
}

// round 12
// speedup vs baseline: 22.6560x; 1.4226x over previous
#include <cuda_runtime.h>
#include <cuda_bf16.h>
#include <cuda_fp16.h>

#define BATCH 8
#define CH    256
#define CQK   32
#define NQ    4096
#define LOG2E 1.4426950408889634f

typedef unsigned long long ull;
typedef unsigned int u32;

// ---------------- scratch ----------------
__device__ __half g_Qhl[BATCH * NQ * 64];   // [b][n][32 hi | 32 lo] fp16
__device__ __half g_Khl[BATCH * NQ * 64];   // [b][m][32 hi | 32 lo] fp16
__device__ __half g_VTh[BATCH * CH * NQ];   // [b][c][m] fp16
__device__ __half g_Whl[163840];            // wq h/l | wk h/l | wv h/l

// ---------------- helpers ----------------
__device__ __forceinline__ float ex2f(float x) {
    float r; asm("ex2.approx.f32 %0, %1;" : "=f"(r) : "f"(x)); return r;
}
__device__ __forceinline__ u32 smem_u32(const void* p) {
    u32 a; asm("{ .reg .u64 t; cvta.to.shared.u64 t, %1; cvt.u32.u64 %0, t; }" : "=r"(a) : "l"(p));
    return a;
}
__device__ __forceinline__ void cpa(u32 dst, const void* src) {
    asm volatile("cp.async.cg.shared.global [%0], [%1], 16;" :: "r"(dst), "l"(src));
}
#define CP_COMMIT() asm volatile("cp.async.commit_group;" ::: "memory")
template<int N> __device__ __forceinline__ void cp_wait() {
    asm volatile("cp.async.wait_group %0;" :: "n"(N) : "memory");
}
__device__ __forceinline__ void ldm4(u32* r, u32 addr) {
    asm volatile("ldmatrix.sync.aligned.m8n8.x4.shared.b16 {%0,%1,%2,%3}, [%4];"
                 : "=r"(r[0]), "=r"(r[1]), "=r"(r[2]), "=r"(r[3]) : "r"(addr));
}
__device__ __forceinline__ void ldm4t(u32* r, u32 addr) {
    asm volatile("ldmatrix.sync.aligned.m8n8.x4.trans.shared.b16 {%0,%1,%2,%3}, [%4];"
                 : "=r"(r[0]), "=r"(r[1]), "=r"(r[2]), "=r"(r[3]) : "r"(addr));
}
__device__ __forceinline__ void mma16816(float* d, const u32* a, const u32* b) {
    asm volatile(
        "mma.sync.aligned.m16n8k16.row.col.f32.f16.f16.f32 "
        "{%0,%1,%2,%3}, {%4,%5,%6,%7}, {%8,%9}, {%0,%1,%2,%3};"
        : "+f"(d[0]), "+f"(d[1]), "+f"(d[2]), "+f"(d[3])
        : "r"(a[0]), "r"(a[1]), "r"(a[2]), "r"(a[3]), "r"(b[0]), "r"(b[1]));
}

// ---------------- prep: W fp32 -> fp16 hi/lo ----------------
__global__ void prep_w(const float* __restrict__ wq, const float* __restrict__ wk,
                       const float* __restrict__ wv, __half* __restrict__ o) {
    int idx = blockIdx.x * 256 + threadIdx.x;
    float v; int hoff, loff, pos;
    if (idx < 8192)       { v = wq[idx];         hoff = 0;     loff = 8192;  pos = idx; }
    else if (idx < 16384) { v = wk[idx - 8192];  hoff = 16384; loff = 24576; pos = idx - 8192; }
    else if (idx < 81920) { v = wv[idx - 16384]; hoff = 32768; loff = 98304; pos = idx - 16384; }
    else return;
    __half h = __float2half_rn(v);
    o[hoff + pos] = h;
    o[loff + pos] = __float2half_rn(v - __half2float(h));
}

// F chunk convert: pre[8] float4 (32 c x 256 n) -> smem hi/lo [c][n] swizzled
__device__ __forceinline__ void f_store(char* smx, u32 fh_off, u32 fl_off,
                                        const float4* pre, int tid) {
#pragma unroll
    for (int i = 0; i < 8; i++) {
        int idx = i * 256 + tid, row = idx >> 6, n = (idx & 63) * 4;
        float4 f = pre[i];
        __half2 h0 = __floats2half2_rn(f.x, f.y);
        __half2 h1 = __floats2half2_rn(f.z, f.w);
        float2 g0 = __half22float2(h0), g1 = __half22float2(h1);
        __half2 l0 = __floats2half2_rn(f.x - g0.x, f.y - g0.y);
        __half2 l1 = __floats2half2_rn(f.z - g1.x, f.w - g1.y);
        u32 off = row * 512 + (((n >> 3) ^ (row & 7)) << 4) + (n & 7) * 2;
        *(uint2*)(smx + fh_off + off) = make_uint2(*(u32*)&h0, *(u32*)&h1);
        *(uint2*)(smx + fl_off + off) = make_uint2(*(u32*)&l0, *(u32*)&l1);
    }
}

// ---------------- conv Q/K via HMMA: out [n][32hi|32lo] ----------------
#define QK_SMEM 69632
__global__ void __launch_bounds__(256, 1)
conv_qk_mma(const float* __restrict__ F, const __half* __restrict__ Wh,
            const __half* __restrict__ Wl, const float* __restrict__ bias,
            __half* __restrict__ out) {
    extern __shared__ char smx[];
    const u32 su = smem_u32(smx);
    const int tid = threadIdx.x, warp = tid >> 5, lane = tid & 31;
    const int n0 = blockIdx.x * 256, b = blockIdx.z;
    const float* Fb = F + (size_t)b * CH * NQ;

    for (int i = tid; i < 2048; i += 256) {
        int arr = i >> 10, rem = i & 1023, row = rem >> 5, cch = rem & 31;
        const __half* src = (arr ? Wl : Wh) + row * 256 + cch * 8;
        *(uint4*)(smx + arr * 16384 + row * 512 + ((cch ^ (row & 7)) << 4)) =
            *(const uint4*)src;
    }

    float4 pre[8];
#pragma unroll
    for (int i = 0; i < 8; i++) {
        int idx = i * 256 + tid, row = idx >> 6, n = (idx & 63) * 4;
        pre[i] = *(const float4*)&Fb[(size_t)row * NQ + n0 + n];
    }

    float oacc[8][4];
#pragma unroll
    for (int i = 0; i < 8; i++)
#pragma unroll
        for (int j = 0; j < 4; j++) oacc[i][j] = 0.f;

    const int arow = (lane & 7) | (((lane >> 3) & 1) << 3);
    const int achk = lane >> 4;
    const int krow = (lane & 7) + ((lane >> 3) & 1) * 8;
    const int nsel = lane >> 4;
    const int ow = warp >> 2, nw = warp & 3;

    for (int ck = 0; ck < 8; ck++) {
        __syncthreads();
        f_store(smx, 32768, 49152, pre, tid);
        if (ck < 7) {
#pragma unroll
            for (int i = 0; i < 8; i++) {
                int idx = i * 256 + tid, row = idx >> 6, n = (idx & 63) * 4;
                pre[i] = *(const float4*)&Fb[(size_t)((ck + 1) * 32 + row) * NQ + n0 + n];
            }
        }
        __syncthreads();
#pragma unroll
        for (int kk = 0; kk < 2; kk++) {
            int orow = ow * 16 + arow;
            int cchunk = ck * 4 + kk * 2 + achk;
            u32 aaddr = su + orow * 512 + ((cchunk ^ (orow & 7)) << 4);
            u32 ah[4], al[4];
            ldm4(ah, aaddr);
            ldm4(al, aaddr + 16384);
            int crow = kk * 16 + krow;
#pragma unroll
            for (int ns = 0; ns < 4; ns++) {
                int nch = (nw * 64 + ns * 16 + nsel * 8) >> 3;
                u32 baddr = su + 32768 + crow * 512 + ((nch ^ (crow & 7)) << 4);
                u32 bh[4], bl[4];
                ldm4t(bh, baddr);
                ldm4t(bl, baddr + 16384);
#pragma unroll
                for (int g = 0; g < 2; g++) {
                    float* d = oacc[ns * 2 + g];
                    mma16816(d, ah, &bh[2 * g]);
                    mma16816(d, ah, &bl[2 * g]);
                    mma16816(d, al, &bh[2 * g]);
                }
            }
        }
    }

    // epilogue: bias + hi/lo split -> staging [n 256][72 halves] at byte 32768
    __syncthreads();
    const int or0 = ow * 16 + (lane >> 2);
    const float b0 = bias[or0], b1 = bias[or0 + 8];
    __half* stg = (__half*)(smx + 32768);
#pragma unroll
    for (int j = 0; j < 8; j++) {
        int n = nw * 64 + j * 8 + (lane & 3) * 2;
#pragma unroll
        for (int e = 0; e < 2; e++) {
            float v0 = oacc[j][e] + b0;
            float v1 = oacc[j][2 + e] + b1;
            __half h0 = __float2half_rn(v0);
            __half h1 = __float2half_rn(v1);
            stg[(n + e) * 72 + or0] = h0;
            stg[(n + e) * 72 + 32 + or0] = __float2half_rn(v0 - __half2float(h0));
            stg[(n + e) * 72 + or0 + 8] = h1;
            stg[(n + e) * 72 + 32 + or0 + 8] = __float2half_rn(v1 - __half2float(h1));
        }
    }
    __syncthreads();
    for (int i = tid; i < 2048; i += 256) {
        int n = i >> 3, u4 = i & 7;
        *(uint4*)&out[((size_t)b * NQ + n0 + n) * 64 + u4 * 8] =
            *(uint4*)(stg + n * 72 + u4 * 8);
    }
}

// ---------------- conv V via HMMA: out [c][m] fp16 ----------------
#define CV_SMEM 98304
__global__ void __launch_bounds__(256, 1)
conv_v_mma(const float* __restrict__ F, const __half* __restrict__ Wh,
           const __half* __restrict__ Wl, const float* __restrict__ bias,
           __half* __restrict__ out) {
    extern __shared__ char smx[];
    const u32 su = smem_u32(smx);
    const int tid = threadIdx.x, warp = tid >> 5, lane = tid & 31;
    const int n0 = blockIdx.x * 256, o0 = blockIdx.y * 64, b = blockIdx.z;
    const float* Fb = F + (size_t)b * CH * NQ;

    for (int i = tid; i < 4096; i += 256) {
        int arr = i >> 11, rem = i & 2047, row = rem >> 5, cch = rem & 31;
        const __half* src = (arr ? Wl : Wh) + (size_t)(o0 + row) * 256 + cch * 8;
        *(uint4*)(smx + arr * 32768 + row * 512 + ((cch ^ (row & 7)) << 4)) =
            *(const uint4*)src;
    }

    float4 pre[8];
#pragma unroll
    for (int i = 0; i < 8; i++) {
        int idx = i * 256 + tid, row = idx >> 6, n = (idx & 63) * 4;
        pre[i] = *(const float4*)&Fb[(size_t)row * NQ + n0 + n];
    }

    float oacc[16][4];
#pragma unroll
    for (int i = 0; i < 16; i++)
#pragma unroll
        for (int j = 0; j < 4; j++) oacc[i][j] = 0.f;

    const int arow = (lane & 7) | (((lane >> 3) & 1) << 3);
    const int achk = lane >> 4;
    const int krow = (lane & 7) + ((lane >> 3) & 1) * 8;
    const int nsel = lane >> 4;
    const int ob = warp >> 1, nw = warp & 1;

    for (int ck = 0; ck < 8; ck++) {
        __syncthreads();
        f_store(smx, 65536, 81920, pre, tid);
        if (ck < 7) {
#pragma unroll
            for (int i = 0; i < 8; i++) {
                int idx = i * 256 + tid, row = idx >> 6, n = (idx & 63) * 4;
                pre[i] = *(const float4*)&Fb[(size_t)((ck + 1) * 32 + row) * NQ + n0 + n];
            }
        }
        __syncthreads();
#pragma unroll
        for (int kk = 0; kk < 2; kk++) {
            int orow = ob * 16 + arow;
            int cchunk = ck * 4 + kk * 2 + achk;
            u32 aaddr = su + orow * 512 + ((cchunk ^ (orow & 7)) << 4);
            u32 ah[4], al[4];
            ldm4(ah, aaddr);
            ldm4(al, aaddr + 32768);
            int crow = kk * 16 + krow;
#pragma unroll
            for (int ns = 0; ns < 8; ns++) {
                int nch = (nw * 128 + ns * 16 + nsel * 8) >> 3;
                u32 baddr = su + 65536 + crow * 512 + ((nch ^ (crow & 7)) << 4);
                u32 bh[4], bl[4];
                ldm4t(bh, baddr);
                ldm4t(bl, baddr + 16384);
#pragma unroll
                for (int g = 0; g < 2; g++) {
                    float* d = oacc[ns * 2 + g];
                    mma16816(d, ah, &bh[2 * g]);
                    mma16816(d, ah, &bl[2 * g]);
                    mma16816(d, al, &bh[2 * g]);
                }
            }
        }
    }

    // epilogue -> staging [o 64][272 halves] at byte 0 (reuse W region)
    __syncthreads();
    const int or0 = ob * 16 + (lane >> 2);
    const float b0 = bias[o0 + or0], b1 = bias[o0 + or0 + 8];
    __half* stg = (__half*)smx;
#pragma unroll
    for (int j = 0; j < 16; j++) {
        int n = nw * 128 + j * 8 + (lane & 3) * 2;
        __half2 h0 = __floats2half2_rn(oacc[j][0] + b0, oacc[j][1] + b0);
        __half2 h1 = __floats2half2_rn(oacc[j][2] + b1, oacc[j][3] + b1);
        *(__half2*)&stg[or0 * 272 + n] = h0;
        *(__half2*)&stg[(or0 + 8) * 272 + n] = h1;
    }
    __syncthreads();
    for (int i = tid; i < 2048; i += 256) {
        int row = i >> 5, c4 = i & 31;
        *(uint4*)&out[((size_t)b * CH + o0 + row) * NQ + n0 + c4 * 8] =
            *(uint4*)(stg + row * 272 + c4 * 8);
    }
}

// ---------------- mma.sync flash attention (fp16, P hi-only PV) ----------------
#define QS_OFF 0
#define KS_OFF 16384
#define VS_OFF 32768
#define NKT    (NQ / 64)
#define ATTN_SMEM 98304

__device__ __forceinline__ void load_kv(u32 su, const __half* Kb,
                                        const __half* Vhb, int kt, int tid) {
    int bf = kt & 1;
    for (int i = tid; i < 512; i += 256) {
        int m = i >> 3, j = i & 7;
        cpa(su + KS_OFF + bf * 8192 + m * 128 + ((j ^ (m & 7)) << 4),
            Kb + ((size_t)(kt * 64 + m)) * 64 + j * 8);
    }
    for (int i = tid; i < 2048; i += 256) {
        int c = i >> 3, j = i & 7;
        cpa(su + VS_OFF + bf * 32768 + c * 128 + ((j ^ (c & 7)) << 4),
            Vhb + (size_t)c * NQ + kt * 64 + j * 8);
    }
}

__global__ void __launch_bounds__(256, 1)
attn_kernel(const __half* __restrict__ Qg, const __half* __restrict__ Kg,
            const __half* __restrict__ Vhg, float* __restrict__ Og) {
    extern __shared__ char smx[];
    const u32 su = smem_u32(smx);
    const int tid = threadIdx.x, warp = tid >> 5, lane = tid & 31;
    const int b = blockIdx.y, q0 = blockIdx.x * 128;

    const __half* Qb  = Qg  + ((size_t)b * NQ + q0) * 64;
    const __half* Kb  = Kg  + (size_t)b * NQ * 64;
    const __half* Vhb = Vhg + (size_t)b * CH * NQ;

    for (int i = tid; i < 1024; i += 256) {
        int q = i >> 3, j = i & 7;
        cpa(su + QS_OFF + q * 128 + ((j ^ (q & 7)) << 4), Qb + (size_t)q * 64 + j * 8);
    }
    load_kv(su, Kb, Vhb, 0, tid);
    CP_COMMIT();
    load_kv(su, Kb, Vhb, 1, tid);
    CP_COMMIT();

    float oacc[32][4];
#pragma unroll
    for (int i = 0; i < 32; i++)
#pragma unroll
        for (int j = 0; j < 4; j++) oacc[i][j] = 0.f;
    float lsum0 = 0.f, lsum1 = 0.f;
    u32 qa[4][4];

    const int arow = (lane & 7) | (((lane >> 3) & 1) << 3);
    const int achk = lane >> 4;
    const int brow = (lane & 7) | ((lane >> 4) << 3);
    const int bchk = (lane >> 3) & 1;

    for (int kt = 0; kt < NKT; kt++) {
        cp_wait<1>();
        __syncthreads();
        if (kt == 0) {
            int qr = warp * 16 + arow;
            u32 qb_ = su + QS_OFF + qr * 128;
#pragma unroll
            for (int t = 0; t < 4; t++)
                ldm4(qa[t], qb_ + (((2 * t + achk) ^ (qr & 7)) << 4));
        }
        u32 kbuf = su + KS_OFF + (kt & 1) * 8192;
        u32 vbuf = su + VS_OFF + (kt & 1) * 32768;

        // ---- S = QK^T (3-term fp16) + exp(S - 8ln2) -> P hi frags only ----
        u32 pah[4][4];
#pragma unroll
        for (int mt = 0; mt < 4; mt++) {
            int kr = mt * 16 + brow;
            u32 kb_ = kbuf + kr * 128;
            int sw = kr & 7;
            u32 kh0[4], kh1[4], kl0[4], kl1[4];
            ldm4(kh0, kb_ + (((0 + bchk) ^ sw) << 4));
            ldm4(kh1, kb_ + (((2 + bchk) ^ sw) << 4));
            ldm4(kl0, kb_ + (((4 + bchk) ^ sw) << 4));
            ldm4(kl1, kb_ + (((6 + bchk) ^ sw) << 4));
#pragma unroll
            for (int g = 0; g < 2; g++) {
                float d[4] = {0.f, 0.f, 0.f, 0.f};
                mma16816(d, qa[0], &kh0[2 * g]);
                mma16816(d, qa[1], &kh1[2 * g]);
                mma16816(d, qa[0], &kl0[2 * g]);   // Qh * Klo
                mma16816(d, qa[1], &kl1[2 * g]);
                mma16816(d, qa[2], &kh0[2 * g]);   // Qlo * Kh
                mma16816(d, qa[3], &kh1[2 * g]);
                float p0 = ex2f(fmaf(d[0], LOG2E, -8.0f));
                float p1 = ex2f(fmaf(d[1], LOG2E, -8.0f));
                float p2 = ex2f(fmaf(d[2], LOG2E, -8.0f));
                float p3 = ex2f(fmaf(d[3], LOG2E, -8.0f));
                lsum0 += p0 + p1;
                lsum1 += p2 + p3;
                __half2 hh01 = __floats2half2_rn(p0, p1);
                __half2 hh23 = __floats2half2_rn(p2, p3);
                pah[mt][2 * g] = *(u32*)&hh01;
                pah[mt][2 * g + 1] = *(u32*)&hh23;
            }
        }

        // ---- O += P V (P hi only) ----
#pragma unroll
        for (int cb = 0; cb < 16; cb++) {
            int vr = cb * 16 + brow;
            u32 vh_ = vbuf + vr * 128;
            int sw = vr & 7;
#pragma unroll
            for (int t = 0; t < 4; t++) {
                u32 vh[4];
                ldm4(vh, vh_ + (((2 * t + bchk) ^ sw) << 4));
                mma16816(oacc[2 * cb],     pah[t], &vh[0]);
                mma16816(oacc[2 * cb + 1], pah[t], &vh[2]);
            }
        }
        __syncthreads();
        if (kt + 2 < NKT) load_kv(su, Kb, Vhb, kt + 2, tid);
        CP_COMMIT();
    }

    lsum0 += __shfl_xor_sync(0xffffffffu, lsum0, 1);
    lsum0 += __shfl_xor_sync(0xffffffffu, lsum0, 2);
    lsum1 += __shfl_xor_sync(0xffffffffu, lsum1, 1);
    lsum1 += __shfl_xor_sync(0xffffffffu, lsum1, 2);
    float inv0 = 1.0f / lsum0, inv1 = 1.0f / lsum1;
    float* og = Og + (size_t)b * CH * NQ;
    int q = q0 + warp * 16 + (lane >> 2);
#pragma unroll
    for (int ng = 0; ng < 32; ng++) {
        int c = ng * 8 + (lane & 3) * 2;
        og[(size_t)c * NQ + q]           = oacc[ng][0] * inv0;
        og[(size_t)(c + 1) * NQ + q]     = oacc[ng][1] * inv0;
        og[(size_t)c * NQ + q + 8]       = oacc[ng][2] * inv1;
        og[(size_t)(c + 1) * NQ + q + 8] = oacc[ng][3] * inv1;
    }
}

// ---------------- launch ----------------
extern "C" void kernel_launch(void* const* d_in, const int* in_sizes, int n_in,
                              void* d_out, int out_size) {
    const float* f1 = (const float*)d_in[0];
    const float* f2 = (const float*)d_in[1];
    const float* f3 = (const float*)d_in[2];
    const float* wq = (const float*)d_in[3];
    const float* bq = (const float*)d_in[4];
    const float* wk = (const float*)d_in[5];
    const float* bk = (const float*)d_in[6];
    const float* wv = (const float*)d_in[7];
    const float* bv = (const float*)d_in[8];
    float* out = (float*)d_out;

    __half *qp, *kp, *vhp, *whl;
    cudaGetSymbolAddress((void**)&qp, g_Qhl);
    cudaGetSymbolAddress((void**)&kp, g_Khl);
    cudaGetSymbolAddress((void**)&vhp, g_VTh);
    cudaGetSymbolAddress((void**)&whl, g_Whl);

    prep_w<<<320, 256>>>(wq, wk, wv, whl);

    cudaFuncSetAttribute(conv_qk_mma, cudaFuncAttributeMaxDynamicSharedMemorySize, QK_SMEM);
    cudaFuncSetAttribute(conv_v_mma, cudaFuncAttributeMaxDynamicSharedMemorySize, CV_SMEM);

    dim3 gqk(NQ / 256, 1, BATCH);
    conv_qk_mma<<<gqk, 256, QK_SMEM>>>(f1, whl, whl + 8192, bq, qp);
    conv_qk_mma<<<gqk, 256, QK_SMEM>>>(f2, whl + 16384, whl + 24576, bk, kp);
    dim3 gv(NQ / 256, CH / 64, BATCH);
    conv_v_mma<<<gv, 256, CV_SMEM>>>(f3, whl + 32768, whl + 98304, bv, vhp);

    cudaFuncSetAttribute(attn_kernel, cudaFuncAttributeMaxDynamicSharedMemorySize,
                         ATTN_SMEM);
    dim3 ga(NQ / 128, BATCH);
    attn_kernel<<<ga, 256, ATTN_SMEM>>>(qp, kp, vhp, out);
}

// round 13
// speedup vs baseline: 23.3864x; 1.0322x over previous
#include <cuda_runtime.h>
#include <cuda_bf16.h>
#include <cuda_fp16.h>

#define BATCH 8
#define CH    256
#define CQK   32
#define NQ    4096
#define LOG2E 1.4426950408889634f

typedef unsigned long long ull;
typedef unsigned int u32;

// ---------------- scratch ----------------
__device__ __half g_Qhl[BATCH * NQ * 64];   // [b][n][32 hi | 32 lo] fp16
__device__ __half g_Khl[BATCH * NQ * 64];   // [b][m][32 hi | 32 lo] fp16
__device__ __half g_VTh[BATCH * CH * NQ];   // [b][c][m] fp16
__device__ __half g_Whl[163840];            // wq h/l | wk h/l | wv h/l

// ---------------- helpers ----------------
__device__ __forceinline__ float ex2f(float x) {
    float r; asm("ex2.approx.f32 %0, %1;" : "=f"(r) : "f"(x)); return r;
}
__device__ __forceinline__ u32 smem_u32(const void* p) {
    u32 a; asm("{ .reg .u64 t; cvta.to.shared.u64 t, %1; cvt.u32.u64 %0, t; }" : "=r"(a) : "l"(p));
    return a;
}
__device__ __forceinline__ void cpa(u32 dst, const void* src) {
    asm volatile("cp.async.cg.shared.global [%0], [%1], 16;" :: "r"(dst), "l"(src));
}
#define CP_COMMIT() asm volatile("cp.async.commit_group;" ::: "memory")
template<int N> __device__ __forceinline__ void cp_wait() {
    asm volatile("cp.async.wait_group %0;" :: "n"(N) : "memory");
}
__device__ __forceinline__ void ldm4(u32* r, u32 addr) {
    asm volatile("ldmatrix.sync.aligned.m8n8.x4.shared.b16 {%0,%1,%2,%3}, [%4];"
                 : "=r"(r[0]), "=r"(r[1]), "=r"(r[2]), "=r"(r[3]) : "r"(addr));
}
__device__ __forceinline__ void ldm4t(u32* r, u32 addr) {
    asm volatile("ldmatrix.sync.aligned.m8n8.x4.trans.shared.b16 {%0,%1,%2,%3}, [%4];"
                 : "=r"(r[0]), "=r"(r[1]), "=r"(r[2]), "=r"(r[3]) : "r"(addr));
}
__device__ __forceinline__ void mma16816(float* d, const u32* a, const u32* b) {
    asm volatile(
        "mma.sync.aligned.m16n8k16.row.col.f32.f16.f16.f32 "
        "{%0,%1,%2,%3}, {%4,%5,%6,%7}, {%8,%9}, {%0,%1,%2,%3};"
        : "+f"(d[0]), "+f"(d[1]), "+f"(d[2]), "+f"(d[3])
        : "r"(a[0]), "r"(a[1]), "r"(a[2]), "r"(a[3]), "r"(b[0]), "r"(b[1]));
}

// ---------------- prep: W fp32 -> fp16 hi/lo ----------------
__global__ void prep_w(const float* __restrict__ wq, const float* __restrict__ wk,
                       const float* __restrict__ wv, __half* __restrict__ o) {
    int idx = blockIdx.x * 256 + threadIdx.x;
    float v; int hoff, loff, pos;
    if (idx < 8192)       { v = wq[idx];         hoff = 0;     loff = 8192;  pos = idx; }
    else if (idx < 16384) { v = wk[idx - 8192];  hoff = 16384; loff = 24576; pos = idx - 8192; }
    else if (idx < 81920) { v = wv[idx - 16384]; hoff = 32768; loff = 98304; pos = idx - 16384; }
    else return;
    __half h = __float2half_rn(v);
    o[hoff + pos] = h;
    o[loff + pos] = __float2half_rn(v - __half2float(h));
}

// F chunk convert: pre[8] float4 (32 c x 256 n) -> smem hi/lo [c][n] swizzled
__device__ __forceinline__ void f_store(char* smx, u32 fh_off, u32 fl_off,
                                        const float4* pre, int tid) {
#pragma unroll
    for (int i = 0; i < 8; i++) {
        int idx = i * 256 + tid, row = idx >> 6, n = (idx & 63) * 4;
        float4 f = pre[i];
        __half2 h0 = __floats2half2_rn(f.x, f.y);
        __half2 h1 = __floats2half2_rn(f.z, f.w);
        float2 g0 = __half22float2(h0), g1 = __half22float2(h1);
        __half2 l0 = __floats2half2_rn(f.x - g0.x, f.y - g0.y);
        __half2 l1 = __floats2half2_rn(f.z - g1.x, f.w - g1.y);
        u32 off = row * 512 + (((n >> 3) ^ (row & 7)) << 4) + (n & 7) * 2;
        *(uint2*)(smx + fh_off + off) = make_uint2(*(u32*)&h0, *(u32*)&h1);
        *(uint2*)(smx + fl_off + off) = make_uint2(*(u32*)&l0, *(u32*)&l1);
    }
}

// ---------------- conv Q/K via HMMA: out [n][32hi|32lo] ----------------
#define QK_SMEM 69632
__global__ void __launch_bounds__(256, 1)
conv_qk_mma(const float* __restrict__ F, const __half* __restrict__ Wh,
            const __half* __restrict__ Wl, const float* __restrict__ bias,
            __half* __restrict__ out) {
    extern __shared__ char smx[];
    const u32 su = smem_u32(smx);
    const int tid = threadIdx.x, warp = tid >> 5, lane = tid & 31;
    const int n0 = blockIdx.x * 256, b = blockIdx.z;
    const float* Fb = F + (size_t)b * CH * NQ;

    for (int i = tid; i < 2048; i += 256) {
        int arr = i >> 10, rem = i & 1023, row = rem >> 5, cch = rem & 31;
        const __half* src = (arr ? Wl : Wh) + row * 256 + cch * 8;
        *(uint4*)(smx + arr * 16384 + row * 512 + ((cch ^ (row & 7)) << 4)) =
            *(const uint4*)src;
    }

    float4 pre[8];
#pragma unroll
    for (int i = 0; i < 8; i++) {
        int idx = i * 256 + tid, row = idx >> 6, n = (idx & 63) * 4;
        pre[i] = *(const float4*)&Fb[(size_t)row * NQ + n0 + n];
    }

    float oacc[8][4];
#pragma unroll
    for (int i = 0; i < 8; i++)
#pragma unroll
        for (int j = 0; j < 4; j++) oacc[i][j] = 0.f;

    const int arow = (lane & 7) | (((lane >> 3) & 1) << 3);
    const int achk = lane >> 4;
    const int krow = (lane & 7) + ((lane >> 3) & 1) * 8;
    const int nsel = lane >> 4;
    const int ow = warp >> 2, nw = warp & 3;

    for (int ck = 0; ck < 8; ck++) {
        __syncthreads();
        f_store(smx, 32768, 49152, pre, tid);
        if (ck < 7) {
#pragma unroll
            for (int i = 0; i < 8; i++) {
                int idx = i * 256 + tid, row = idx >> 6, n = (idx & 63) * 4;
                pre[i] = *(const float4*)&Fb[(size_t)((ck + 1) * 32 + row) * NQ + n0 + n];
            }
        }
        __syncthreads();
#pragma unroll
        for (int kk = 0; kk < 2; kk++) {
            int orow = ow * 16 + arow;
            int cchunk = ck * 4 + kk * 2 + achk;
            u32 aaddr = su + orow * 512 + ((cchunk ^ (orow & 7)) << 4);
            u32 ah[4], al[4];
            ldm4(ah, aaddr);
            ldm4(al, aaddr + 16384);
            int crow = kk * 16 + krow;
#pragma unroll
            for (int ns = 0; ns < 4; ns++) {
                int nch = (nw * 64 + ns * 16 + nsel * 8) >> 3;
                u32 baddr = su + 32768 + crow * 512 + ((nch ^ (crow & 7)) << 4);
                u32 bh[4], bl[4];
                ldm4t(bh, baddr);
                ldm4t(bl, baddr + 16384);
#pragma unroll
                for (int g = 0; g < 2; g++) {
                    float* d = oacc[ns * 2 + g];
                    mma16816(d, ah, &bh[2 * g]);
                    mma16816(d, ah, &bl[2 * g]);
                    mma16816(d, al, &bh[2 * g]);
                }
            }
        }
    }

    // epilogue: bias + hi/lo split -> staging [n 256][72 halves] at byte 32768
    __syncthreads();
    const int or0 = ow * 16 + (lane >> 2);
    const float b0 = bias[or0], b1 = bias[or0 + 8];
    __half* stg = (__half*)(smx + 32768);
#pragma unroll
    for (int j = 0; j < 8; j++) {
        int n = nw * 64 + j * 8 + (lane & 3) * 2;
#pragma unroll
        for (int e = 0; e < 2; e++) {
            float v0 = oacc[j][e] + b0;
            float v1 = oacc[j][2 + e] + b1;
            __half h0 = __float2half_rn(v0);
            __half h1 = __float2half_rn(v1);
            stg[(n + e) * 72 + or0] = h0;
            stg[(n + e) * 72 + 32 + or0] = __float2half_rn(v0 - __half2float(h0));
            stg[(n + e) * 72 + or0 + 8] = h1;
            stg[(n + e) * 72 + 32 + or0 + 8] = __float2half_rn(v1 - __half2float(h1));
        }
    }
    __syncthreads();
    for (int i = tid; i < 2048; i += 256) {
        int n = i >> 3, u4 = i & 7;
        *(uint4*)&out[((size_t)b * NQ + n0 + n) * 64 + u4 * 8] =
            *(uint4*)(stg + n * 72 + u4 * 8);
    }
}

// ---------------- conv V via HMMA (2-term, W hi only): out [c][m] fp16 ----------------
#define CV_SMEM 98304
__global__ void __launch_bounds__(256, 1)
conv_v_mma(const float* __restrict__ F, const __half* __restrict__ Wh,
           const __half* __restrict__ Wl, const float* __restrict__ bias,
           __half* __restrict__ out) {
    extern __shared__ char smx[];
    const u32 su = smem_u32(smx);
    const int tid = threadIdx.x, warp = tid >> 5, lane = tid & 31;
    const int n0 = blockIdx.x * 256, o0 = blockIdx.y * 64, b = blockIdx.z;
    const float* Fb = F + (size_t)b * CH * NQ;

    for (int i = tid; i < 2048; i += 256) {
        int row = i >> 5, cch = i & 31;
        const __half* src = Wh + (size_t)(o0 + row) * 256 + cch * 8;
        *(uint4*)(smx + row * 512 + ((cch ^ (row & 7)) << 4)) = *(const uint4*)src;
    }

    float4 pre[8];
#pragma unroll
    for (int i = 0; i < 8; i++) {
        int idx = i * 256 + tid, row = idx >> 6, n = (idx & 63) * 4;
        pre[i] = *(const float4*)&Fb[(size_t)row * NQ + n0 + n];
    }

    float oacc[16][4];
#pragma unroll
    for (int i = 0; i < 16; i++)
#pragma unroll
        for (int j = 0; j < 4; j++) oacc[i][j] = 0.f;

    const int arow = (lane & 7) | (((lane >> 3) & 1) << 3);
    const int achk = lane >> 4;
    const int krow = (lane & 7) + ((lane >> 3) & 1) * 8;
    const int nsel = lane >> 4;
    const int ob = warp >> 1, nw = warp & 1;

    for (int ck = 0; ck < 8; ck++) {
        __syncthreads();
        f_store(smx, 65536, 81920, pre, tid);
        if (ck < 7) {
#pragma unroll
            for (int i = 0; i < 8; i++) {
                int idx = i * 256 + tid, row = idx >> 6, n = (idx & 63) * 4;
                pre[i] = *(const float4*)&Fb[(size_t)((ck + 1) * 32 + row) * NQ + n0 + n];
            }
        }
        __syncthreads();
#pragma unroll
        for (int kk = 0; kk < 2; kk++) {
            int orow = ob * 16 + arow;
            int cchunk = ck * 4 + kk * 2 + achk;
            u32 aaddr = su + orow * 512 + ((cchunk ^ (orow & 7)) << 4);
            u32 ah[4];
            ldm4(ah, aaddr);
            int crow = kk * 16 + krow;
#pragma unroll
            for (int ns = 0; ns < 8; ns++) {
                int nch = (nw * 128 + ns * 16 + nsel * 8) >> 3;
                u32 baddr = su + 65536 + crow * 512 + ((nch ^ (crow & 7)) << 4);
                u32 bh[4], bl[4];
                ldm4t(bh, baddr);
                ldm4t(bl, baddr + 16384);
#pragma unroll
                for (int g = 0; g < 2; g++) {
                    float* d = oacc[ns * 2 + g];
                    mma16816(d, ah, &bh[2 * g]);
                    mma16816(d, ah, &bl[2 * g]);
                }
            }
        }
    }

    // epilogue -> staging [o 64][272 halves] at byte 0 (reuse W region)
    __syncthreads();
    const int or0 = ob * 16 + (lane >> 2);
    const float b0 = bias[o0 + or0], b1 = bias[o0 + or0 + 8];
    __half* stg = (__half*)smx;
#pragma unroll
    for (int j = 0; j < 16; j++) {
        int n = nw * 128 + j * 8 + (lane & 3) * 2;
        __half2 h0 = __floats2half2_rn(oacc[j][0] + b0, oacc[j][1] + b0);
        __half2 h1 = __floats2half2_rn(oacc[j][2] + b1, oacc[j][3] + b1);
        *(__half2*)&stg[or0 * 272 + n] = h0;
        *(__half2*)&stg[(or0 + 8) * 272 + n] = h1;
    }
    __syncthreads();
    for (int i = tid; i < 2048; i += 256) {
        int row = i >> 5, c4 = i & 31;
        *(uint4*)&out[((size_t)b * CH + o0 + row) * NQ + n0 + c4 * 8] =
            *(uint4*)(stg + row * 272 + c4 * 8);
    }
}

// ---------------- mma.sync flash attention (fp16, 64q CTA, occ 2) ----------------
#define QS_OFF 0
#define KS_OFF 8192
#define VS_OFF 24576
#define NKT    (NQ / 64)
#define ATTN_SMEM 90112
#define ATHR   128

__device__ __forceinline__ void load_kv(u32 su, const __half* Kb,
                                        const __half* Vhb, int kt, int tid) {
    int bf = kt & 1;
    for (int i = tid; i < 512; i += ATHR) {
        int m = i >> 3, j = i & 7;
        cpa(su + KS_OFF + bf * 8192 + m * 128 + ((j ^ (m & 7)) << 4),
            Kb + ((size_t)(kt * 64 + m)) * 64 + j * 8);
    }
    for (int i = tid; i < 2048; i += ATHR) {
        int c = i >> 3, j = i & 7;
        cpa(su + VS_OFF + bf * 32768 + c * 128 + ((j ^ (c & 7)) << 4),
            Vhb + (size_t)c * NQ + kt * 64 + j * 8);
    }
}

__global__ void __launch_bounds__(ATHR, 2)
attn_kernel(const __half* __restrict__ Qg, const __half* __restrict__ Kg,
            const __half* __restrict__ Vhg, float* __restrict__ Og) {
    extern __shared__ char smx[];
    const u32 su = smem_u32(smx);
    const int tid = threadIdx.x, warp = tid >> 5, lane = tid & 31;
    const int b = blockIdx.y, q0 = blockIdx.x * 64;

    const __half* Qb  = Qg  + ((size_t)b * NQ + q0) * 64;
    const __half* Kb  = Kg  + (size_t)b * NQ * 64;
    const __half* Vhb = Vhg + (size_t)b * CH * NQ;

    for (int i = tid; i < 512; i += ATHR) {
        int q = i >> 3, j = i & 7;
        cpa(su + QS_OFF + q * 128 + ((j ^ (q & 7)) << 4), Qb + (size_t)q * 64 + j * 8);
    }
    load_kv(su, Kb, Vhb, 0, tid);
    CP_COMMIT();
    load_kv(su, Kb, Vhb, 1, tid);
    CP_COMMIT();

    float oacc[32][4];
#pragma unroll
    for (int i = 0; i < 32; i++)
#pragma unroll
        for (int j = 0; j < 4; j++) oacc[i][j] = 0.f;
    float lsum0 = 0.f, lsum1 = 0.f;
    u32 qa[4][4];

    const int arow = (lane & 7) | (((lane >> 3) & 1) << 3);
    const int achk = lane >> 4;
    const int brow = (lane & 7) | ((lane >> 4) << 3);
    const int bchk = (lane >> 3) & 1;

    for (int kt = 0; kt < NKT; kt++) {
        cp_wait<1>();
        __syncthreads();
        if (kt == 0) {
            int qr = warp * 16 + arow;
            u32 qb_ = su + QS_OFF + qr * 128;
#pragma unroll
            for (int t = 0; t < 4; t++)
                ldm4(qa[t], qb_ + (((2 * t + achk) ^ (qr & 7)) << 4));
        }
        u32 kbuf = su + KS_OFF + (kt & 1) * 8192;
        u32 vbuf = su + VS_OFF + (kt & 1) * 32768;

        // ---- S = QK^T (3-term fp16) + exp(S - 8ln2) -> P hi frags only ----
        u32 pah[4][4];
#pragma unroll
        for (int mt = 0; mt < 4; mt++) {
            int kr = mt * 16 + brow;
            u32 kb_ = kbuf + kr * 128;
            int sw = kr & 7;
            u32 kh0[4], kh1[4], kl0[4], kl1[4];
            ldm4(kh0, kb_ + (((0 + bchk) ^ sw) << 4));
            ldm4(kh1, kb_ + (((2 + bchk) ^ sw) << 4));
            ldm4(kl0, kb_ + (((4 + bchk) ^ sw) << 4));
            ldm4(kl1, kb_ + (((6 + bchk) ^ sw) << 4));
#pragma unroll
            for (int g = 0; g < 2; g++) {
                float d[4] = {0.f, 0.f, 0.f, 0.f};
                mma16816(d, qa[0], &kh0[2 * g]);
                mma16816(d, qa[1], &kh1[2 * g]);
                mma16816(d, qa[0], &kl0[2 * g]);   // Qh * Klo
                mma16816(d, qa[1], &kl1[2 * g]);
                mma16816(d, qa[2], &kh0[2 * g]);   // Qlo * Kh
                mma16816(d, qa[3], &kh1[2 * g]);
                float p0 = ex2f(fmaf(d[0], LOG2E, -8.0f));
                float p1 = ex2f(fmaf(d[1], LOG2E, -8.0f));
                float p2 = ex2f(fmaf(d[2], LOG2E, -8.0f));
                float p3 = ex2f(fmaf(d[3], LOG2E, -8.0f));
                lsum0 += p0 + p1;
                lsum1 += p2 + p3;
                __half2 hh01 = __floats2half2_rn(p0, p1);
                __half2 hh23 = __floats2half2_rn(p2, p3);
                pah[mt][2 * g] = *(u32*)&hh01;
                pah[mt][2 * g + 1] = *(u32*)&hh23;
            }
        }

        // ---- O += P V (P hi only) ----
#pragma unroll
        for (int cb = 0; cb < 16; cb++) {
            int vr = cb * 16 + brow;
            u32 vh_ = vbuf + vr * 128;
            int sw = vr & 7;
#pragma unroll
            for (int t = 0; t < 4; t++) {
                u32 vh[4];
                ldm4(vh, vh_ + (((2 * t + bchk) ^ sw) << 4));
                mma16816(oacc[2 * cb],     pah[t], &vh[0]);
                mma16816(oacc[2 * cb + 1], pah[t], &vh[2]);
            }
        }
        __syncthreads();
        if (kt + 2 < NKT) load_kv(su, Kb, Vhb, kt + 2, tid);
        CP_COMMIT();
    }

    lsum0 += __shfl_xor_sync(0xffffffffu, lsum0, 1);
    lsum0 += __shfl_xor_sync(0xffffffffu, lsum0, 2);
    lsum1 += __shfl_xor_sync(0xffffffffu, lsum1, 1);
    lsum1 += __shfl_xor_sync(0xffffffffu, lsum1, 2);
    float inv0 = 1.0f / lsum0, inv1 = 1.0f / lsum1;
    float* og = Og + (size_t)b * CH * NQ;
    int q = q0 + warp * 16 + (lane >> 2);
#pragma unroll
    for (int ng = 0; ng < 32; ng++) {
        int c = ng * 8 + (lane & 3) * 2;
        og[(size_t)c * NQ + q]           = oacc[ng][0] * inv0;
        og[(size_t)(c + 1) * NQ + q]     = oacc[ng][1] * inv0;
        og[(size_t)c * NQ + q + 8]       = oacc[ng][2] * inv1;
        og[(size_t)(c + 1) * NQ + q + 8] = oacc[ng][3] * inv1;
    }
}

// ---------------- launch ----------------
extern "C" void kernel_launch(void* const* d_in, const int* in_sizes, int n_in,
                              void* d_out, int out_size) {
    const float* f1 = (const float*)d_in[0];
    const float* f2 = (const float*)d_in[1];
    const float* f3 = (const float*)d_in[2];
    const float* wq = (const float*)d_in[3];
    const float* bq = (const float*)d_in[4];
    const float* wk = (const float*)d_in[5];
    const float* bk = (const float*)d_in[6];
    const float* wv = (const float*)d_in[7];
    const float* bv = (const float*)d_in[8];
    float* out = (float*)d_out;

    __half *qp, *kp, *vhp, *whl;
    cudaGetSymbolAddress((void**)&qp, g_Qhl);
    cudaGetSymbolAddress((void**)&kp, g_Khl);
    cudaGetSymbolAddress((void**)&vhp, g_VTh);
    cudaGetSymbolAddress((void**)&whl, g_Whl);

    prep_w<<<320, 256>>>(wq, wk, wv, whl);

    cudaFuncSetAttribute(conv_qk_mma, cudaFuncAttributeMaxDynamicSharedMemorySize, QK_SMEM);
    cudaFuncSetAttribute(conv_v_mma, cudaFuncAttributeMaxDynamicSharedMemorySize, CV_SMEM);

    dim3 gqk(NQ / 256, 1, BATCH);
    conv_qk_mma<<<gqk, 256, QK_SMEM>>>(f1, whl, whl + 8192, bq, qp);
    conv_qk_mma<<<gqk, 256, QK_SMEM>>>(f2, whl + 16384, whl + 24576, bk, kp);
    dim3 gv(NQ / 256, CH / 64, BATCH);
    conv_v_mma<<<gv, 256, CV_SMEM>>>(f3, whl + 32768, whl + 98304, bv, vhp);

    cudaFuncSetAttribute(attn_kernel, cudaFuncAttributeMaxDynamicSharedMemorySize,
                         ATTN_SMEM);
    dim3 ga(NQ / 64, BATCH);
    attn_kernel<<<ga, ATHR, ATTN_SMEM>>>(qp, kp, vhp, out);
}

// round 14
// speedup vs baseline: 24.8978x; 1.0646x over previous
#include <cuda_runtime.h>
#include <cuda_bf16.h>
#include <cuda_fp16.h>

#define BATCH 8
#define CH    256
#define CQK   32
#define NQ    4096
#define LOG2E 1.4426950408889634f

typedef unsigned long long ull;
typedef unsigned int u32;

// ---------------- scratch ----------------
__device__ __half g_Qhl[BATCH * NQ * 64];   // [b][n][32 hi | 32 lo] fp16
__device__ __half g_Khl[BATCH * NQ * 64];   // [b][m][32 hi | 32 lo] fp16
__device__ __half g_VTh[BATCH * CH * NQ];   // [b][c][m] fp16
__device__ __half g_Whl[163840];            // wq h/l | wk h/l | wv h/l

// ---------------- helpers ----------------
__device__ __forceinline__ float ex2f(float x) {
    float r; asm("ex2.approx.f32 %0, %1;" : "=f"(r) : "f"(x)); return r;
}
__device__ __forceinline__ u32 smem_u32(const void* p) {
    u32 a; asm("{ .reg .u64 t; cvta.to.shared.u64 t, %1; cvt.u32.u64 %0, t; }" : "=r"(a) : "l"(p));
    return a;
}
__device__ __forceinline__ void cpa(u32 dst, const void* src) {
    asm volatile("cp.async.cg.shared.global [%0], [%1], 16;" :: "r"(dst), "l"(src));
}
#define CP_COMMIT() asm volatile("cp.async.commit_group;" ::: "memory")
template<int N> __device__ __forceinline__ void cp_wait() {
    asm volatile("cp.async.wait_group %0;" :: "n"(N) : "memory");
}
__device__ __forceinline__ void ldm4(u32* r, u32 addr) {
    asm volatile("ldmatrix.sync.aligned.m8n8.x4.shared.b16 {%0,%1,%2,%3}, [%4];"
                 : "=r"(r[0]), "=r"(r[1]), "=r"(r[2]), "=r"(r[3]) : "r"(addr));
}
__device__ __forceinline__ void ldm4t(u32* r, u32 addr) {
    asm volatile("ldmatrix.sync.aligned.m8n8.x4.trans.shared.b16 {%0,%1,%2,%3}, [%4];"
                 : "=r"(r[0]), "=r"(r[1]), "=r"(r[2]), "=r"(r[3]) : "r"(addr));
}
__device__ __forceinline__ void mma16816(float* d, const u32* a, const u32* b) {
    asm volatile(
        "mma.sync.aligned.m16n8k16.row.col.f32.f16.f16.f32 "
        "{%0,%1,%2,%3}, {%4,%5,%6,%7}, {%8,%9}, {%0,%1,%2,%3};"
        : "+f"(d[0]), "+f"(d[1]), "+f"(d[2]), "+f"(d[3])
        : "r"(a[0]), "r"(a[1]), "r"(a[2]), "r"(a[3]), "r"(b[0]), "r"(b[1]));
}

// ---------------- prep: W fp32 -> fp16 hi/lo ----------------
__global__ void prep_w(const float* __restrict__ wq, const float* __restrict__ wk,
                       const float* __restrict__ wv, __half* __restrict__ o) {
    int idx = blockIdx.x * 256 + threadIdx.x;
    float v; int hoff, loff, pos;
    if (idx < 8192)       { v = wq[idx];         hoff = 0;     loff = 8192;  pos = idx; }
    else if (idx < 16384) { v = wk[idx - 8192];  hoff = 16384; loff = 24576; pos = idx - 8192; }
    else if (idx < 81920) { v = wv[idx - 16384]; hoff = 32768; loff = 98304; pos = idx - 16384; }
    else return;
    __half h = __float2half_rn(v);
    o[hoff + pos] = h;
    o[loff + pos] = __float2half_rn(v - __half2float(h));
}

// F chunk convert hi+lo -> smem swizzled (for QK conv)
__device__ __forceinline__ void f_store(char* smx, u32 fh_off, u32 fl_off,
                                        const float4* pre, int tid) {
#pragma unroll
    for (int i = 0; i < 8; i++) {
        int idx = i * 256 + tid, row = idx >> 6, n = (idx & 63) * 4;
        float4 f = pre[i];
        __half2 h0 = __floats2half2_rn(f.x, f.y);
        __half2 h1 = __floats2half2_rn(f.z, f.w);
        float2 g0 = __half22float2(h0), g1 = __half22float2(h1);
        __half2 l0 = __floats2half2_rn(f.x - g0.x, f.y - g0.y);
        __half2 l1 = __floats2half2_rn(f.z - g1.x, f.w - g1.y);
        u32 off = row * 512 + (((n >> 3) ^ (row & 7)) << 4) + (n & 7) * 2;
        *(uint2*)(smx + fh_off + off) = make_uint2(*(u32*)&h0, *(u32*)&h1);
        *(uint2*)(smx + fl_off + off) = make_uint2(*(u32*)&l0, *(u32*)&l1);
    }
}

// F chunk convert hi only (for V conv)
__device__ __forceinline__ void f_store_h(char* smx, u32 fh_off,
                                          const float4* pre, int tid) {
#pragma unroll
    for (int i = 0; i < 8; i++) {
        int idx = i * 256 + tid, row = idx >> 6, n = (idx & 63) * 4;
        float4 f = pre[i];
        __half2 h0 = __floats2half2_rn(f.x, f.y);
        __half2 h1 = __floats2half2_rn(f.z, f.w);
        u32 off = row * 512 + (((n >> 3) ^ (row & 7)) << 4) + (n & 7) * 2;
        *(uint2*)(smx + fh_off + off) = make_uint2(*(u32*)&h0, *(u32*)&h1);
    }
}

// ---------------- merged conv Q+K via HMMA: out [n][32hi|32lo] ----------------
// blockIdx.y: 0 -> Q (f1), 1 -> K (f2)
#define QK_SMEM 69632
__global__ void __launch_bounds__(256, 1)
conv_qk_mma(const float* __restrict__ F1, const float* __restrict__ F2,
            const __half* __restrict__ Wall,
            const float* __restrict__ bq, const float* __restrict__ bk,
            __half* __restrict__ outq, __half* __restrict__ outk) {
    extern __shared__ char smx[];
    const u32 su = smem_u32(smx);
    const int tid = threadIdx.x, warp = tid >> 5, lane = tid & 31;
    const int n0 = blockIdx.x * 256, b = blockIdx.z;
    const int sel = blockIdx.y;
    const float* F = sel ? F2 : F1;
    const __half* Wh = Wall + sel * 16384;
    const __half* Wl = Wh + 8192;
    const float* bias = sel ? bk : bq;
    __half* out = sel ? outk : outq;
    const float* Fb = F + (size_t)b * CH * NQ;

    for (int i = tid; i < 2048; i += 256) {
        int arr = i >> 10, rem = i & 1023, row = rem >> 5, cch = rem & 31;
        const __half* src = (arr ? Wl : Wh) + row * 256 + cch * 8;
        *(uint4*)(smx + arr * 16384 + row * 512 + ((cch ^ (row & 7)) << 4)) =
            *(const uint4*)src;
    }

    float4 pre[8];
#pragma unroll
    for (int i = 0; i < 8; i++) {
        int idx = i * 256 + tid, row = idx >> 6, n = (idx & 63) * 4;
        pre[i] = *(const float4*)&Fb[(size_t)row * NQ + n0 + n];
    }

    float oacc[8][4];
#pragma unroll
    for (int i = 0; i < 8; i++)
#pragma unroll
        for (int j = 0; j < 4; j++) oacc[i][j] = 0.f;

    const int arow = (lane & 7) | (((lane >> 3) & 1) << 3);
    const int achk = lane >> 4;
    const int krow = (lane & 7) + ((lane >> 3) & 1) * 8;
    const int nsel = lane >> 4;
    const int ow = warp >> 2, nw = warp & 3;

    for (int ck = 0; ck < 8; ck++) {
        __syncthreads();
        f_store(smx, 32768, 49152, pre, tid);
        if (ck < 7) {
#pragma unroll
            for (int i = 0; i < 8; i++) {
                int idx = i * 256 + tid, row = idx >> 6, n = (idx & 63) * 4;
                pre[i] = *(const float4*)&Fb[(size_t)((ck + 1) * 32 + row) * NQ + n0 + n];
            }
        }
        __syncthreads();
#pragma unroll
        for (int kk = 0; kk < 2; kk++) {
            int orow = ow * 16 + arow;
            int cchunk = ck * 4 + kk * 2 + achk;
            u32 aaddr = su + orow * 512 + ((cchunk ^ (orow & 7)) << 4);
            u32 ah[4], al[4];
            ldm4(ah, aaddr);
            ldm4(al, aaddr + 16384);
            int crow = kk * 16 + krow;
#pragma unroll
            for (int ns = 0; ns < 4; ns++) {
                int nch = (nw * 64 + ns * 16 + nsel * 8) >> 3;
                u32 baddr = su + 32768 + crow * 512 + ((nch ^ (crow & 7)) << 4);
                u32 bh[4], bl[4];
                ldm4t(bh, baddr);
                ldm4t(bl, baddr + 16384);
#pragma unroll
                for (int g = 0; g < 2; g++) {
                    float* d = oacc[ns * 2 + g];
                    mma16816(d, ah, &bh[2 * g]);
                    mma16816(d, ah, &bl[2 * g]);
                    mma16816(d, al, &bh[2 * g]);
                }
            }
        }
    }

    // epilogue: bias + hi/lo split -> staging [n 256][72 halves] at byte 32768
    __syncthreads();
    const int or0 = ow * 16 + (lane >> 2);
    const float b0 = bias[or0], b1 = bias[or0 + 8];
    __half* stg = (__half*)(smx + 32768);
#pragma unroll
    for (int j = 0; j < 8; j++) {
        int n = nw * 64 + j * 8 + (lane & 3) * 2;
#pragma unroll
        for (int e = 0; e < 2; e++) {
            float v0 = oacc[j][e] + b0;
            float v1 = oacc[j][2 + e] + b1;
            __half h0 = __float2half_rn(v0);
            __half h1 = __float2half_rn(v1);
            stg[(n + e) * 72 + or0] = h0;
            stg[(n + e) * 72 + 32 + or0] = __float2half_rn(v0 - __half2float(h0));
            stg[(n + e) * 72 + or0 + 8] = h1;
            stg[(n + e) * 72 + 32 + or0 + 8] = __float2half_rn(v1 - __half2float(h1));
        }
    }
    __syncthreads();
    for (int i = tid; i < 2048; i += 256) {
        int n = i >> 3, u4 = i & 7;
        *(uint4*)&out[((size_t)b * NQ + n0 + n) * 64 + u4 * 8] =
            *(uint4*)(stg + n * 72 + u4 * 8);
    }
}

// ---------------- conv V via HMMA (single term Wh*Fh): out [c][m] fp16 ----------------
#define CV_SMEM 49152
__global__ void __launch_bounds__(256, 1)
conv_v_mma(const float* __restrict__ F, const __half* __restrict__ Wh,
           const float* __restrict__ bias, __half* __restrict__ out) {
    extern __shared__ char smx[];
    const u32 su = smem_u32(smx);
    const int tid = threadIdx.x, warp = tid >> 5, lane = tid & 31;
    const int n0 = blockIdx.x * 256, o0 = blockIdx.y * 64, b = blockIdx.z;
    const float* Fb = F + (size_t)b * CH * NQ;

    for (int i = tid; i < 2048; i += 256) {
        int row = i >> 5, cch = i & 31;
        const __half* src = Wh + (size_t)(o0 + row) * 256 + cch * 8;
        *(uint4*)(smx + row * 512 + ((cch ^ (row & 7)) << 4)) = *(const uint4*)src;
    }

    float4 pre[8];
#pragma unroll
    for (int i = 0; i < 8; i++) {
        int idx = i * 256 + tid, row = idx >> 6, n = (idx & 63) * 4;
        pre[i] = *(const float4*)&Fb[(size_t)row * NQ + n0 + n];
    }

    float oacc[16][4];
#pragma unroll
    for (int i = 0; i < 16; i++)
#pragma unroll
        for (int j = 0; j < 4; j++) oacc[i][j] = 0.f;

    const int arow = (lane & 7) | (((lane >> 3) & 1) << 3);
    const int achk = lane >> 4;
    const int krow = (lane & 7) + ((lane >> 3) & 1) * 8;
    const int nsel = lane >> 4;
    const int ob = warp >> 1, nw = warp & 1;

    for (int ck = 0; ck < 8; ck++) {
        __syncthreads();
        f_store_h(smx, 32768, pre, tid);
        if (ck < 7) {
#pragma unroll
            for (int i = 0; i < 8; i++) {
                int idx = i * 256 + tid, row = idx >> 6, n = (idx & 63) * 4;
                pre[i] = *(const float4*)&Fb[(size_t)((ck + 1) * 32 + row) * NQ + n0 + n];
            }
        }
        __syncthreads();
#pragma unroll
        for (int kk = 0; kk < 2; kk++) {
            int orow = ob * 16 + arow;
            int cchunk = ck * 4 + kk * 2 + achk;
            u32 aaddr = su + orow * 512 + ((cchunk ^ (orow & 7)) << 4);
            u32 ah[4];
            ldm4(ah, aaddr);
            int crow = kk * 16 + krow;
#pragma unroll
            for (int ns = 0; ns < 8; ns++) {
                int nch = (nw * 128 + ns * 16 + nsel * 8) >> 3;
                u32 baddr = su + 32768 + crow * 512 + ((nch ^ (crow & 7)) << 4);
                u32 bh[4];
                ldm4t(bh, baddr);
#pragma unroll
                for (int g = 0; g < 2; g++) {
                    float* d = oacc[ns * 2 + g];
                    mma16816(d, ah, &bh[2 * g]);
                }
            }
        }
    }

    // epilogue -> staging [o 64][272 halves] at byte 0 (reuse W region)
    __syncthreads();
    const int or0 = ob * 16 + (lane >> 2);
    const float b0 = bias[o0 + or0], b1 = bias[o0 + or0 + 8];
    __half* stg = (__half*)smx;
#pragma unroll
    for (int j = 0; j < 16; j++) {
        int n = nw * 128 + j * 8 + (lane & 3) * 2;
        __half2 h0 = __floats2half2_rn(oacc[j][0] + b0, oacc[j][1] + b0);
        __half2 h1 = __floats2half2_rn(oacc[j][2] + b1, oacc[j][3] + b1);
        *(__half2*)&stg[or0 * 272 + n] = h0;
        *(__half2*)&stg[(or0 + 8) * 272 + n] = h1;
    }
    __syncthreads();
    for (int i = tid; i < 2048; i += 256) {
        int row = i >> 5, c4 = i & 31;
        *(uint4*)&out[((size_t)b * CH + o0 + row) * NQ + n0 + c4 * 8] =
            *(uint4*)(stg + row * 272 + c4 * 8);
    }
}

// ---------------- mma.sync flash attention (fp16, split-key pipelined) ----------------
#define QS_OFF 0
#define KS_OFF 16384
#define VS_OFF 32768
#define NKT    (NQ / 64)
#define ATTN_SMEM 98304

__device__ __forceinline__ void exp_pack(const float* d, u32* ph,
                                         float& l0, float& l1) {
#pragma unroll
    for (int g = 0; g < 2; g++) {
        float p0 = ex2f(fmaf(d[4 * g + 0], LOG2E, -8.0f));
        float p1 = ex2f(fmaf(d[4 * g + 1], LOG2E, -8.0f));
        float p2 = ex2f(fmaf(d[4 * g + 2], LOG2E, -8.0f));
        float p3 = ex2f(fmaf(d[4 * g + 3], LOG2E, -8.0f));
        l0 += p0 + p1;
        l1 += p2 + p3;
        __half2 hh01 = __floats2half2_rn(p0, p1);
        __half2 hh23 = __floats2half2_rn(p2, p3);
        ph[2 * g] = *(u32*)&hh01;
        ph[2 * g + 1] = *(u32*)&hh23;
    }
}

__device__ __forceinline__ void load_kv(u32 su, const __half* Kb,
                                        const __half* Vhb, int kt, int tid) {
    int bf = kt & 1;
    for (int i = tid; i < 512; i += 256) {
        int m = i >> 3, j = i & 7;
        cpa(su + KS_OFF + bf * 8192 + m * 128 + ((j ^ (m & 7)) << 4),
            Kb + ((size_t)(kt * 64 + m)) * 64 + j * 8);
    }
    for (int i = tid; i < 2048; i += 256) {
        int c = i >> 3, j = i & 7;
        cpa(su + VS_OFF + bf * 32768 + c * 128 + ((j ^ (c & 7)) << 4),
            Vhb + (size_t)c * NQ + kt * 64 + j * 8);
    }
}

__global__ void __launch_bounds__(256, 1)
attn_kernel(const __half* __restrict__ Qg, const __half* __restrict__ Kg,
            const __half* __restrict__ Vhg, float* __restrict__ Og) {
    extern __shared__ char smx[];
    const u32 su = smem_u32(smx);
    const int tid = threadIdx.x, warp = tid >> 5, lane = tid & 31;
    const int b = blockIdx.y, q0 = blockIdx.x * 128;

    const __half* Qb  = Qg  + ((size_t)b * NQ + q0) * 64;
    const __half* Kb  = Kg  + (size_t)b * NQ * 64;
    const __half* Vhb = Vhg + (size_t)b * CH * NQ;

    for (int i = tid; i < 1024; i += 256) {
        int q = i >> 3, j = i & 7;
        cpa(su + QS_OFF + q * 128 + ((j ^ (q & 7)) << 4), Qb + (size_t)q * 64 + j * 8);
    }
    load_kv(su, Kb, Vhb, 0, tid);
    CP_COMMIT();
    load_kv(su, Kb, Vhb, 1, tid);
    CP_COMMIT();

    float oacc[32][4];
#pragma unroll
    for (int i = 0; i < 32; i++)
#pragma unroll
        for (int j = 0; j < 4; j++) oacc[i][j] = 0.f;
    float lsum0 = 0.f, lsum1 = 0.f;
    u32 qa[4][4];

    const int arow = (lane & 7) | (((lane >> 3) & 1) << 3);
    const int achk = lane >> 4;
    const int brow = (lane & 7) | ((lane >> 4) << 3);
    const int bchk = (lane >> 3) & 1;

    for (int kt = 0; kt < NKT; kt++) {
        cp_wait<1>();
        __syncthreads();
        if (kt == 0) {
            int qr = warp * 16 + arow;
            u32 qb_ = su + QS_OFF + qr * 128;
#pragma unroll
            for (int t = 0; t < 4; t++)
                ldm4(qa[t], qb_ + (((2 * t + achk) ^ (qr & 7)) << 4));
        }
        u32 kbuf = su + KS_OFF + (kt & 1) * 8192;
        u32 vbuf = su + VS_OFF + (kt & 1) * 32768;

        // ---- S = QK^T (3-term fp16), all 4 key-chunks into registers ----
        float ds[4][8];
#pragma unroll
        for (int mt = 0; mt < 4; mt++) {
            int kr = mt * 16 + brow;
            u32 kb_ = kbuf + kr * 128;
            int sw = kr & 7;
            u32 kh0[4], kh1[4], kl0[4], kl1[4];
            ldm4(kh0, kb_ + (((0 + bchk) ^ sw) << 4));
            ldm4(kh1, kb_ + (((2 + bchk) ^ sw) << 4));
            ldm4(kl0, kb_ + (((4 + bchk) ^ sw) << 4));
            ldm4(kl1, kb_ + (((6 + bchk) ^ sw) << 4));
#pragma unroll
            for (int g = 0; g < 2; g++) {
                float* d = &ds[mt][4 * g];
                d[0] = 0.f; d[1] = 0.f; d[2] = 0.f; d[3] = 0.f;
                mma16816(d, qa[0], &kh0[2 * g]);
                mma16816(d, qa[1], &kh1[2 * g]);
                mma16816(d, qa[0], &kl0[2 * g]);   // Qh * Klo
                mma16816(d, qa[1], &kl1[2 * g]);
                mma16816(d, qa[2], &kh0[2 * g]);   // Qlo * Kh
                mma16816(d, qa[3], &kh1[2 * g]);
            }
        }

        // ---- exp keys 0..31, then PV on t=0,1 while exp 32..63 interleaves ----
        u32 pah[4][4];
        exp_pack(ds[0], pah[0], lsum0, lsum1);
        exp_pack(ds[1], pah[1], lsum0, lsum1);

#pragma unroll
        for (int cb = 0; cb < 8; cb++) {
            int vr = cb * 16 + brow;
            u32 vh_ = vbuf + vr * 128;
            int sw = vr & 7;
            u32 v0[4], v1[4];
            ldm4(v0, vh_ + (((0 + bchk) ^ sw) << 4));
            ldm4(v1, vh_ + (((2 + bchk) ^ sw) << 4));
            mma16816(oacc[2 * cb],     pah[0], &v0[0]);
            mma16816(oacc[2 * cb + 1], pah[0], &v0[2]);
            mma16816(oacc[2 * cb],     pah[1], &v1[0]);
            mma16816(oacc[2 * cb + 1], pah[1], &v1[2]);
        }

        exp_pack(ds[2], pah[2], lsum0, lsum1);
        exp_pack(ds[3], pah[3], lsum0, lsum1);

#pragma unroll
        for (int cb = 8; cb < 16; cb++) {
            int vr = cb * 16 + brow;
            u32 vh_ = vbuf + vr * 128;
            int sw = vr & 7;
            u32 v0[4], v1[4];
            ldm4(v0, vh_ + (((0 + bchk) ^ sw) << 4));
            ldm4(v1, vh_ + (((2 + bchk) ^ sw) << 4));
            mma16816(oacc[2 * cb],     pah[0], &v0[0]);
            mma16816(oacc[2 * cb + 1], pah[0], &v0[2]);
            mma16816(oacc[2 * cb],     pah[1], &v1[0]);
            mma16816(oacc[2 * cb + 1], pah[1], &v1[2]);
        }

        // ---- PV on t=2,3 ----
#pragma unroll
        for (int cb = 0; cb < 16; cb++) {
            int vr = cb * 16 + brow;
            u32 vh_ = vbuf + vr * 128;
            int sw = vr & 7;
            u32 v2[4], v3[4];
            ldm4(v2, vh_ + (((4 + bchk) ^ sw) << 4));
            ldm4(v3, vh_ + (((6 + bchk) ^ sw) << 4));
            mma16816(oacc[2 * cb],     pah[2], &v2[0]);
            mma16816(oacc[2 * cb + 1], pah[2], &v2[2]);
            mma16816(oacc[2 * cb],     pah[3], &v3[0]);
            mma16816(oacc[2 * cb + 1], pah[3], &v3[2]);
        }

        __syncthreads();
        if (kt + 2 < NKT) load_kv(su, Kb, Vhb, kt + 2, tid);
        CP_COMMIT();
    }

    lsum0 += __shfl_xor_sync(0xffffffffu, lsum0, 1);
    lsum0 += __shfl_xor_sync(0xffffffffu, lsum0, 2);
    lsum1 += __shfl_xor_sync(0xffffffffu, lsum1, 1);
    lsum1 += __shfl_xor_sync(0xffffffffu, lsum1, 2);
    float inv0 = 1.0f / lsum0, inv1 = 1.0f / lsum1;
    float* og = Og + (size_t)b * CH * NQ;
    int q = q0 + warp * 16 + (lane >> 2);
#pragma unroll
    for (int ng = 0; ng < 32; ng++) {
        int c = ng * 8 + (lane & 3) * 2;
        og[(size_t)c * NQ + q]           = oacc[ng][0] * inv0;
        og[(size_t)(c + 1) * NQ + q]     = oacc[ng][1] * inv0;
        og[(size_t)c * NQ + q + 8]       = oacc[ng][2] * inv1;
        og[(size_t)(c + 1) * NQ + q + 8] = oacc[ng][3] * inv1;
    }
}

// ---------------- launch ----------------
extern "C" void kernel_launch(void* const* d_in, const int* in_sizes, int n_in,
                              void* d_out, int out_size) {
    const float* f1 = (const float*)d_in[0];
    const float* f2 = (const float*)d_in[1];
    const float* f3 = (const float*)d_in[2];
    const float* wq = (const float*)d_in[3];
    const float* bq = (const float*)d_in[4];
    const float* wk = (const float*)d_in[5];
    const float* bk = (const float*)d_in[6];
    const float* wv = (const float*)d_in[7];
    const float* bv = (const float*)d_in[8];
    float* out = (float*)d_out;

    __half *qp, *kp, *vhp, *whl;
    cudaGetSymbolAddress((void**)&qp, g_Qhl);
    cudaGetSymbolAddress((void**)&kp, g_Khl);
    cudaGetSymbolAddress((void**)&vhp, g_VTh);
    cudaGetSymbolAddress((void**)&whl, g_Whl);

    prep_w<<<320, 256>>>(wq, wk, wv, whl);

    cudaFuncSetAttribute(conv_qk_mma, cudaFuncAttributeMaxDynamicSharedMemorySize, QK_SMEM);
    cudaFuncSetAttribute(conv_v_mma, cudaFuncAttributeMaxDynamicSharedMemorySize, CV_SMEM);

    dim3 gqk(NQ / 256, 2, BATCH);
    conv_qk_mma<<<gqk, 256, QK_SMEM>>>(f1, f2, whl, bq, bk, qp, kp);
    dim3 gv(NQ / 256, CH / 64, BATCH);
    conv_v_mma<<<gv, 256, CV_SMEM>>>(f3, whl + 32768, bv, vhp);

    cudaFuncSetAttribute(attn_kernel, cudaFuncAttributeMaxDynamicSharedMemorySize,
                         ATTN_SMEM);
    dim3 ga(NQ / 128, BATCH);
    attn_kernel<<<ga, 256, ATTN_SMEM>>>(qp, kp, vhp, out);
}

// round 15
// speedup vs baseline: 26.7640x; 1.0750x over previous
#include <cuda_runtime.h>
#include <cuda_bf16.h>
#include <cuda_fp16.h>

#define BATCH 8
#define CH    256
#define CQK   32
#define NQ    4096
#define LOG2E 1.4426950408889634f

typedef unsigned long long ull;
typedef unsigned int u32;

// ---------------- scratch ----------------
__device__ __half g_Qhl[BATCH * NQ * 64];   // [b][n][32 hi | 32 lo] fp16
__device__ __half g_Khl[BATCH * NQ * 64];   // [b][m][32 hi | 32 lo] fp16
__device__ __half g_VTh[BATCH * CH * NQ];   // [b][c][m] fp16
__device__ __half g_Whl[163840];            // wq h/l | wk h/l | wv h/l

// ---------------- helpers ----------------
__device__ __forceinline__ float ex2f(float x) {
    float r; asm("ex2.approx.f32 %0, %1;" : "=f"(r) : "f"(x)); return r;
}
__device__ __forceinline__ u32 smem_u32(const void* p) {
    u32 a; asm("{ .reg .u64 t; cvta.to.shared.u64 t, %1; cvt.u32.u64 %0, t; }" : "=r"(a) : "l"(p));
    return a;
}
__device__ __forceinline__ void cpa(u32 dst, const void* src) {
    asm volatile("cp.async.cg.shared.global [%0], [%1], 16;" :: "r"(dst), "l"(src));
}
#define CP_COMMIT() asm volatile("cp.async.commit_group;" ::: "memory")
template<int N> __device__ __forceinline__ void cp_wait() {
    asm volatile("cp.async.wait_group %0;" :: "n"(N) : "memory");
}
__device__ __forceinline__ void ldm4(u32* r, u32 addr) {
    asm volatile("ldmatrix.sync.aligned.m8n8.x4.shared.b16 {%0,%1,%2,%3}, [%4];"
                 : "=r"(r[0]), "=r"(r[1]), "=r"(r[2]), "=r"(r[3]) : "r"(addr));
}
__device__ __forceinline__ void ldm4t(u32* r, u32 addr) {
    asm volatile("ldmatrix.sync.aligned.m8n8.x4.trans.shared.b16 {%0,%1,%2,%3}, [%4];"
                 : "=r"(r[0]), "=r"(r[1]), "=r"(r[2]), "=r"(r[3]) : "r"(addr));
}
__device__ __forceinline__ void mma16816(float* d, const u32* a, const u32* b) {
    asm volatile(
        "mma.sync.aligned.m16n8k16.row.col.f32.f16.f16.f32 "
        "{%0,%1,%2,%3}, {%4,%5,%6,%7}, {%8,%9}, {%0,%1,%2,%3};"
        : "+f"(d[0]), "+f"(d[1]), "+f"(d[2]), "+f"(d[3])
        : "r"(a[0]), "r"(a[1]), "r"(a[2]), "r"(a[3]), "r"(b[0]), "r"(b[1]));
}

// ---------------- prep: W fp32 -> fp16 hi/lo ----------------
__global__ void prep_w(const float* __restrict__ wq, const float* __restrict__ wk,
                       const float* __restrict__ wv, __half* __restrict__ o) {
    int idx = blockIdx.x * 256 + threadIdx.x;
    float v; int hoff, loff, pos;
    if (idx < 8192)       { v = wq[idx];         hoff = 0;     loff = 8192;  pos = idx; }
    else if (idx < 16384) { v = wk[idx - 8192];  hoff = 16384; loff = 24576; pos = idx - 8192; }
    else if (idx < 81920) { v = wv[idx - 16384]; hoff = 32768; loff = 98304; pos = idx - 16384; }
    else return;
    __half h = __float2half_rn(v);
    o[hoff + pos] = h;
    o[loff + pos] = __float2half_rn(v - __half2float(h));
}

// F chunk convert hi+lo -> smem swizzled (for QK conv)
__device__ __forceinline__ void f_store(char* smx, u32 fh_off, u32 fl_off,
                                        const float4* pre, int tid) {
#pragma unroll
    for (int i = 0; i < 8; i++) {
        int idx = i * 256 + tid, row = idx >> 6, n = (idx & 63) * 4;
        float4 f = pre[i];
        __half2 h0 = __floats2half2_rn(f.x, f.y);
        __half2 h1 = __floats2half2_rn(f.z, f.w);
        float2 g0 = __half22float2(h0), g1 = __half22float2(h1);
        __half2 l0 = __floats2half2_rn(f.x - g0.x, f.y - g0.y);
        __half2 l1 = __floats2half2_rn(f.z - g1.x, f.w - g1.y);
        u32 off = row * 512 + (((n >> 3) ^ (row & 7)) << 4) + (n & 7) * 2;
        *(uint2*)(smx + fh_off + off) = make_uint2(*(u32*)&h0, *(u32*)&h1);
        *(uint2*)(smx + fl_off + off) = make_uint2(*(u32*)&l0, *(u32*)&l1);
    }
}

// F chunk convert hi only (for V conv)
__device__ __forceinline__ void f_store_h(char* smx, u32 fh_off,
                                          const float4* pre, int tid) {
#pragma unroll
    for (int i = 0; i < 8; i++) {
        int idx = i * 256 + tid, row = idx >> 6, n = (idx & 63) * 4;
        float4 f = pre[i];
        __half2 h0 = __floats2half2_rn(f.x, f.y);
        __half2 h1 = __floats2half2_rn(f.z, f.w);
        u32 off = row * 512 + (((n >> 3) ^ (row & 7)) << 4) + (n & 7) * 2;
        *(uint2*)(smx + fh_off + off) = make_uint2(*(u32*)&h0, *(u32*)&h1);
    }
}

// ---------------- merged conv Q+K via HMMA: out [n][32hi|32lo] ----------------
// blockIdx.y: 0 -> Q (f1), 1 -> K (f2)
#define QK_SMEM 69632
__global__ void __launch_bounds__(256, 1)
conv_qk_mma(const float* __restrict__ F1, const float* __restrict__ F2,
            const __half* __restrict__ Wall,
            const float* __restrict__ bq, const float* __restrict__ bk,
            __half* __restrict__ outq, __half* __restrict__ outk) {
    extern __shared__ char smx[];
    const u32 su = smem_u32(smx);
    const int tid = threadIdx.x, warp = tid >> 5, lane = tid & 31;
    const int n0 = blockIdx.x * 256, b = blockIdx.z;
    const int sel = blockIdx.y;
    const float* F = sel ? F2 : F1;
    const __half* Wh = Wall + sel * 16384;
    const __half* Wl = Wh + 8192;
    const float* bias = sel ? bk : bq;
    __half* out = sel ? outk : outq;
    const float* Fb = F + (size_t)b * CH * NQ;

    for (int i = tid; i < 2048; i += 256) {
        int arr = i >> 10, rem = i & 1023, row = rem >> 5, cch = rem & 31;
        const __half* src = (arr ? Wl : Wh) + row * 256 + cch * 8;
        *(uint4*)(smx + arr * 16384 + row * 512 + ((cch ^ (row & 7)) << 4)) =
            *(const uint4*)src;
    }

    float4 pre[8];
#pragma unroll
    for (int i = 0; i < 8; i++) {
        int idx = i * 256 + tid, row = idx >> 6, n = (idx & 63) * 4;
        pre[i] = *(const float4*)&Fb[(size_t)row * NQ + n0 + n];
    }

    float oacc[8][4];
#pragma unroll
    for (int i = 0; i < 8; i++)
#pragma unroll
        for (int j = 0; j < 4; j++) oacc[i][j] = 0.f;

    const int arow = (lane & 7) | (((lane >> 3) & 1) << 3);
    const int achk = lane >> 4;
    const int krow = (lane & 7) + ((lane >> 3) & 1) * 8;
    const int nsel = lane >> 4;
    const int ow = warp >> 2, nw = warp & 3;

    for (int ck = 0; ck < 8; ck++) {
        __syncthreads();
        f_store(smx, 32768, 49152, pre, tid);
        if (ck < 7) {
#pragma unroll
            for (int i = 0; i < 8; i++) {
                int idx = i * 256 + tid, row = idx >> 6, n = (idx & 63) * 4;
                pre[i] = *(const float4*)&Fb[(size_t)((ck + 1) * 32 + row) * NQ + n0 + n];
            }
        }
        __syncthreads();
#pragma unroll
        for (int kk = 0; kk < 2; kk++) {
            int orow = ow * 16 + arow;
            int cchunk = ck * 4 + kk * 2 + achk;
            u32 aaddr = su + orow * 512 + ((cchunk ^ (orow & 7)) << 4);
            u32 ah[4], al[4];
            ldm4(ah, aaddr);
            ldm4(al, aaddr + 16384);
            int crow = kk * 16 + krow;
#pragma unroll
            for (int ns = 0; ns < 4; ns++) {
                int nch = (nw * 64 + ns * 16 + nsel * 8) >> 3;
                u32 baddr = su + 32768 + crow * 512 + ((nch ^ (crow & 7)) << 4);
                u32 bh[4], bl[4];
                ldm4t(bh, baddr);
                ldm4t(bl, baddr + 16384);
#pragma unroll
                for (int g = 0; g < 2; g++) {
                    float* d = oacc[ns * 2 + g];
                    mma16816(d, ah, &bh[2 * g]);
                    mma16816(d, ah, &bl[2 * g]);
                    mma16816(d, al, &bh[2 * g]);
                }
            }
        }
    }

    // epilogue: bias + hi/lo split -> staging [n 256][72 halves] at byte 32768
    __syncthreads();
    const int or0 = ow * 16 + (lane >> 2);
    const float b0 = bias[or0], b1 = bias[or0 + 8];
    __half* stg = (__half*)(smx + 32768);
#pragma unroll
    for (int j = 0; j < 8; j++) {
        int n = nw * 64 + j * 8 + (lane & 3) * 2;
#pragma unroll
        for (int e = 0; e < 2; e++) {
            float v0 = oacc[j][e] + b0;
            float v1 = oacc[j][2 + e] + b1;
            __half h0 = __float2half_rn(v0);
            __half h1 = __float2half_rn(v1);
            stg[(n + e) * 72 + or0] = h0;
            stg[(n + e) * 72 + 32 + or0] = __float2half_rn(v0 - __half2float(h0));
            stg[(n + e) * 72 + or0 + 8] = h1;
            stg[(n + e) * 72 + 32 + or0 + 8] = __float2half_rn(v1 - __half2float(h1));
        }
    }
    __syncthreads();
    for (int i = tid; i < 2048; i += 256) {
        int n = i >> 3, u4 = i & 7;
        *(uint4*)&out[((size_t)b * NQ + n0 + n) * 64 + u4 * 8] =
            *(uint4*)(stg + n * 72 + u4 * 8);
    }
}

// ---------------- conv V via HMMA (single term Wh*Fh): out [c][m] fp16 ----------------
#define CV_SMEM 49152
__global__ void __launch_bounds__(256, 1)
conv_v_mma(const float* __restrict__ F, const __half* __restrict__ Wh,
           const float* __restrict__ bias, __half* __restrict__ out) {
    extern __shared__ char smx[];
    const u32 su = smem_u32(smx);
    const int tid = threadIdx.x, warp = tid >> 5, lane = tid & 31;
    const int n0 = blockIdx.x * 256, o0 = blockIdx.y * 64, b = blockIdx.z;
    const float* Fb = F + (size_t)b * CH * NQ;

    for (int i = tid; i < 2048; i += 256) {
        int row = i >> 5, cch = i & 31;
        const __half* src = Wh + (size_t)(o0 + row) * 256 + cch * 8;
        *(uint4*)(smx + row * 512 + ((cch ^ (row & 7)) << 4)) = *(const uint4*)src;
    }

    float4 pre[8];
#pragma unroll
    for (int i = 0; i < 8; i++) {
        int idx = i * 256 + tid, row = idx >> 6, n = (idx & 63) * 4;
        pre[i] = *(const float4*)&Fb[(size_t)row * NQ + n0 + n];
    }

    float oacc[16][4];
#pragma unroll
    for (int i = 0; i < 16; i++)
#pragma unroll
        for (int j = 0; j < 4; j++) oacc[i][j] = 0.f;

    const int arow = (lane & 7) | (((lane >> 3) & 1) << 3);
    const int achk = lane >> 4;
    const int krow = (lane & 7) + ((lane >> 3) & 1) * 8;
    const int nsel = lane >> 4;
    const int ob = warp >> 1, nw = warp & 1;

    for (int ck = 0; ck < 8; ck++) {
        __syncthreads();
        f_store_h(smx, 32768, pre, tid);
        if (ck < 7) {
#pragma unroll
            for (int i = 0; i < 8; i++) {
                int idx = i * 256 + tid, row = idx >> 6, n = (idx & 63) * 4;
                pre[i] = *(const float4*)&Fb[(size_t)((ck + 1) * 32 + row) * NQ + n0 + n];
            }
        }
        __syncthreads();
#pragma unroll
        for (int kk = 0; kk < 2; kk++) {
            int orow = ob * 16 + arow;
            int cchunk = ck * 4 + kk * 2 + achk;
            u32 aaddr = su + orow * 512 + ((cchunk ^ (orow & 7)) << 4);
            u32 ah[4];
            ldm4(ah, aaddr);
            int crow = kk * 16 + krow;
#pragma unroll
            for (int ns = 0; ns < 8; ns++) {
                int nch = (nw * 128 + ns * 16 + nsel * 8) >> 3;
                u32 baddr = su + 32768 + crow * 512 + ((nch ^ (crow & 7)) << 4);
                u32 bh[4];
                ldm4t(bh, baddr);
#pragma unroll
                for (int g = 0; g < 2; g++) {
                    float* d = oacc[ns * 2 + g];
                    mma16816(d, ah, &bh[2 * g]);
                }
            }
        }
    }

    // epilogue -> staging [o 64][272 halves] at byte 0 (reuse W region)
    __syncthreads();
    const int or0 = ob * 16 + (lane >> 2);
    const float b0 = bias[o0 + or0], b1 = bias[o0 + or0 + 8];
    __half* stg = (__half*)smx;
#pragma unroll
    for (int j = 0; j < 16; j++) {
        int n = nw * 128 + j * 8 + (lane & 3) * 2;
        __half2 h0 = __floats2half2_rn(oacc[j][0] + b0, oacc[j][1] + b0);
        __half2 h1 = __floats2half2_rn(oacc[j][2] + b1, oacc[j][3] + b1);
        *(__half2*)&stg[or0 * 272 + n] = h0;
        *(__half2*)&stg[(or0 + 8) * 272 + n] = h1;
    }
    __syncthreads();
    for (int i = tid; i < 2048; i += 256) {
        int row = i >> 5, c4 = i & 31;
        *(uint4*)&out[((size_t)b * CH + o0 + row) * NQ + n0 + c4 * 8] =
            *(uint4*)(stg + row * 272 + c4 * 8);
    }
}

// ---------------- mma.sync flash attention (fp16, 2-term S, 3-stage ring) ----------------
#define QS_OFF 0
#define KS_OFF 16384
#define VS_OFF 40960
#define NKT    (NQ / 64)
#define ATTN_SMEM 139264

__device__ __forceinline__ void exp_pack(const float* d, u32* ph,
                                         float& l0, float& l1) {
#pragma unroll
    for (int g = 0; g < 2; g++) {
        float p0 = ex2f(fmaf(d[4 * g + 0], LOG2E, -8.0f));
        float p1 = ex2f(fmaf(d[4 * g + 1], LOG2E, -8.0f));
        float p2 = ex2f(fmaf(d[4 * g + 2], LOG2E, -8.0f));
        float p3 = ex2f(fmaf(d[4 * g + 3], LOG2E, -8.0f));
        l0 += p0 + p1;
        l1 += p2 + p3;
        __half2 hh01 = __floats2half2_rn(p0, p1);
        __half2 hh23 = __floats2half2_rn(p2, p3);
        ph[2 * g] = *(u32*)&hh01;
        ph[2 * g + 1] = *(u32*)&hh23;
    }
}

// K hi only (S is 2-term (Qh+Ql)*Kh): 8KB/stage K, 32KB/stage V, 3 stages
__device__ __forceinline__ void load_kv(u32 su, const __half* Kb,
                                        const __half* Vhb, int kt, int tid) {
    int bf = kt % 3;
    for (int i = tid; i < 512; i += 256) {
        int m = i >> 3, j = i & 7;
        cpa(su + KS_OFF + bf * 8192 + m * 128 + ((j ^ (m & 7)) << 4),
            Kb + ((size_t)(kt * 64 + m)) * 64 + j * 8);
    }
    for (int i = tid; i < 2048; i += 256) {
        int c = i >> 3, j = i & 7;
        cpa(su + VS_OFF + bf * 32768 + c * 128 + ((j ^ (c & 7)) << 4),
            Vhb + (size_t)c * NQ + kt * 64 + j * 8);
    }
}

__global__ void __launch_bounds__(256, 1)
attn_kernel(const __half* __restrict__ Qg, const __half* __restrict__ Kg,
            const __half* __restrict__ Vhg, float* __restrict__ Og) {
    extern __shared__ char smx[];
    const u32 su = smem_u32(smx);
    const int tid = threadIdx.x, warp = tid >> 5, lane = tid & 31;
    const int b = blockIdx.y, q0 = blockIdx.x * 128;

    const __half* Qb  = Qg  + ((size_t)b * NQ + q0) * 64;
    const __half* Kb  = Kg  + (size_t)b * NQ * 64;
    const __half* Vhb = Vhg + (size_t)b * CH * NQ;

    for (int i = tid; i < 1024; i += 256) {
        int q = i >> 3, j = i & 7;
        cpa(su + QS_OFF + q * 128 + ((j ^ (q & 7)) << 4), Qb + (size_t)q * 64 + j * 8);
    }
    load_kv(su, Kb, Vhb, 0, tid);
    CP_COMMIT();
    load_kv(su, Kb, Vhb, 1, tid);
    CP_COMMIT();

    float oacc[32][4];
#pragma unroll
    for (int i = 0; i < 32; i++)
#pragma unroll
        for (int j = 0; j < 4; j++) oacc[i][j] = 0.f;
    float lsum0 = 0.f, lsum1 = 0.f;
    u32 qa[4][4];

    const int arow = (lane & 7) | (((lane >> 3) & 1) << 3);
    const int achk = lane >> 4;
    const int brow = (lane & 7) | ((lane >> 4) << 3);
    const int bchk = (lane >> 3) & 1;

    for (int kt = 0; kt < NKT; kt++) {
        // wait own tile-kt loads; sync makes everyone's visible; bounds drift
        cp_wait<1>();
        __syncthreads();
        // issue loads for kt+2 into stage (kt+2)%3 — consumed stage (kt-1)%3 is free
        if (kt + 2 < NKT) load_kv(su, Kb, Vhb, kt + 2, tid);
        CP_COMMIT();

        if (kt == 0) {
            int qr = warp * 16 + arow;
            u32 qb_ = su + QS_OFF + qr * 128;
#pragma unroll
            for (int t = 0; t < 4; t++)
                ldm4(qa[t], qb_ + (((2 * t + achk) ^ (qr & 7)) << 4));
        }
        u32 kbuf = su + KS_OFF + (kt % 3) * 8192;
        u32 vbuf = su + VS_OFF + (kt % 3) * 32768;

        // ---- S = (Qh+Ql) Kh^T (2-term), all 4 key-chunks into registers ----
        float ds[4][8];
#pragma unroll
        for (int mt = 0; mt < 4; mt++) {
            int kr = mt * 16 + brow;
            u32 kb_ = kbuf + kr * 128;
            int sw = kr & 7;
            u32 kh0[4], kh1[4];
            ldm4(kh0, kb_ + (((0 + bchk) ^ sw) << 4));
            ldm4(kh1, kb_ + (((2 + bchk) ^ sw) << 4));
#pragma unroll
            for (int g = 0; g < 2; g++) {
                float* d = &ds[mt][4 * g];
                d[0] = 0.f; d[1] = 0.f; d[2] = 0.f; d[3] = 0.f;
                mma16816(d, qa[0], &kh0[2 * g]);
                mma16816(d, qa[1], &kh1[2 * g]);
                mma16816(d, qa[2], &kh0[2 * g]);   // Qlo * Kh
                mma16816(d, qa[3], &kh1[2 * g]);
            }
        }

        // ---- exp keys 0..31, PV t=0,1 (first half), exp 32..63, PV rest ----
        u32 pah[4][4];
        exp_pack(ds[0], pah[0], lsum0, lsum1);
        exp_pack(ds[1], pah[1], lsum0, lsum1);

#pragma unroll
        for (int cb = 0; cb < 8; cb++) {
            int vr = cb * 16 + brow;
            u32 vh_ = vbuf + vr * 128;
            int sw = vr & 7;
            u32 v0[4], v1[4];
            ldm4(v0, vh_ + (((0 + bchk) ^ sw) << 4));
            ldm4(v1, vh_ + (((2 + bchk) ^ sw) << 4));
            mma16816(oacc[2 * cb],     pah[0], &v0[0]);
            mma16816(oacc[2 * cb + 1], pah[0], &v0[2]);
            mma16816(oacc[2 * cb],     pah[1], &v1[0]);
            mma16816(oacc[2 * cb + 1], pah[1], &v1[2]);
        }

        exp_pack(ds[2], pah[2], lsum0, lsum1);
        exp_pack(ds[3], pah[3], lsum0, lsum1);

#pragma unroll
        for (int cb = 8; cb < 16; cb++) {
            int vr = cb * 16 + brow;
            u32 vh_ = vbuf + vr * 128;
            int sw = vr & 7;
            u32 v0[4], v1[4];
            ldm4(v0, vh_ + (((0 + bchk) ^ sw) << 4));
            ldm4(v1, vh_ + (((2 + bchk) ^ sw) << 4));
            mma16816(oacc[2 * cb],     pah[0], &v0[0]);
            mma16816(oacc[2 * cb + 1], pah[0], &v0[2]);
            mma16816(oacc[2 * cb],     pah[1], &v1[0]);
            mma16816(oacc[2 * cb + 1], pah[1], &v1[2]);
        }

#pragma unroll
        for (int cb = 0; cb < 16; cb++) {
            int vr = cb * 16 + brow;
            u32 vh_ = vbuf + vr * 128;
            int sw = vr & 7;
            u32 v2[4], v3[4];
            ldm4(v2, vh_ + (((4 + bchk) ^ sw) << 4));
            ldm4(v3, vh_ + (((6 + bchk) ^ sw) << 4));
            mma16816(oacc[2 * cb],     pah[2], &v2[0]);
            mma16816(oacc[2 * cb + 1], pah[2], &v2[2]);
            mma16816(oacc[2 * cb],     pah[3], &v3[0]);
            mma16816(oacc[2 * cb + 1], pah[3], &v3[2]);
        }
    }

    lsum0 += __shfl_xor_sync(0xffffffffu, lsum0, 1);
    lsum0 += __shfl_xor_sync(0xffffffffu, lsum0, 2);
    lsum1 += __shfl_xor_sync(0xffffffffu, lsum1, 1);
    lsum1 += __shfl_xor_sync(0xffffffffu, lsum1, 2);
    float inv0 = 1.0f / lsum0, inv1 = 1.0f / lsum1;
    float* og = Og + (size_t)b * CH * NQ;
    int q = q0 + warp * 16 + (lane >> 2);
#pragma unroll
    for (int ng = 0; ng < 32; ng++) {
        int c = ng * 8 + (lane & 3) * 2;
        og[(size_t)c * NQ + q]           = oacc[ng][0] * inv0;
        og[(size_t)(c + 1) * NQ + q]     = oacc[ng][1] * inv0;
        og[(size_t)c * NQ + q + 8]       = oacc[ng][2] * inv1;
        og[(size_t)(c + 1) * NQ + q + 8] = oacc[ng][3] * inv1;
    }
}

// ---------------- launch ----------------
extern "C" void kernel_launch(void* const* d_in, const int* in_sizes, int n_in,
                              void* d_out, int out_size) {
    const float* f1 = (const float*)d_in[0];
    const float* f2 = (const float*)d_in[1];
    const float* f3 = (const float*)d_in[2];
    const float* wq = (const float*)d_in[3];
    const float* bq = (const float*)d_in[4];
    const float* wk = (const float*)d_in[5];
    const float* bk = (const float*)d_in[6];
    const float* wv = (const float*)d_in[7];
    const float* bv = (const float*)d_in[8];
    float* out = (float*)d_out;

    __half *qp, *kp, *vhp, *whl;
    cudaGetSymbolAddress((void**)&qp, g_Qhl);
    cudaGetSymbolAddress((void**)&kp, g_Khl);
    cudaGetSymbolAddress((void**)&vhp, g_VTh);
    cudaGetSymbolAddress((void**)&whl, g_Whl);

    prep_w<<<320, 256>>>(wq, wk, wv, whl);

    cudaFuncSetAttribute(conv_qk_mma, cudaFuncAttributeMaxDynamicSharedMemorySize, QK_SMEM);
    cudaFuncSetAttribute(conv_v_mma, cudaFuncAttributeMaxDynamicSharedMemorySize, CV_SMEM);

    dim3 gqk(NQ / 256, 2, BATCH);
    conv_qk_mma<<<gqk, 256, QK_SMEM>>>(f1, f2, whl, bq, bk, qp, kp);
    dim3 gv(NQ / 256, CH / 64, BATCH);
    conv_v_mma<<<gv, 256, CV_SMEM>>>(f3, whl + 32768, bv, vhp);

    cudaFuncSetAttribute(attn_kernel, cudaFuncAttributeMaxDynamicSharedMemorySize,
                         ATTN_SMEM);
    dim3 ga(NQ / 128, BATCH);
    attn_kernel<<<ga, 256, ATTN_SMEM>>>(qp, kp, vhp, out);
}

// round 16
// speedup vs baseline: 26.9543x; 1.0071x over previous
#include <cuda_runtime.h>
#include <cuda_bf16.h>
#include <cuda_fp16.h>

#define BATCH 8
#define CH    256
#define CQK   32
#define NQ    4096
#define LOG2E 1.4426950408889634f

typedef unsigned long long ull;
typedef unsigned int u32;

// ---------------- scratch ----------------
__device__ __half g_Qhl[BATCH * NQ * 64];   // [b][n][32 hi | 32 lo] fp16
__device__ __half g_Khl[BATCH * NQ * 64];   // [b][m][32 hi | 32 lo] fp16
__device__ __half g_VTh[BATCH * CH * NQ];   // [b][c][m] fp16
__device__ __half g_Whl[163840];            // wq h/l | wk h/l | wv h/l

// ---------------- helpers ----------------
__device__ __forceinline__ float ex2f(float x) {
    float r; asm("ex2.approx.f32 %0, %1;" : "=f"(r) : "f"(x)); return r;
}
__device__ __forceinline__ u32 smem_u32(const void* p) {
    u32 a; asm("{ .reg .u64 t; cvta.to.shared.u64 t, %1; cvt.u32.u64 %0, t; }" : "=r"(a) : "l"(p));
    return a;
}
__device__ __forceinline__ void cpa(u32 dst, const void* src) {
    asm volatile("cp.async.cg.shared.global [%0], [%1], 16;" :: "r"(dst), "l"(src));
}
#define CP_COMMIT() asm volatile("cp.async.commit_group;" ::: "memory")
template<int N> __device__ __forceinline__ void cp_wait() {
    asm volatile("cp.async.wait_group %0;" :: "n"(N) : "memory");
}
__device__ __forceinline__ void ldm4(u32* r, u32 addr) {
    asm volatile("ldmatrix.sync.aligned.m8n8.x4.shared.b16 {%0,%1,%2,%3}, [%4];"
                 : "=r"(r[0]), "=r"(r[1]), "=r"(r[2]), "=r"(r[3]) : "r"(addr));
}
__device__ __forceinline__ void ldm4t(u32* r, u32 addr) {
    asm volatile("ldmatrix.sync.aligned.m8n8.x4.trans.shared.b16 {%0,%1,%2,%3}, [%4];"
                 : "=r"(r[0]), "=r"(r[1]), "=r"(r[2]), "=r"(r[3]) : "r"(addr));
}
__device__ __forceinline__ void mma16816(float* d, const u32* a, const u32* b) {
    asm volatile(
        "mma.sync.aligned.m16n8k16.row.col.f32.f16.f16.f32 "
        "{%0,%1,%2,%3}, {%4,%5,%6,%7}, {%8,%9}, {%0,%1,%2,%3};"
        : "+f"(d[0]), "+f"(d[1]), "+f"(d[2]), "+f"(d[3])
        : "r"(a[0]), "r"(a[1]), "r"(a[2]), "r"(a[3]), "r"(b[0]), "r"(b[1]));
}

// ---------------- prep: W fp32 -> fp16 hi/lo ----------------
__global__ void prep_w(const float* __restrict__ wq, const float* __restrict__ wk,
                       const float* __restrict__ wv, __half* __restrict__ o) {
    int idx = blockIdx.x * 256 + threadIdx.x;
    float v; int hoff, loff, pos;
    if (idx < 8192)       { v = wq[idx];         hoff = 0;     loff = 8192;  pos = idx; }
    else if (idx < 16384) { v = wk[idx - 8192];  hoff = 16384; loff = 24576; pos = idx - 8192; }
    else if (idx < 81920) { v = wv[idx - 16384]; hoff = 32768; loff = 98304; pos = idx - 16384; }
    else return;
    __half h = __float2half_rn(v);
    o[hoff + pos] = h;
    o[loff + pos] = __float2half_rn(v - __half2float(h));
}

// F chunk convert hi+lo -> smem swizzled (for QK conv)
__device__ __forceinline__ void f_store(char* smx, u32 fh_off, u32 fl_off,
                                        const float4* pre, int tid) {
#pragma unroll
    for (int i = 0; i < 8; i++) {
        int idx = i * 256 + tid, row = idx >> 6, n = (idx & 63) * 4;
        float4 f = pre[i];
        __half2 h0 = __floats2half2_rn(f.x, f.y);
        __half2 h1 = __floats2half2_rn(f.z, f.w);
        float2 g0 = __half22float2(h0), g1 = __half22float2(h1);
        __half2 l0 = __floats2half2_rn(f.x - g0.x, f.y - g0.y);
        __half2 l1 = __floats2half2_rn(f.z - g1.x, f.w - g1.y);
        u32 off = row * 512 + (((n >> 3) ^ (row & 7)) << 4) + (n & 7) * 2;
        *(uint2*)(smx + fh_off + off) = make_uint2(*(u32*)&h0, *(u32*)&h1);
        *(uint2*)(smx + fl_off + off) = make_uint2(*(u32*)&l0, *(u32*)&l1);
    }
}

// F chunk convert hi only (for V conv)
__device__ __forceinline__ void f_store_h(char* smx, u32 fh_off,
                                          const float4* pre, int tid) {
#pragma unroll
    for (int i = 0; i < 8; i++) {
        int idx = i * 256 + tid, row = idx >> 6, n = (idx & 63) * 4;
        float4 f = pre[i];
        __half2 h0 = __floats2half2_rn(f.x, f.y);
        __half2 h1 = __floats2half2_rn(f.z, f.w);
        u32 off = row * 512 + (((n >> 3) ^ (row & 7)) << 4) + (n & 7) * 2;
        *(uint2*)(smx + fh_off + off) = make_uint2(*(u32*)&h0, *(u32*)&h1);
    }
}

// ---------------- merged conv Q+K via HMMA: out [n][32hi|32lo] ----------------
// blockIdx.y: 0 -> Q (f1), 1 -> K (f2)
#define QK_SMEM 69632
__global__ void __launch_bounds__(256, 1)
conv_qk_mma(const float* __restrict__ F1, const float* __restrict__ F2,
            const __half* __restrict__ Wall,
            const float* __restrict__ bq, const float* __restrict__ bk,
            __half* __restrict__ outq, __half* __restrict__ outk) {
    extern __shared__ char smx[];
    const u32 su = smem_u32(smx);
    const int tid = threadIdx.x, warp = tid >> 5, lane = tid & 31;
    const int n0 = blockIdx.x * 256, b = blockIdx.z;
    const int sel = blockIdx.y;
    const float* F = sel ? F2 : F1;
    const __half* Wh = Wall + sel * 16384;
    const __half* Wl = Wh + 8192;
    const float* bias = sel ? bk : bq;
    __half* out = sel ? outk : outq;
    const float* Fb = F + (size_t)b * CH * NQ;

    for (int i = tid; i < 2048; i += 256) {
        int arr = i >> 10, rem = i & 1023, row = rem >> 5, cch = rem & 31;
        const __half* src = (arr ? Wl : Wh) + row * 256 + cch * 8;
        *(uint4*)(smx + arr * 16384 + row * 512 + ((cch ^ (row & 7)) << 4)) =
            *(const uint4*)src;
    }

    float4 pre[8];
#pragma unroll
    for (int i = 0; i < 8; i++) {
        int idx = i * 256 + tid, row = idx >> 6, n = (idx & 63) * 4;
        pre[i] = *(const float4*)&Fb[(size_t)row * NQ + n0 + n];
    }

    float oacc[8][4];
#pragma unroll
    for (int i = 0; i < 8; i++)
#pragma unroll
        for (int j = 0; j < 4; j++) oacc[i][j] = 0.f;

    const int arow = (lane & 7) | (((lane >> 3) & 1) << 3);
    const int achk = lane >> 4;
    const int krow = (lane & 7) + ((lane >> 3) & 1) * 8;
    const int nsel = lane >> 4;
    const int ow = warp >> 2, nw = warp & 3;

    for (int ck = 0; ck < 8; ck++) {
        __syncthreads();
        f_store(smx, 32768, 49152, pre, tid);
        if (ck < 7) {
#pragma unroll
            for (int i = 0; i < 8; i++) {
                int idx = i * 256 + tid, row = idx >> 6, n = (idx & 63) * 4;
                pre[i] = *(const float4*)&Fb[(size_t)((ck + 1) * 32 + row) * NQ + n0 + n];
            }
        }
        __syncthreads();
#pragma unroll
        for (int kk = 0; kk < 2; kk++) {
            int orow = ow * 16 + arow;
            int cchunk = ck * 4 + kk * 2 + achk;
            u32 aaddr = su + orow * 512 + ((cchunk ^ (orow & 7)) << 4);
            u32 ah[4], al[4];
            ldm4(ah, aaddr);
            ldm4(al, aaddr + 16384);
            int crow = kk * 16 + krow;
#pragma unroll
            for (int ns = 0; ns < 4; ns++) {
                int nch = (nw * 64 + ns * 16 + nsel * 8) >> 3;
                u32 baddr = su + 32768 + crow * 512 + ((nch ^ (crow & 7)) << 4);
                u32 bh[4], bl[4];
                ldm4t(bh, baddr);
                ldm4t(bl, baddr + 16384);
#pragma unroll
                for (int g = 0; g < 2; g++) {
                    float* d = oacc[ns * 2 + g];
                    mma16816(d, ah, &bh[2 * g]);
                    mma16816(d, ah, &bl[2 * g]);
                    mma16816(d, al, &bh[2 * g]);
                }
            }
        }
    }

    // epilogue: bias + hi/lo split -> staging [n 256][72 halves] at byte 32768
    __syncthreads();
    const int or0 = ow * 16 + (lane >> 2);
    const float b0 = bias[or0], b1 = bias[or0 + 8];
    __half* stg = (__half*)(smx + 32768);
#pragma unroll
    for (int j = 0; j < 8; j++) {
        int n = nw * 64 + j * 8 + (lane & 3) * 2;
#pragma unroll
        for (int e = 0; e < 2; e++) {
            float v0 = oacc[j][e] + b0;
            float v1 = oacc[j][2 + e] + b1;
            __half h0 = __float2half_rn(v0);
            __half h1 = __float2half_rn(v1);
            stg[(n + e) * 72 + or0] = h0;
            stg[(n + e) * 72 + 32 + or0] = __float2half_rn(v0 - __half2float(h0));
            stg[(n + e) * 72 + or0 + 8] = h1;
            stg[(n + e) * 72 + 32 + or0 + 8] = __float2half_rn(v1 - __half2float(h1));
        }
    }
    __syncthreads();
    for (int i = tid; i < 2048; i += 256) {
        int n = i >> 3, u4 = i & 7;
        *(uint4*)&out[((size_t)b * NQ + n0 + n) * 64 + u4 * 8] =
            *(uint4*)(stg + n * 72 + u4 * 8);
    }
}

// ---------------- conv V via HMMA (single term Wh*Fh): out [c][m] fp16 ----------------
#define CV_SMEM 49152
__global__ void __launch_bounds__(256, 1)
conv_v_mma(const float* __restrict__ F, const __half* __restrict__ Wh,
           const float* __restrict__ bias, __half* __restrict__ out) {
    extern __shared__ char smx[];
    const u32 su = smem_u32(smx);
    const int tid = threadIdx.x, warp = tid >> 5, lane = tid & 31;
    const int n0 = blockIdx.x * 256, o0 = blockIdx.y * 64, b = blockIdx.z;
    const float* Fb = F + (size_t)b * CH * NQ;

    for (int i = tid; i < 2048; i += 256) {
        int row = i >> 5, cch = i & 31;
        const __half* src = Wh + (size_t)(o0 + row) * 256 + cch * 8;
        *(uint4*)(smx + row * 512 + ((cch ^ (row & 7)) << 4)) = *(const uint4*)src;
    }

    float4 pre[8];
#pragma unroll
    for (int i = 0; i < 8; i++) {
        int idx = i * 256 + tid, row = idx >> 6, n = (idx & 63) * 4;
        pre[i] = *(const float4*)&Fb[(size_t)row * NQ + n0 + n];
    }

    float oacc[16][4];
#pragma unroll
    for (int i = 0; i < 16; i++)
#pragma unroll
        for (int j = 0; j < 4; j++) oacc[i][j] = 0.f;

    const int arow = (lane & 7) | (((lane >> 3) & 1) << 3);
    const int achk = lane >> 4;
    const int krow = (lane & 7) + ((lane >> 3) & 1) * 8;
    const int nsel = lane >> 4;
    const int ob = warp >> 1, nw = warp & 1;

    for (int ck = 0; ck < 8; ck++) {
        __syncthreads();
        f_store_h(smx, 32768, pre, tid);
        if (ck < 7) {
#pragma unroll
            for (int i = 0; i < 8; i++) {
                int idx = i * 256 + tid, row = idx >> 6, n = (idx & 63) * 4;
                pre[i] = *(const float4*)&Fb[(size_t)((ck + 1) * 32 + row) * NQ + n0 + n];
            }
        }
        __syncthreads();
#pragma unroll
        for (int kk = 0; kk < 2; kk++) {
            int orow = ob * 16 + arow;
            int cchunk = ck * 4 + kk * 2 + achk;
            u32 aaddr = su + orow * 512 + ((cchunk ^ (orow & 7)) << 4);
            u32 ah[4];
            ldm4(ah, aaddr);
            int crow = kk * 16 + krow;
#pragma unroll
            for (int ns = 0; ns < 8; ns++) {
                int nch = (nw * 128 + ns * 16 + nsel * 8) >> 3;
                u32 baddr = su + 32768 + crow * 512 + ((nch ^ (crow & 7)) << 4);
                u32 bh[4];
                ldm4t(bh, baddr);
#pragma unroll
                for (int g = 0; g < 2; g++) {
                    float* d = oacc[ns * 2 + g];
                    mma16816(d, ah, &bh[2 * g]);
                }
            }
        }
    }

    // epilogue -> staging [o 64][272 halves] at byte 0 (reuse W region)
    __syncthreads();
    const int or0 = ob * 16 + (lane >> 2);
    const float b0 = bias[o0 + or0], b1 = bias[o0 + or0 + 8];
    __half* stg = (__half*)smx;
#pragma unroll
    for (int j = 0; j < 16; j++) {
        int n = nw * 128 + j * 8 + (lane & 3) * 2;
        __half2 h0 = __floats2half2_rn(oacc[j][0] + b0, oacc[j][1] + b0);
        __half2 h1 = __floats2half2_rn(oacc[j][2] + b1, oacc[j][3] + b1);
        *(__half2*)&stg[or0 * 272 + n] = h0;
        *(__half2*)&stg[(or0 + 8) * 272 + n] = h1;
    }
    __syncthreads();
    for (int i = tid; i < 2048; i += 256) {
        int row = i >> 5, c4 = i & 31;
        *(uint4*)&out[((size_t)b * CH + o0 + row) * NQ + n0 + c4 * 8] =
            *(uint4*)(stg + row * 272 + c4 * 8);
    }
}

// ---------------- mma.sync flash attention (fp16, chunk-pipelined) ----------------
#define QS_OFF 0
#define KS_OFF 16384
#define VS_OFF 40960
#define NKT    (NQ / 64)
#define ATTN_SMEM 139264

__device__ __forceinline__ void exp_pack(const float* d, u32* ph,
                                         float& l0, float& l1) {
#pragma unroll
    for (int g = 0; g < 2; g++) {
        float p0 = ex2f(fmaf(d[4 * g + 0], LOG2E, -8.0f));
        float p1 = ex2f(fmaf(d[4 * g + 1], LOG2E, -8.0f));
        float p2 = ex2f(fmaf(d[4 * g + 2], LOG2E, -8.0f));
        float p3 = ex2f(fmaf(d[4 * g + 3], LOG2E, -8.0f));
        l0 += p0 + p1;
        l1 += p2 + p3;
        __half2 hh01 = __floats2half2_rn(p0, p1);
        __half2 hh23 = __floats2half2_rn(p2, p3);
        ph[2 * g] = *(u32*)&hh01;
        ph[2 * g + 1] = *(u32*)&hh23;
    }
}

// S for one 16-key chunk: 2-term (Qh+Ql)*Kh
__device__ __forceinline__ void s_chunk(u32 kbuf, int mt, int brow, int bchk,
                                        const u32 qa[4][4], float* d8) {
    int kr = mt * 16 + brow;
    u32 kb_ = kbuf + kr * 128;
    int sw = kr & 7;
    u32 kh0[4], kh1[4];
    ldm4(kh0, kb_ + (((0 + bchk) ^ sw) << 4));
    ldm4(kh1, kb_ + (((2 + bchk) ^ sw) << 4));
#pragma unroll
    for (int g = 0; g < 2; g++) {
        float* d = d8 + 4 * g;
        d[0] = 0.f; d[1] = 0.f; d[2] = 0.f; d[3] = 0.f;
        mma16816(d, qa[0], &kh0[2 * g]);
        mma16816(d, qa[1], &kh1[2 * g]);
        mma16816(d, qa[2], &kh0[2 * g]);   // Qlo * Kh
        mma16816(d, qa[3], &kh1[2 * g]);
    }
}

// K hi only: 8KB/stage K, 32KB/stage V, 3 stages
__device__ __forceinline__ void load_kv(u32 su, const __half* Kb,
                                        const __half* Vhb, int kt, int tid) {
    int bf = kt % 3;
    for (int i = tid; i < 512; i += 256) {
        int m = i >> 3, j = i & 7;
        cpa(su + KS_OFF + bf * 8192 + m * 128 + ((j ^ (m & 7)) << 4),
            Kb + ((size_t)(kt * 64 + m)) * 64 + j * 8);
    }
    for (int i = tid; i < 2048; i += 256) {
        int c = i >> 3, j = i & 7;
        cpa(su + VS_OFF + bf * 32768 + c * 128 + ((j ^ (c & 7)) << 4),
            Vhb + (size_t)c * NQ + kt * 64 + j * 8);
    }
}

__global__ void __launch_bounds__(256, 1)
attn_kernel(const __half* __restrict__ Qg, const __half* __restrict__ Kg,
            const __half* __restrict__ Vhg, float* __restrict__ Og) {
    extern __shared__ char smx[];
    const u32 su = smem_u32(smx);
    const int tid = threadIdx.x, warp = tid >> 5, lane = tid & 31;
    const int b = blockIdx.y, q0 = blockIdx.x * 128;

    const __half* Qb  = Qg  + ((size_t)b * NQ + q0) * 64;
    const __half* Kb  = Kg  + (size_t)b * NQ * 64;
    const __half* Vhb = Vhg + (size_t)b * CH * NQ;

    for (int i = tid; i < 1024; i += 256) {
        int q = i >> 3, j = i & 7;
        cpa(su + QS_OFF + q * 128 + ((j ^ (q & 7)) << 4), Qb + (size_t)q * 64 + j * 8);
    }
    load_kv(su, Kb, Vhb, 0, tid);
    CP_COMMIT();
    load_kv(su, Kb, Vhb, 1, tid);
    CP_COMMIT();

    float oacc[32][4];
#pragma unroll
    for (int i = 0; i < 32; i++)
#pragma unroll
        for (int j = 0; j < 4; j++) oacc[i][j] = 0.f;
    float lsum0 = 0.f, lsum1 = 0.f;
    u32 qa[4][4];

    const int arow = (lane & 7) | (((lane >> 3) & 1) << 3);
    const int achk = lane >> 4;
    const int brow = (lane & 7) | ((lane >> 4) << 3);
    const int bchk = (lane >> 3) & 1;

    for (int kt = 0; kt < NKT; kt++) {
        cp_wait<1>();
        __syncthreads();
        if (kt + 2 < NKT) load_kv(su, Kb, Vhb, kt + 2, tid);
        CP_COMMIT();

        if (kt == 0) {
            int qr = warp * 16 + arow;
            u32 qb_ = su + QS_OFF + qr * 128;
#pragma unroll
            for (int t = 0; t < 4; t++)
                ldm4(qa[t], qb_ + (((2 * t + achk) ^ (qr & 7)) << 4));
        }
        u32 kbuf = su + KS_OFF + (kt % 3) * 8192;
        u32 vbuf = su + VS_OFF + (kt % 3) * 32768;

        // ---- chunk-pipelined: S(0); exp; { S(mt+1) | PV(mt) | exp } ----
        u32 pah[4];
        {
            float ds[8];
            s_chunk(kbuf, 0, brow, bchk, qa, ds);
            exp_pack(ds, pah, lsum0, lsum1);
        }
#pragma unroll
        for (int mt = 0; mt < 4; mt++) {
            float dsn[8];
            if (mt < 3) s_chunk(kbuf, mt + 1, brow, bchk, qa, dsn);
            // PV for chunk mt
#pragma unroll
            for (int cb = 0; cb < 16; cb++) {
                int vr = cb * 16 + brow;
                u32 vh_ = vbuf + vr * 128;
                int sw = vr & 7;
                u32 v[4];
                ldm4(v, vh_ + (((2 * mt + bchk) ^ sw) << 4));
                mma16816(oacc[2 * cb],     pah, &v[0]);
                mma16816(oacc[2 * cb + 1], pah, &v[2]);
            }
            if (mt < 3) exp_pack(dsn, pah, lsum0, lsum1);
        }
    }

    lsum0 += __shfl_xor_sync(0xffffffffu, lsum0, 1);
    lsum0 += __shfl_xor_sync(0xffffffffu, lsum0, 2);
    lsum1 += __shfl_xor_sync(0xffffffffu, lsum1, 1);
    lsum1 += __shfl_xor_sync(0xffffffffu, lsum1, 2);
    float inv0 = 1.0f / lsum0, inv1 = 1.0f / lsum1;
    float* og = Og + (size_t)b * CH * NQ;
    int q = q0 + warp * 16 + (lane >> 2);
#pragma unroll
    for (int ng = 0; ng < 32; ng++) {
        int c = ng * 8 + (lane & 3) * 2;
        og[(size_t)c * NQ + q]           = oacc[ng][0] * inv0;
        og[(size_t)(c + 1) * NQ + q]     = oacc[ng][1] * inv0;
        og[(size_t)c * NQ + q + 8]       = oacc[ng][2] * inv1;
        og[(size_t)(c + 1) * NQ + q + 8] = oacc[ng][3] * inv1;
    }
}

// ---------------- launch ----------------
extern "C" void kernel_launch(void* const* d_in, const int* in_sizes, int n_in,
                              void* d_out, int out_size) {
    const float* f1 = (const float*)d_in[0];
    const float* f2 = (const float*)d_in[1];
    const float* f3 = (const float*)d_in[2];
    const float* wq = (const float*)d_in[3];
    const float* bq = (const float*)d_in[4];
    const float* wk = (const float*)d_in[5];
    const float* bk = (const float*)d_in[6];
    const float* wv = (const float*)d_in[7];
    const float* bv = (const float*)d_in[8];
    float* out = (float*)d_out;

    __half *qp, *kp, *vhp, *whl;
    cudaGetSymbolAddress((void**)&qp, g_Qhl);
    cudaGetSymbolAddress((void**)&kp, g_Khl);
    cudaGetSymbolAddress((void**)&vhp, g_VTh);
    cudaGetSymbolAddress((void**)&whl, g_Whl);

    prep_w<<<320, 256>>>(wq, wk, wv, whl);

    cudaFuncSetAttribute(conv_qk_mma, cudaFuncAttributeMaxDynamicSharedMemorySize, QK_SMEM);
    cudaFuncSetAttribute(conv_v_mma, cudaFuncAttributeMaxDynamicSharedMemorySize, CV_SMEM);

    dim3 gqk(NQ / 256, 2, BATCH);
    conv_qk_mma<<<gqk, 256, QK_SMEM>>>(f1, f2, whl, bq, bk, qp, kp);
    dim3 gv(NQ / 256, CH / 64, BATCH);
    conv_v_mma<<<gv, 256, CV_SMEM>>>(f3, whl + 32768, bv, vhp);

    cudaFuncSetAttribute(attn_kernel, cudaFuncAttributeMaxDynamicSharedMemorySize,
                         ATTN_SMEM);
    dim3 ga(NQ / 128, BATCH);
    attn_kernel<<<ga, 256, ATTN_SMEM>>>(qp, kp, vhp, out);
}